// round 1
// baseline (speedup 1.0000x reference)
#include <cuda_runtime.h>

#define B_ 8
#define N_ 1024
#define D_ 512
#define H_ 8
#define DH_ 64
#define NW_ (N_/32)   // 32 words of adj bits per row

// ---------------- scratch (static device globals; no allocs) ----------------
__device__ float    g_xn[B_*N_*D_];          // LN1 output
__device__ float    g_h [B_*N_*D_];          // h, layout [b][n][h][k]
__device__ float    g_fs[B_*H_*N_];          // f_src  [b][h][n]
__device__ float    g_fd[B_*H_*N_];          // f_dst  [b][h][n]
__device__ float    g_gmax[B_*H_];           // max_j f_dst per (b,h)
__device__ unsigned g_adjb[B_*N_*NW_];       // adjacency bitmask [b][i][w]
__device__ float    g_y [B_*N_*D_];          // x + elu(ggat)  (pre-LN2)

// ---------------- fast exp on FMA pipe (no MUFU) ----------------
__device__ __forceinline__ float fexp(float x) {
    float t = x * 1.4426950408889634f;          // x * log2(e)
    t = fmaxf(t, -125.0f);                      // keep exponent math safe
    float r = t + 12582912.0f;                  // round-to-nearest-int magic
    int   n = __float_as_int(r) - 0x4B400000;
    float f = t - (r - 12582912.0f);            // f in [-0.5, 0.5]
    float p = 1.3333558146e-3f;                 // Taylor of 2^f (err ~2.4e-6)
    p = fmaf(p, f, 9.6181291298e-3f);
    p = fmaf(p, f, 5.5504108664e-2f);
    p = fmaf(p, f, 2.4022650696e-1f);
    p = fmaf(p, f, 6.9314718056e-1f);
    p = fmaf(p, f, 1.0f);
    return __int_as_float(__float_as_int(p) + (n << 23));
}

__device__ __forceinline__ float elu1(float v) { return v > 0.0f ? v : expm1f(v); }

// ---------------- LayerNorm (one block per row, 128 thr, float4) ----------------
__device__ __forceinline__ void ln_row(const float* __restrict__ in, float* __restrict__ out,
                                       const float* __restrict__ gw, const float* __restrict__ bw) {
    int row = blockIdx.x;
    int t = threadIdx.x;                         // 0..127
    const float4 v = ((const float4*)(in + (size_t)row * D_))[t];
    float s = v.x + v.y + v.z + v.w;
    float q = v.x*v.x + v.y*v.y + v.z*v.z + v.w*v.w;
#pragma unroll
    for (int o = 16; o; o >>= 1) {
        s += __shfl_xor_sync(0xffffffffu, s, o);
        q += __shfl_xor_sync(0xffffffffu, q, o);
    }
    __shared__ float ss[4], qs[4];
    if ((t & 31) == 0) { ss[t >> 5] = s; qs[t >> 5] = q; }
    __syncthreads();
    s = ss[0] + ss[1] + ss[2] + ss[3];
    q = qs[0] + qs[1] + qs[2] + qs[3];
    float mean = s * (1.0f / D_);
    float var  = fmaxf(q * (1.0f / D_) - mean * mean, 0.0f);
    float inv  = 1.0f / (sqrtf(var) + 1e-6f);    // jnp: g*(x-mean)/(std+eps)+b
    const float4 g4 = ((const float4*)gw)[t];
    const float4 b4 = ((const float4*)bw)[t];
    float4 o;
    o.x = fmaf(g4.x * (v.x - mean), inv, b4.x);
    o.y = fmaf(g4.y * (v.y - mean), inv, b4.y);
    o.z = fmaf(g4.z * (v.z - mean), inv, b4.z);
    o.w = fmaf(g4.w * (v.w - mean), inv, b4.w);
    ((float4*)(out + (size_t)row * D_))[t] = o;
}

__global__ void ln1_kernel(const float* __restrict__ x, const float* __restrict__ g,
                           const float* __restrict__ b) { ln_row(x, g_xn, g, b); }
__global__ void ln2_kernel(const float* __restrict__ g, const float* __restrict__ b,
                           float* __restrict__ out)     { ln_row(g_y, out, g, b); }

// ---------------- pack adj -> bitmask (warp ballot per word) ----------------
__global__ void pack_adj_kernel(const int* __restrict__ adj) {
    int gw   = (blockIdx.x * blockDim.x + threadIdx.x) >> 5;   // word index
    int lane = threadIdx.x & 31;
    int v = adj[(size_t)gw * 32 + lane];
    unsigned m = __ballot_sync(0xffffffffu, v > 0);
    if (lane == 0) g_adjb[gw] = m;
}

// ---------------- GEMM1: h = xn @ W   (M=8192, N=64 per head, K=512) ----------------
__global__ __launch_bounds__(256) void gemm1_kernel(const float* __restrict__ W) {
    __shared__ float As[16][132];     // A transposed, padded
    __shared__ float Bs[16][64];
    int h  = blockIdx.y;
    int m0 = blockIdx.x * 128;
    int tid = threadIdx.x;
    int tx = tid & 15, ty = tid >> 4;
    float acc[8][4];
#pragma unroll
    for (int i = 0; i < 8; i++)
#pragma unroll
        for (int j = 0; j < 4; j++) acc[i][j] = 0.0f;
    const float* Wh = W + (size_t)h * D_ * DH_;

    for (int k0 = 0; k0 < D_; k0 += 16) {
#pragma unroll
        for (int l = 0; l < 2; l++) {
            int li = tid * 2 + l;                 // 0..511
            int m = li >> 2, kq = li & 3;
            float4 a = *(const float4*)(g_xn + (size_t)(m0 + m) * D_ + k0 + kq * 4);
            As[kq*4+0][m] = a.x; As[kq*4+1][m] = a.y;
            As[kq*4+2][m] = a.z; As[kq*4+3][m] = a.w;
        }
        {
            int k = tid >> 4, c = tid & 15;
            *(float4*)&Bs[k][c*4] = *(const float4*)(Wh + (size_t)(k0 + k) * DH_ + c * 4);
        }
        __syncthreads();
#pragma unroll
        for (int kk = 0; kk < 16; kk++) {
            float4 a0 = *(float4*)&As[kk][ty*8];
            float4 a1 = *(float4*)&As[kk][ty*8+4];
            float4 b0 = *(float4*)&Bs[kk][tx*4];
            float av[8] = {a0.x,a0.y,a0.z,a0.w,a1.x,a1.y,a1.z,a1.w};
            float bv[4] = {b0.x,b0.y,b0.z,b0.w};
#pragma unroll
            for (int i = 0; i < 8; i++)
#pragma unroll
                for (int j = 0; j < 4; j++)
                    acc[i][j] = fmaf(av[i], bv[j], acc[i][j]);
        }
        __syncthreads();
    }
#pragma unroll
    for (int i = 0; i < 8; i++) {
        float4 o = make_float4(acc[i][0], acc[i][1], acc[i][2], acc[i][3]);
        *(float4*)(g_h + (size_t)(m0 + ty*8 + i) * D_ + h * DH_ + tx * 4) = o;
    }
}

// ---------------- f_src / f_dst (one warp per (b,n,h)) ----------------
__global__ void fsd_kernel(const float* __restrict__ a_src, const float* __restrict__ a_dst) {
    int gw   = (blockIdx.x * blockDim.x + threadIdx.x) >> 5;   // 0 .. B*N*H-1
    int lane = threadIdx.x & 31;
    int h = gw & 7, bn = gw >> 3;
    float2 hv = *(const float2*)(g_h + (size_t)bn * D_ + h * DH_ + lane * 2);
    float2 as = *(const float2*)(a_src + h * DH_ + lane * 2);
    float2 ad = *(const float2*)(a_dst + h * DH_ + lane * 2);
    float s = hv.x * as.x + hv.y * as.y;
    float d = hv.x * ad.x + hv.y * ad.y;
#pragma unroll
    for (int o = 16; o; o >>= 1) {
        s += __shfl_xor_sync(0xffffffffu, s, o);
        d += __shfl_xor_sync(0xffffffffu, d, o);
    }
    if (lane == 0) {
        int b = bn >> 10, n = bn & 1023;
        g_fs[(b * H_ + h) * N_ + n] = s;
        g_fd[(b * H_ + h) * N_ + n] = d;
    }
}

// ---------------- per-(b,h) max of f_dst ----------------
__global__ void gmax_kernel() {
    int bh = blockIdx.x, t = threadIdx.x;
    float m = -1e30f;
    for (int i = t; i < N_; i += 256) m = fmaxf(m, g_fd[bh * N_ + i]);
#pragma unroll
    for (int o = 16; o; o >>= 1) m = fmaxf(m, __shfl_xor_sync(0xffffffffu, m, o));
    __shared__ float sm[8];
    if ((t & 31) == 0) sm[t >> 5] = m;
    __syncthreads();
    if (t == 0) {
        float mm = sm[0];
#pragma unroll
        for (int i = 1; i < 8; i++) mm = fmaxf(mm, sm[i]);
        g_gmax[bh] = mm;
    }
}

// ---------------- attention: out = softmax(masked lrelu(fs+fd)) @ h, + elu + residual ----
// grid (N/32, H, B), 512 threads. Warp = 2 rows; lane owns 4 d-columns.
__global__ __launch_bounds__(512) void attn_kernel(const float* __restrict__ x) {
    __shared__ float    hs[64 * 64];      // h tile [j][d]
    __shared__ float    ps[32 * 64];      // probabilities [i][j]
    __shared__ float    fss[32], ms[32], fds[64];
    __shared__ unsigned aw[32][2];

    int b = blockIdx.z, h = blockIdx.y;
    int i0 = blockIdx.x * 32;
    int tid  = threadIdx.x;
    int warp = tid >> 5, lane = tid & 31;
    int row  = warp * 2 + (lane >> 4);        // 0..31
    int d0   = (lane & 15) * 4;
    int bh   = b * H_ + h;

    if (tid < 32) {
        float fsv = g_fs[bh * N_ + i0 + tid];
        fss[tid] = fsv;
        float bound = fsv + g_gmax[bh];       // lrelu monotone -> valid row max bound
        ms[tid] = bound > 0.0f ? bound : 0.2f * bound;
    }

    float acc0 = 0.f, acc1 = 0.f, acc2 = 0.f, acc3 = 0.f, den = 0.f;

    for (int jt = 0; jt < 16; jt++) {
        int j0 = jt * 64;
        __syncthreads();                      // previous tile fully consumed
        // load h tile: 1024 float4, 2 per thread (coalesced)
#pragma unroll
        for (int l = 0; l < 2; l++) {
            int li = tid + l * 512;
            int j = li >> 4, q = li & 15;
            *(float4*)&hs[j * 64 + q * 4] =
                *(const float4*)(g_h + (size_t)(b * N_ + j0 + j) * D_ + h * DH_ + q * 4);
        }
        if (tid < 64) {
            fds[tid] = g_fd[bh * N_ + j0 + tid];
        } else if (tid < 128) {
            int t2 = tid - 64;
            aw[t2 >> 1][t2 & 1] = g_adjb[(size_t)(b * N_ + i0 + (t2 >> 1)) * NW_ + jt * 2 + (t2 & 1)];
        }
        __syncthreads();

        // phase 1: probabilities (4 per thread)
        {
            int i  = tid >> 4;
            int jb = (tid & 15) * 4;
            float fsv = fss[i], m = ms[i];
            unsigned w = aw[i][jb >> 5];
            float4 pv;
            {
                float e = fsv + fds[jb + 0]; float lr = e > 0.f ? e : 0.2f * e;
                pv.x = ((w >> ((jb + 0) & 31)) & 1u) ? fexp(lr - m) : 0.f;
            }
            {
                float e = fsv + fds[jb + 1]; float lr = e > 0.f ? e : 0.2f * e;
                pv.y = ((w >> ((jb + 1) & 31)) & 1u) ? fexp(lr - m) : 0.f;
            }
            {
                float e = fsv + fds[jb + 2]; float lr = e > 0.f ? e : 0.2f * e;
                pv.z = ((w >> ((jb + 2) & 31)) & 1u) ? fexp(lr - m) : 0.f;
            }
            {
                float e = fsv + fds[jb + 3]; float lr = e > 0.f ? e : 0.2f * e;
                pv.w = ((w >> ((jb + 3) & 31)) & 1u) ? fexp(lr - m) : 0.f;
            }
            *(float4*)&ps[i * 64 + jb] = pv;
        }
        __syncthreads();

        // phase 2: accumulate out tile
        const float* psr = &ps[row * 64];
#pragma unroll 8
        for (int j = 0; j < 64; j++) {
            float p = psr[j];
            float4 hv = *(const float4*)&hs[j * 64 + d0];
            acc0 = fmaf(p, hv.x, acc0);
            acc1 = fmaf(p, hv.y, acc1);
            acc2 = fmaf(p, hv.z, acc2);
            acc3 = fmaf(p, hv.w, acc3);
            den += p;
        }
    }

    float invd = 1.0f / den;
    size_t idx = (size_t)(b * N_ + i0 + row) * D_ + h * DH_ + d0;
    float4 xv = *(const float4*)(x + idx);
    float4 ov;
    ov.x = xv.x + elu1(acc0 * invd);
    ov.y = xv.y + elu1(acc1 * invd);
    ov.z = xv.z + elu1(acc2 * invd);
    ov.w = xv.w + elu1(acc3 * invd);
    *(float4*)(g_y + idx) = ov;
}

// ---------------- launch ----------------
extern "C" void kernel_launch(void* const* d_in, const int* in_sizes, int n_in,
                              void* d_out, int out_size) {
    const float* x     = (const float*)d_in[0];
    const int*   adj   = (const int*)  d_in[2];
    const float* W     = (const float*)d_in[3];
    const float* a_src = (const float*)d_in[4];
    const float* a_dst = (const float*)d_in[5];
    const float* ln1g  = (const float*)d_in[6];
    const float* ln1b  = (const float*)d_in[7];
    const float* ln2g  = (const float*)d_in[8];
    const float* ln2b  = (const float*)d_in[9];
    float* out = (float*)d_out;

    ln1_kernel  <<<B_*N_, 128>>>(x, ln1g, ln1b);
    pack_adj_kernel<<<(B_*N_*N_) / 256, 256>>>(adj);        // 8 words/block
    gemm1_kernel<<<dim3(B_*N_/128, H_), 256>>>(W);
    fsd_kernel  <<<B_*N_*H_/8, 256>>>(a_src, a_dst);        // 1 warp per (b,n,h)
    gmax_kernel <<<B_*H_, 256>>>();
    attn_kernel <<<dim3(N_/32, H_, B_), 512>>>(x);
    ln2_kernel  <<<B_*N_, 128>>>(ln2g, ln2b, out);
}

// round 2
// speedup vs baseline: 2.4772x; 2.4772x over previous
#include <cuda_runtime.h>

#define B_ 8
#define N_ 1024
#define D_ 512
#define H_ 8
#define DH_ 64
#define NW_ (N_/32)
#define L2E 1.4426950408889634f

// ---------------- scratch ----------------
__device__ unsigned short g_xnh[B_*N_*D_];   // LN1 out, bf16 hi
__device__ unsigned short g_xnl[B_*N_*D_];   // LN1 out, bf16 lo
__device__ unsigned short g_Wth[H_*DH_*D_];  // W^T [h][d][k] bf16 hi
__device__ unsigned short g_Wtl[H_*DH_*D_];
__device__ float    g_h [B_*N_*D_];          // h fp32, [b][n][h][k]
__device__ unsigned short g_hTh[B_*H_*DH_*N_]; // h^T [b][h][d][j] bf16 hi
__device__ unsigned short g_hTl[B_*H_*DH_*N_];
__device__ float    g_fs[B_*H_*N_];          // f_src * log2(e)
__device__ float    g_fd[B_*H_*N_];          // f_dst * log2(e)
__device__ float    g_gmax[B_*H_];
__device__ unsigned g_adjb[B_*N_*NW_];
__device__ float    g_y [B_*N_*D_];

// ---------------- helpers ----------------
__device__ __forceinline__ float fexp2f(float t) {   // 2^t, FMA pipe only
    t = fmaxf(t, -125.0f);
    float r = t + 12582912.0f;
    int   n = __float_as_int(r) - 0x4B400000;
    float f = t - (r - 12582912.0f);
    float p = 1.3333558146e-3f;
    p = fmaf(p, f, 9.6181291298e-3f);
    p = fmaf(p, f, 5.5504108664e-2f);
    p = fmaf(p, f, 2.4022650696e-1f);
    p = fmaf(p, f, 6.9314718056e-1f);
    p = fmaf(p, f, 1.0f);
    return __int_as_float(__float_as_int(p) + (n << 23));
}
__device__ __forceinline__ float elu1(float v) {
    return v > 0.0f ? v : (fexp2f(v * L2E) - 1.0f);
}
__device__ __forceinline__ unsigned short bfsplit(float x, float &rem) {
    unsigned xi = __float_as_uint(x);
    unsigned hb = (xi + 0x8000u) & 0xffff0000u;
    rem = x - __uint_as_float(hb);
    return (unsigned short)(hb >> 16);
}
__device__ __forceinline__ unsigned short bfround(float x) {
    return (unsigned short)(((__float_as_uint(x) + 0x8000u) & 0xffff0000u) >> 16);
}
__device__ __forceinline__ void mma16816(float* c, unsigned a0, unsigned a1,
                                         unsigned a2, unsigned a3,
                                         unsigned b0, unsigned b1) {
    asm volatile(
        "mma.sync.aligned.m16n8k16.row.col.f32.bf16.bf16.f32 "
        "{%0,%1,%2,%3}, {%4,%5,%6,%7}, {%8,%9}, {%0,%1,%2,%3};\n"
        : "+f"(c[0]), "+f"(c[1]), "+f"(c[2]), "+f"(c[3])
        : "r"(a0), "r"(a1), "r"(a2), "r"(a3), "r"(b0), "r"(b1));
}

// Shared mma tile step: A[128][32] (stride 40), B[64][32] (stride 40), both hi/lo.
// acc[8][4] per warp covering rows ibase..ibase+15, cols 0..63.
__device__ __forceinline__ void mma_chunk(float acc[8][4],
        const unsigned short* __restrict__ Ah, const unsigned short* __restrict__ Al,
        const unsigned short* __restrict__ Bh, const unsigned short* __restrict__ Bl,
        int ibase, int lane) {
    int r  = lane >> 2;
    int c2 = (lane & 3) * 2;
#pragma unroll
    for (int kk = 0; kk < 2; kk++) {
        const unsigned short* pA = Ah + (ibase + r) * 40 + kk * 16 + c2;
        const unsigned short* qA = Al + (ibase + r) * 40 + kk * 16 + c2;
        unsigned ah0 = *(const unsigned*)(pA);
        unsigned ah1 = *(const unsigned*)(pA + 8 * 40);
        unsigned ah2 = *(const unsigned*)(pA + 8);
        unsigned ah3 = *(const unsigned*)(pA + 8 * 40 + 8);
        unsigned al0 = *(const unsigned*)(qA);
        unsigned al1 = *(const unsigned*)(qA + 8 * 40);
        unsigned al2 = *(const unsigned*)(qA + 8);
        unsigned al3 = *(const unsigned*)(qA + 8 * 40 + 8);
#pragma unroll
        for (int nt = 0; nt < 8; nt++) {
            const unsigned short* pB = Bh + (nt * 8 + r) * 40 + kk * 16 + c2;
            const unsigned short* qB = Bl + (nt * 8 + r) * 40 + kk * 16 + c2;
            unsigned bh0 = *(const unsigned*)(pB);
            unsigned bh1 = *(const unsigned*)(pB + 8);
            unsigned bl0 = *(const unsigned*)(qB);
            unsigned bl1 = *(const unsigned*)(qB + 8);
            mma16816(acc[nt], ah0, ah1, ah2, ah3, bh0, bh1);   // hi*hi
            mma16816(acc[nt], ah0, ah1, ah2, ah3, bl0, bl1);   // hi*lo
            mma16816(acc[nt], al0, al1, al2, al3, bh0, bh1);   // lo*hi
        }
    }
}

// ---------------- LN1 (writes bf16 split) ----------------
__global__ void ln1_kernel(const float* __restrict__ x, const float* __restrict__ gw,
                           const float* __restrict__ bw) {
    int row = blockIdx.x, t = threadIdx.x;
    const float4 v = ((const float4*)(x + (size_t)row * D_))[t];
    float s = v.x + v.y + v.z + v.w;
    float q = v.x*v.x + v.y*v.y + v.z*v.z + v.w*v.w;
#pragma unroll
    for (int o = 16; o; o >>= 1) {
        s += __shfl_xor_sync(0xffffffffu, s, o);
        q += __shfl_xor_sync(0xffffffffu, q, o);
    }
    __shared__ float ss[4], qs[4];
    if ((t & 31) == 0) { ss[t >> 5] = s; qs[t >> 5] = q; }
    __syncthreads();
    s = ss[0] + ss[1] + ss[2] + ss[3];
    q = qs[0] + qs[1] + qs[2] + qs[3];
    float mean = s * (1.0f / D_);
    float var  = fmaxf(q * (1.0f / D_) - mean * mean, 0.0f);
    float inv  = 1.0f / (sqrtf(var) + 1e-6f);
    const float4 g4 = ((const float4*)gw)[t];
    const float4 b4 = ((const float4*)bw)[t];
    float o0 = fmaf(g4.x * (v.x - mean), inv, b4.x);
    float o1 = fmaf(g4.y * (v.y - mean), inv, b4.y);
    float o2 = fmaf(g4.z * (v.z - mean), inv, b4.z);
    float o3 = fmaf(g4.w * (v.w - mean), inv, b4.w);
    float r0, r1, r2, r3;
    unsigned short h0 = bfsplit(o0, r0), h1 = bfsplit(o1, r1);
    unsigned short h2 = bfsplit(o2, r2), h3 = bfsplit(o3, r3);
    uint2 vh = make_uint2((unsigned)h0 | ((unsigned)h1 << 16),
                          (unsigned)h2 | ((unsigned)h3 << 16));
    uint2 vl = make_uint2((unsigned)bfround(r0) | ((unsigned)bfround(r1) << 16),
                          (unsigned)bfround(r2) | ((unsigned)bfround(r3) << 16));
    *(uint2*)&g_xnh[(size_t)row * D_ + t * 4] = vh;
    *(uint2*)&g_xnl[(size_t)row * D_ + t * 4] = vl;
}

// ---------------- LN2 ----------------
__global__ void ln2_kernel(const float* __restrict__ gw, const float* __restrict__ bw,
                           float* __restrict__ out) {
    int row = blockIdx.x, t = threadIdx.x;
    const float4 v = ((const float4*)(g_y + (size_t)row * D_))[t];
    float s = v.x + v.y + v.z + v.w;
    float q = v.x*v.x + v.y*v.y + v.z*v.z + v.w*v.w;
#pragma unroll
    for (int o = 16; o; o >>= 1) {
        s += __shfl_xor_sync(0xffffffffu, s, o);
        q += __shfl_xor_sync(0xffffffffu, q, o);
    }
    __shared__ float ss[4], qs[4];
    if ((t & 31) == 0) { ss[t >> 5] = s; qs[t >> 5] = q; }
    __syncthreads();
    s = ss[0] + ss[1] + ss[2] + ss[3];
    q = qs[0] + qs[1] + qs[2] + qs[3];
    float mean = s * (1.0f / D_);
    float var  = fmaxf(q * (1.0f / D_) - mean * mean, 0.0f);
    float inv  = 1.0f / (sqrtf(var) + 1e-6f);
    const float4 g4 = ((const float4*)gw)[t];
    const float4 b4 = ((const float4*)bw)[t];
    float4 o;
    o.x = fmaf(g4.x * (v.x - mean), inv, b4.x);
    o.y = fmaf(g4.y * (v.y - mean), inv, b4.y);
    o.z = fmaf(g4.z * (v.z - mean), inv, b4.z);
    o.w = fmaf(g4.w * (v.w - mean), inv, b4.w);
    ((float4*)(out + (size_t)row * D_))[t] = o;
}

// ---------------- pack adj ----------------
__global__ void pack_adj_kernel(const int* __restrict__ adj) {
    int gw   = (blockIdx.x * blockDim.x + threadIdx.x) >> 5;
    int lane = threadIdx.x & 31;
    int v = adj[(size_t)gw * 32 + lane];
    unsigned m = __ballot_sync(0xffffffffu, v > 0);
    if (lane == 0) g_adjb[gw] = m;
}

// ---------------- W -> W^T bf16 split ----------------
__global__ void prep_w_kernel(const float* __restrict__ W) {
    int hd = blockIdx.x;             // 0..511 : h*64+d
    int h = hd >> 6, d = hd & 63;
    for (int k = threadIdx.x; k < D_; k += 128) {
        float v = W[(size_t)h * D_ * DH_ + (size_t)k * DH_ + d];
        float rem;
        unsigned short hi = bfsplit(v, rem);
        g_Wth[(size_t)hd * D_ + k] = hi;
        g_Wtl[(size_t)hd * D_ + k] = bfround(rem);
    }
}

// ---------------- GEMM1: h = xn @ W, tensorized bf16x3 ----------------
__global__ __launch_bounds__(256) void gemm1t_kernel() {
    __shared__ unsigned short ah_s[128 * 40], al_s[128 * 40];
    __shared__ unsigned short bh_s[64 * 40],  bl_s[64 * 40];

    int m0 = blockIdx.x * 128;
    int h  = blockIdx.y;
    int t = threadIdx.x, warp = t >> 5, lane = t & 31;
    int ibase = warp * 16;

    float acc[8][4];
#pragma unroll
    for (int i = 0; i < 8; i++)
#pragma unroll
        for (int j = 0; j < 4; j++) acc[i][j] = 0.0f;

    // prefetch mapping
    int ai = t >> 1, asg = t & 1;       // A: row ai, 16-col segment asg
    int bd = t >> 2, bq = t & 3;        // B: row d, uint4 seg q
    uint4 nA0h, nA1h, nA0l, nA1l, nBh, nBl;
    {
        const unsigned short* pa = g_xnh + (size_t)(m0 + ai) * D_ + asg * 16;
        const unsigned short* qa = g_xnl + (size_t)(m0 + ai) * D_ + asg * 16;
        nA0h = ((const uint4*)pa)[0]; nA1h = ((const uint4*)pa)[1];
        nA0l = ((const uint4*)qa)[0]; nA1l = ((const uint4*)qa)[1];
        const unsigned short* pb = g_Wth + (size_t)(h * 64 + bd) * D_ + bq * 8;
        const unsigned short* qb = g_Wtl + (size_t)(h * 64 + bd) * D_ + bq * 8;
        nBh = *(const uint4*)pb; nBl = *(const uint4*)qb;
    }

    for (int kc = 0; kc < 16; kc++) {
        __syncthreads();                       // prev mma done
        *(uint4*)&ah_s[ai * 40 + asg * 16]     = nA0h;
        *(uint4*)&ah_s[ai * 40 + asg * 16 + 8] = nA1h;
        *(uint4*)&al_s[ai * 40 + asg * 16]     = nA0l;
        *(uint4*)&al_s[ai * 40 + asg * 16 + 8] = nA1l;
        *(uint4*)&bh_s[bd * 40 + bq * 8] = nBh;
        *(uint4*)&bl_s[bd * 40 + bq * 8] = nBl;
        int kn = (kc + 1 < 16) ? (kc + 1) * 32 : kc * 32;
        {
            const unsigned short* pa = g_xnh + (size_t)(m0 + ai) * D_ + kn + asg * 16;
            const unsigned short* qa = g_xnl + (size_t)(m0 + ai) * D_ + kn + asg * 16;
            nA0h = ((const uint4*)pa)[0]; nA1h = ((const uint4*)pa)[1];
            nA0l = ((const uint4*)qa)[0]; nA1l = ((const uint4*)qa)[1];
            const unsigned short* pb = g_Wth + (size_t)(h * 64 + bd) * D_ + kn + bq * 8;
            const unsigned short* qb = g_Wtl + (size_t)(h * 64 + bd) * D_ + kn + bq * 8;
            nBh = *(const uint4*)pb; nBl = *(const uint4*)qb;
        }
        __syncthreads();                       // tiles visible
        mma_chunk(acc, ah_s, al_s, bh_s, bl_s, ibase, lane);
    }

    int r = lane >> 2, c2 = (lane & 3) * 2;
#pragma unroll
    for (int nt = 0; nt < 8; nt++) {
        size_t i1 = (size_t)(m0 + ibase + r) * D_ + h * DH_ + nt * 8 + c2;
        size_t i2 = (size_t)(m0 + ibase + r + 8) * D_ + h * DH_ + nt * 8 + c2;
        *(float2*)&g_h[i1] = make_float2(acc[nt][0], acc[nt][1]);
        *(float2*)&g_h[i2] = make_float2(acc[nt][2], acc[nt][3]);
    }
}

// ---------------- f_src/f_dst (pre-scaled by log2 e) ----------------
__global__ void fsd_kernel(const float* __restrict__ a_src, const float* __restrict__ a_dst) {
    int gw   = (blockIdx.x * blockDim.x + threadIdx.x) >> 5;
    int lane = threadIdx.x & 31;
    int h = gw & 7, bn = gw >> 3;
    float2 hv = *(const float2*)(g_h + (size_t)bn * D_ + h * DH_ + lane * 2);
    float2 as = *(const float2*)(a_src + h * DH_ + lane * 2);
    float2 ad = *(const float2*)(a_dst + h * DH_ + lane * 2);
    float s = hv.x * as.x + hv.y * as.y;
    float d = hv.x * ad.x + hv.y * ad.y;
#pragma unroll
    for (int o = 16; o; o >>= 1) {
        s += __shfl_xor_sync(0xffffffffu, s, o);
        d += __shfl_xor_sync(0xffffffffu, d, o);
    }
    if (lane == 0) {
        int b = bn >> 10, n = bn & 1023;
        g_fs[(b * H_ + h) * N_ + n] = s * L2E;
        g_fd[(b * H_ + h) * N_ + n] = d * L2E;
    }
}

__global__ void gmax_kernel() {
    int bh = blockIdx.x, t = threadIdx.x;
    float m = -1e30f;
    for (int i = t; i < N_; i += 256) m = fmaxf(m, g_fd[bh * N_ + i]);
#pragma unroll
    for (int o = 16; o; o >>= 1) m = fmaxf(m, __shfl_xor_sync(0xffffffffu, m, o));
    __shared__ float sm[8];
    if ((t & 31) == 0) sm[t >> 5] = m;
    __syncthreads();
    if (t == 0) {
        float mm = sm[0];
#pragma unroll
        for (int i = 1; i < 8; i++) mm = fmaxf(mm, sm[i]);
        g_gmax[bh] = mm;
    }
}

// ---------------- h -> h^T bf16 split  [b][h][d][j] ----------------
__global__ void htrans_kernel() {
    __shared__ float s[32][33];
    int bh = blockIdx.z, j0 = blockIdx.x * 32, d0 = blockIdx.y * 32;
    int b = bh >> 3, h = bh & 7;
    int tx = threadIdx.x, ty = threadIdx.y;
#pragma unroll
    for (int k = 0; k < 4; k++) {
        int jj = ty + k * 8;
        s[jj][tx] = g_h[(size_t)(b * N_ + j0 + jj) * D_ + h * DH_ + d0 + tx];
    }
    __syncthreads();
#pragma unroll
    for (int k = 0; k < 4; k++) {
        int dd = ty + k * 8;
        float v = s[tx][dd];
        float rem;
        unsigned short hi = bfsplit(v, rem);
        size_t idx = (size_t)bh * DH_ * N_ + (size_t)(d0 + dd) * N_ + j0 + tx;
        g_hTh[idx] = hi;
        g_hTl[idx] = bfround(rem);
    }
}

// ---------------- attention: tensorized P @ h ----------------
__global__ __launch_bounds__(256) void attn_kernel(const float* __restrict__ x) {
    __shared__ unsigned short ph_s[128 * 40], pl_s[128 * 40];
    __shared__ unsigned short bh_s[64 * 40],  bl_s[64 * 40];
    __shared__ float fds_s[32];
    __shared__ float fss[128], mss[128], dens[128];

    int b = blockIdx.z, h = blockIdx.y;
    int i0 = blockIdx.x * 128;
    int bh = b * H_ + h;
    int t = threadIdx.x, warp = t >> 5, lane = t & 31;
    int ibase = warp * 16;
    int il = t >> 1, s = t & 1;          // P-build: row il, col half s
    int bd = t >> 2, bq = t & 3;         // h-tile: row d, uint4 seg

    if (t < 128) {
        float fsv = g_fs[bh * N_ + i0 + t];
        fss[t] = fsv;
        float bound = fsv + g_gmax[bh];
        mss[t] = fmaxf(bound, 0.2f * bound);
    }

    float acc[8][4];
#pragma unroll
    for (int i = 0; i < 8; i++)
#pragma unroll
        for (int j = 0; j < 4; j++) acc[i][j] = 0.0f;
    float den = 0.0f;

    // prefetch chunk 0
    float4 nfd;
    unsigned nadj;
    uint4 nBh, nBl;
    {
        if (t < 8) nfd = *(const float4*)(g_fd + bh * N_ + t * 4);
        nadj = g_adjb[(size_t)(b * N_ + i0 + il) * NW_ + 0];
        const unsigned short* pb = g_hTh + (size_t)bh * DH_ * N_ + (size_t)bd * N_ + bq * 8;
        const unsigned short* qb = g_hTl + (size_t)bh * DH_ * N_ + (size_t)bd * N_ + bq * 8;
        nBh = *(const uint4*)pb; nBl = *(const uint4*)qb;
    }
    __syncthreads();
    float fsv = fss[il], m = mss[il];

    for (int jt = 0; jt < 32; jt++) {
        __syncthreads();                         // (A) prev mma done
        if (t < 8) *(float4*)&fds_s[t * 4] = nfd;
        *(uint4*)&bh_s[bd * 40 + bq * 8] = nBh;
        *(uint4*)&bl_s[bd * 40 + bq * 8] = nBl;
        unsigned w = nadj;
        int jn = (jt + 1 < 32) ? jt + 1 : jt;
        {
            if (t < 8) nfd = *(const float4*)(g_fd + bh * N_ + jn * 32 + t * 4);
            nadj = g_adjb[(size_t)(b * N_ + i0 + il) * NW_ + jn];
            const unsigned short* pb = g_hTh + (size_t)bh * DH_ * N_ + (size_t)bd * N_ + jn * 32 + bq * 8;
            const unsigned short* qb = g_hTl + (size_t)bh * DH_ * N_ + (size_t)bd * N_ + jn * 32 + bq * 8;
            nBh = *(const uint4*)pb; nBl = *(const uint4*)qb;
        }
        __syncthreads();                         // (B) fds + h tiles visible

        // build P tile rows: thread -> row il, cols s*16 .. s*16+15
        int jb = s * 16;
#pragma unroll
        for (int qq = 0; qq < 16; qq += 4) {
            float4 f4 = *(const float4*)&fds_s[jb + qq];
            float fdv[4] = {f4.x, f4.y, f4.z, f4.w};
            unsigned short hi16[4], lo16[4];
#pragma unroll
            for (int u = 0; u < 4; u++) {
                float e  = fsv + fdv[u];
                float lr = fmaxf(e, 0.2f * e);
                float p  = ((w >> (jb + qq + u)) & 1u) ? fexp2f(lr - m) : 0.0f;
                den += p;
                float rem;
                hi16[u] = bfsplit(p, rem);
                lo16[u] = bfround(rem);
            }
            uint2 vh = make_uint2((unsigned)hi16[0] | ((unsigned)hi16[1] << 16),
                                  (unsigned)hi16[2] | ((unsigned)hi16[3] << 16));
            uint2 vl = make_uint2((unsigned)lo16[0] | ((unsigned)lo16[1] << 16),
                                  (unsigned)lo16[2] | ((unsigned)lo16[3] << 16));
            *(uint2*)&ph_s[il * 40 + jb + qq] = vh;
            *(uint2*)&pl_s[il * 40 + jb + qq] = vl;
        }
        __syncthreads();                         // (C) P visible
        mma_chunk(acc, ph_s, pl_s, bh_s, bl_s, ibase, lane);
    }

    // den: combine the two col-halves of each row
    den += __shfl_xor_sync(0xffffffffu, den, 1);
    dens[il] = den;
    __syncthreads();

    int r = lane >> 2, c2 = (lane & 3) * 2;
    float inv1 = 1.0f / dens[ibase + r];
    float inv2 = 1.0f / dens[ibase + r + 8];
#pragma unroll
    for (int nt = 0; nt < 8; nt++) {
        size_t i1 = (size_t)(b * N_ + i0 + ibase + r) * D_ + h * DH_ + nt * 8 + c2;
        size_t i2 = (size_t)(b * N_ + i0 + ibase + r + 8) * D_ + h * DH_ + nt * 8 + c2;
        float2 x1 = *(const float2*)(x + i1);
        float2 x2 = *(const float2*)(x + i2);
        float2 o1 = make_float2(x1.x + elu1(acc[nt][0] * inv1),
                                x1.y + elu1(acc[nt][1] * inv1));
        float2 o2 = make_float2(x2.x + elu1(acc[nt][2] * inv2),
                                x2.y + elu1(acc[nt][3] * inv2));
        *(float2*)&g_y[i1] = o1;
        *(float2*)&g_y[i2] = o2;
    }
}

// ---------------- launch ----------------
extern "C" void kernel_launch(void* const* d_in, const int* in_sizes, int n_in,
                              void* d_out, int out_size) {
    const float* x     = (const float*)d_in[0];
    const int*   adj   = (const int*)  d_in[2];
    const float* W     = (const float*)d_in[3];
    const float* a_src = (const float*)d_in[4];
    const float* a_dst = (const float*)d_in[5];
    const float* ln1g  = (const float*)d_in[6];
    const float* ln1b  = (const float*)d_in[7];
    const float* ln2g  = (const float*)d_in[8];
    const float* ln2b  = (const float*)d_in[9];
    float* out = (float*)d_out;

    ln1_kernel   <<<B_*N_, 128>>>(x, ln1g, ln1b);
    pack_adj_kernel<<<(B_*N_*N_) / 256, 256>>>(adj);
    prep_w_kernel<<<H_*DH_, 128>>>(W);
    gemm1t_kernel<<<dim3(B_*N_/128, H_), 256>>>();
    fsd_kernel   <<<B_*N_*H_/8, 256>>>(a_src, a_dst);
    gmax_kernel  <<<B_*H_, 256>>>();
    htrans_kernel<<<dim3(N_/32, DH_/32, B_*H_), dim3(32, 8)>>>();
    attn_kernel  <<<dim3(N_/128, H_, B_), 256>>>(x);
    ln2_kernel   <<<B_*N_, 128>>>(ln2g, ln2b, out);
}

// round 3
// speedup vs baseline: 2.8069x; 1.1331x over previous
#include <cuda_runtime.h>

#define B_ 8
#define N_ 1024
#define D_ 512
#define H_ 8
#define DH_ 64
#define NW_ (N_/32)
#define L2E 1.4426950408889634f

// ---------------- scratch ----------------
__device__ unsigned short g_xnh[B_*N_*D_];   // LN1 out, bf16 hi
__device__ unsigned short g_xnl[B_*N_*D_];   // LN1 out, bf16 lo
__device__ unsigned short g_Wth[H_*DH_*D_];  // W^T [h][d][k] bf16 hi
__device__ unsigned short g_Wtl[H_*DH_*D_];
__device__ float    g_h [B_*N_*D_];          // h fp32, [b][n][h][k]
__device__ unsigned short g_hTh[B_*H_*DH_*N_]; // h^T [b][h][d][j] bf16 hi
__device__ unsigned short g_hTl[B_*H_*DH_*N_];
__device__ float    g_fs[B_*H_*N_];          // f_src * log2(e)
__device__ float    g_fd[B_*H_*N_];          // f_dst * log2(e)
__device__ float    g_gmax[B_*H_];
__device__ unsigned g_adjb[B_*N_*NW_];
__device__ float    g_y [B_*N_*D_];
// factorized softmax terms
__device__ float    g_A[B_*H_*N_];           // exp2(fs+gm-m)
__device__ float    g_C[B_*H_*N_];           // exp2(0.2(fs+gm)-m)
__device__ float    g_T[B_*H_*N_];           // exp2(-(fs+gm)) threshold
__device__ float    g_u[B_*H_*N_];           // exp2(fd-gm)
__device__ float    g_v[B_*H_*N_];           // exp2(0.2(fd-gm))

// ---------------- helpers ----------------
__device__ __forceinline__ float fexp2f(float t) {   // 2^t, FMA pipe only
    t = fmaxf(t, -125.0f);
    float r = t + 12582912.0f;
    int   n = __float_as_int(r) - 0x4B400000;
    float f = t - (r - 12582912.0f);
    float p = 1.3333558146e-3f;
    p = fmaf(p, f, 9.6181291298e-3f);
    p = fmaf(p, f, 5.5504108664e-2f);
    p = fmaf(p, f, 2.4022650696e-1f);
    p = fmaf(p, f, 6.9314718056e-1f);
    p = fmaf(p, f, 1.0f);
    return __int_as_float(__float_as_int(p) + (n << 23));
}
__device__ __forceinline__ float elu1(float v) {
    return v > 0.0f ? v : (fexp2f(v * L2E) - 1.0f);
}
__device__ __forceinline__ unsigned short bfsplit(float x, float &rem) {
    unsigned xi = __float_as_uint(x);
    unsigned hb = (xi + 0x8000u) & 0xffff0000u;
    rem = x - __uint_as_float(hb);
    return (unsigned short)(hb >> 16);
}
__device__ __forceinline__ unsigned short bfround(float x) {
    return (unsigned short)(((__float_as_uint(x) + 0x8000u) & 0xffff0000u) >> 16);
}
__device__ __forceinline__ void mma16816(float* c, unsigned a0, unsigned a1,
                                         unsigned a2, unsigned a3,
                                         unsigned b0, unsigned b1) {
    asm volatile(
        "mma.sync.aligned.m16n8k16.row.col.f32.bf16.bf16.f32 "
        "{%0,%1,%2,%3}, {%4,%5,%6,%7}, {%8,%9}, {%0,%1,%2,%3};\n"
        : "+f"(c[0]), "+f"(c[1]), "+f"(c[2]), "+f"(c[3])
        : "r"(a0), "r"(a1), "r"(a2), "r"(a3), "r"(b0), "r"(b1));
}

// mma tile step, REORDERED for ILP: B frags for 4 accumulators loaded, then
// hh x4, hl x4, lh x4 issued -> same-acc dependency distance = 4 HMMA.
__device__ __forceinline__ void mma_chunk(float acc[8][4],
        const unsigned short* __restrict__ Ah, const unsigned short* __restrict__ Al,
        const unsigned short* __restrict__ Bh, const unsigned short* __restrict__ Bl,
        int ibase, int lane) {
    int r  = lane >> 2;
    int c2 = (lane & 3) * 2;
#pragma unroll
    for (int kk = 0; kk < 2; kk++) {
        const unsigned short* pA = Ah + (ibase + r) * 40 + kk * 16 + c2;
        const unsigned short* qA = Al + (ibase + r) * 40 + kk * 16 + c2;
        unsigned ah0 = *(const unsigned*)(pA);
        unsigned ah1 = *(const unsigned*)(pA + 8 * 40);
        unsigned ah2 = *(const unsigned*)(pA + 8);
        unsigned ah3 = *(const unsigned*)(pA + 8 * 40 + 8);
        unsigned al0 = *(const unsigned*)(qA);
        unsigned al1 = *(const unsigned*)(qA + 8 * 40);
        unsigned al2 = *(const unsigned*)(qA + 8);
        unsigned al3 = *(const unsigned*)(qA + 8 * 40 + 8);
#pragma unroll
        for (int g = 0; g < 2; g++) {
            unsigned bh[4][2], bl[4][2];
#pragma unroll
            for (int q = 0; q < 4; q++) {
                int nt = g * 4 + q;
                const unsigned short* pB = Bh + (nt * 8 + r) * 40 + kk * 16 + c2;
                const unsigned short* qB = Bl + (nt * 8 + r) * 40 + kk * 16 + c2;
                bh[q][0] = *(const unsigned*)(pB);
                bh[q][1] = *(const unsigned*)(pB + 8);
                bl[q][0] = *(const unsigned*)(qB);
                bl[q][1] = *(const unsigned*)(qB + 8);
            }
#pragma unroll
            for (int q = 0; q < 4; q++)
                mma16816(acc[g*4+q], ah0, ah1, ah2, ah3, bh[q][0], bh[q][1]);
#pragma unroll
            for (int q = 0; q < 4; q++)
                mma16816(acc[g*4+q], ah0, ah1, ah2, ah3, bl[q][0], bl[q][1]);
#pragma unroll
            for (int q = 0; q < 4; q++)
                mma16816(acc[g*4+q], al0, al1, al2, al3, bh[q][0], bh[q][1]);
        }
    }
}

// ---------------- LN1 (writes bf16 split) ----------------
__global__ void ln1_kernel(const float* __restrict__ x, const float* __restrict__ gw,
                           const float* __restrict__ bw) {
    int row = blockIdx.x, t = threadIdx.x;
    const float4 v = ((const float4*)(x + (size_t)row * D_))[t];
    float s = v.x + v.y + v.z + v.w;
    float q = v.x*v.x + v.y*v.y + v.z*v.z + v.w*v.w;
#pragma unroll
    for (int o = 16; o; o >>= 1) {
        s += __shfl_xor_sync(0xffffffffu, s, o);
        q += __shfl_xor_sync(0xffffffffu, q, o);
    }
    __shared__ float ss[4], qs[4];
    if ((t & 31) == 0) { ss[t >> 5] = s; qs[t >> 5] = q; }
    __syncthreads();
    s = ss[0] + ss[1] + ss[2] + ss[3];
    q = qs[0] + qs[1] + qs[2] + qs[3];
    float mean = s * (1.0f / D_);
    float var  = fmaxf(q * (1.0f / D_) - mean * mean, 0.0f);
    float inv  = 1.0f / (sqrtf(var) + 1e-6f);
    const float4 g4 = ((const float4*)gw)[t];
    const float4 b4 = ((const float4*)bw)[t];
    float o0 = fmaf(g4.x * (v.x - mean), inv, b4.x);
    float o1 = fmaf(g4.y * (v.y - mean), inv, b4.y);
    float o2 = fmaf(g4.z * (v.z - mean), inv, b4.z);
    float o3 = fmaf(g4.w * (v.w - mean), inv, b4.w);
    float r0, r1, r2, r3;
    unsigned short h0 = bfsplit(o0, r0), h1 = bfsplit(o1, r1);
    unsigned short h2 = bfsplit(o2, r2), h3 = bfsplit(o3, r3);
    uint2 vh = make_uint2((unsigned)h0 | ((unsigned)h1 << 16),
                          (unsigned)h2 | ((unsigned)h3 << 16));
    uint2 vl = make_uint2((unsigned)bfround(r0) | ((unsigned)bfround(r1) << 16),
                          (unsigned)bfround(r2) | ((unsigned)bfround(r3) << 16));
    *(uint2*)&g_xnh[(size_t)row * D_ + t * 4] = vh;
    *(uint2*)&g_xnl[(size_t)row * D_ + t * 4] = vl;
}

// ---------------- LN2 ----------------
__global__ void ln2_kernel(const float* __restrict__ gw, const float* __restrict__ bw,
                           float* __restrict__ out) {
    int row = blockIdx.x, t = threadIdx.x;
    const float4 v = ((const float4*)(g_y + (size_t)row * D_))[t];
    float s = v.x + v.y + v.z + v.w;
    float q = v.x*v.x + v.y*v.y + v.z*v.z + v.w*v.w;
#pragma unroll
    for (int o = 16; o; o >>= 1) {
        s += __shfl_xor_sync(0xffffffffu, s, o);
        q += __shfl_xor_sync(0xffffffffu, q, o);
    }
    __shared__ float ss[4], qs[4];
    if ((t & 31) == 0) { ss[t >> 5] = s; qs[t >> 5] = q; }
    __syncthreads();
    s = ss[0] + ss[1] + ss[2] + ss[3];
    q = qs[0] + qs[1] + qs[2] + qs[3];
    float mean = s * (1.0f / D_);
    float var  = fmaxf(q * (1.0f / D_) - mean * mean, 0.0f);
    float inv  = 1.0f / (sqrtf(var) + 1e-6f);
    const float4 g4 = ((const float4*)gw)[t];
    const float4 b4 = ((const float4*)bw)[t];
    float4 o;
    o.x = fmaf(g4.x * (v.x - mean), inv, b4.x);
    o.y = fmaf(g4.y * (v.y - mean), inv, b4.y);
    o.z = fmaf(g4.z * (v.z - mean), inv, b4.z);
    o.w = fmaf(g4.w * (v.w - mean), inv, b4.w);
    ((float4*)(out + (size_t)row * D_))[t] = o;
}

// ---------------- pack adj ----------------
__global__ void pack_adj_kernel(const int* __restrict__ adj) {
    int gw   = (blockIdx.x * blockDim.x + threadIdx.x) >> 5;
    int lane = threadIdx.x & 31;
    int v = adj[(size_t)gw * 32 + lane];
    unsigned m = __ballot_sync(0xffffffffu, v > 0);
    if (lane == 0) g_adjb[gw] = m;
}

// ---------------- W -> W^T bf16 split ----------------
__global__ void prep_w_kernel(const float* __restrict__ W) {
    int hd = blockIdx.x;             // 0..511 : h*64+d
    int h = hd >> 6, d = hd & 63;
    for (int k = threadIdx.x; k < D_; k += 128) {
        float v = W[(size_t)h * D_ * DH_ + (size_t)k * DH_ + d];
        float rem;
        unsigned short hi = bfsplit(v, rem);
        g_Wth[(size_t)hd * D_ + k] = hi;
        g_Wtl[(size_t)hd * D_ + k] = bfround(rem);
    }
}

// ---------------- GEMM1: h = xn @ W, tensorized bf16x3 ----------------
__global__ __launch_bounds__(256) void gemm1t_kernel() {
    __shared__ unsigned short ah_s[128 * 40], al_s[128 * 40];
    __shared__ unsigned short bh_s[64 * 40],  bl_s[64 * 40];

    int m0 = blockIdx.x * 128;
    int h  = blockIdx.y;
    int t = threadIdx.x, warp = t >> 5, lane = t & 31;
    int ibase = warp * 16;

    float acc[8][4];
#pragma unroll
    for (int i = 0; i < 8; i++)
#pragma unroll
        for (int j = 0; j < 4; j++) acc[i][j] = 0.0f;

    int ai = t >> 1, asg = t & 1;
    int bd = t >> 2, bq = t & 3;
    uint4 nA0h, nA1h, nA0l, nA1l, nBh, nBl;
    {
        const unsigned short* pa = g_xnh + (size_t)(m0 + ai) * D_ + asg * 16;
        const unsigned short* qa = g_xnl + (size_t)(m0 + ai) * D_ + asg * 16;
        nA0h = ((const uint4*)pa)[0]; nA1h = ((const uint4*)pa)[1];
        nA0l = ((const uint4*)qa)[0]; nA1l = ((const uint4*)qa)[1];
        const unsigned short* pb = g_Wth + (size_t)(h * 64 + bd) * D_ + bq * 8;
        const unsigned short* qb = g_Wtl + (size_t)(h * 64 + bd) * D_ + bq * 8;
        nBh = *(const uint4*)pb; nBl = *(const uint4*)qb;
    }

    for (int kc = 0; kc < 16; kc++) {
        __syncthreads();
        *(uint4*)&ah_s[ai * 40 + asg * 16]     = nA0h;
        *(uint4*)&ah_s[ai * 40 + asg * 16 + 8] = nA1h;
        *(uint4*)&al_s[ai * 40 + asg * 16]     = nA0l;
        *(uint4*)&al_s[ai * 40 + asg * 16 + 8] = nA1l;
        *(uint4*)&bh_s[bd * 40 + bq * 8] = nBh;
        *(uint4*)&bl_s[bd * 40 + bq * 8] = nBl;
        int kn = (kc + 1 < 16) ? (kc + 1) * 32 : kc * 32;
        {
            const unsigned short* pa = g_xnh + (size_t)(m0 + ai) * D_ + kn + asg * 16;
            const unsigned short* qa = g_xnl + (size_t)(m0 + ai) * D_ + kn + asg * 16;
            nA0h = ((const uint4*)pa)[0]; nA1h = ((const uint4*)pa)[1];
            nA0l = ((const uint4*)qa)[0]; nA1l = ((const uint4*)qa)[1];
            const unsigned short* pb = g_Wth + (size_t)(h * 64 + bd) * D_ + kn + bq * 8;
            const unsigned short* qb = g_Wtl + (size_t)(h * 64 + bd) * D_ + kn + bq * 8;
            nBh = *(const uint4*)pb; nBl = *(const uint4*)qb;
        }
        __syncthreads();
        mma_chunk(acc, ah_s, al_s, bh_s, bl_s, ibase, lane);
    }

    int r = lane >> 2, c2 = (lane & 3) * 2;
#pragma unroll
    for (int nt = 0; nt < 8; nt++) {
        size_t i1 = (size_t)(m0 + ibase + r) * D_ + h * DH_ + nt * 8 + c2;
        size_t i2 = (size_t)(m0 + ibase + r + 8) * D_ + h * DH_ + nt * 8 + c2;
        *(float2*)&g_h[i1] = make_float2(acc[nt][0], acc[nt][1]);
        *(float2*)&g_h[i2] = make_float2(acc[nt][2], acc[nt][3]);
    }
}

// ---------------- f_src/f_dst (pre-scaled by log2 e) ----------------
__global__ void fsd_kernel(const float* __restrict__ a_src, const float* __restrict__ a_dst) {
    int gw   = (blockIdx.x * blockDim.x + threadIdx.x) >> 5;
    int lane = threadIdx.x & 31;
    int h = gw & 7, bn = gw >> 3;
    float2 hv = *(const float2*)(g_h + (size_t)bn * D_ + h * DH_ + lane * 2);
    float2 as = *(const float2*)(a_src + h * DH_ + lane * 2);
    float2 ad = *(const float2*)(a_dst + h * DH_ + lane * 2);
    float s = hv.x * as.x + hv.y * as.y;
    float d = hv.x * ad.x + hv.y * ad.y;
#pragma unroll
    for (int o = 16; o; o >>= 1) {
        s += __shfl_xor_sync(0xffffffffu, s, o);
        d += __shfl_xor_sync(0xffffffffu, d, o);
    }
    if (lane == 0) {
        int b = bn >> 10, n = bn & 1023;
        g_fs[(b * H_ + h) * N_ + n] = s * L2E;
        g_fd[(b * H_ + h) * N_ + n] = d * L2E;
    }
}

__global__ void gmax_kernel() {
    int bh = blockIdx.x, t = threadIdx.x;
    float m = -1e30f;
    for (int i = t; i < N_; i += 256) m = fmaxf(m, g_fd[bh * N_ + i]);
#pragma unroll
    for (int o = 16; o; o >>= 1) m = fmaxf(m, __shfl_xor_sync(0xffffffffu, m, o));
    __shared__ float sm[8];
    if ((t & 31) == 0) sm[t >> 5] = m;
    __syncthreads();
    if (t == 0) {
        float mm = sm[0];
#pragma unroll
        for (int i = 1; i < 8; i++) mm = fmaxf(mm, sm[i]);
        g_gmax[bh] = mm;
    }
}

// ---------------- factorized softmax terms ----------------
// p_ij = adj * ( e>0 ? A_i*u_j : C_i*v_j ),  e>0  <=>  u_j > T_i
__global__ void uv_kernel() {
    int idx = blockIdx.x * 256 + threadIdx.x;     // bh*N + n
    int bh = idx >> 10;
    float gm = g_gmax[bh];
    float fs = g_fs[idx], fd = g_fd[idx];
    float bound = fs + gm;
    float m = fmaxf(bound, 0.2f * bound);
    g_A[idx] = fexp2f(bound - m);
    g_C[idx] = fexp2f(0.2f * bound - m);
    g_T[idx] = fexp2f(-bound);
    g_u[idx] = fexp2f(fd - gm);
    g_v[idx] = fexp2f(0.2f * (fd - gm));
}

// ---------------- h -> h^T bf16 split  [b][h][d][j] ----------------
__global__ void htrans_kernel() {
    __shared__ float s[32][33];
    int bh = blockIdx.z, j0 = blockIdx.x * 32, d0 = blockIdx.y * 32;
    int b = bh >> 3, h = bh & 7;
    int tx = threadIdx.x, ty = threadIdx.y;
#pragma unroll
    for (int k = 0; k < 4; k++) {
        int jj = ty + k * 8;
        s[jj][tx] = g_h[(size_t)(b * N_ + j0 + jj) * D_ + h * DH_ + d0 + tx];
    }
    __syncthreads();
#pragma unroll
    for (int k = 0; k < 4; k++) {
        int dd = ty + k * 8;
        float v = s[tx][dd];
        float rem;
        unsigned short hi = bfsplit(v, rem);
        size_t idx = (size_t)bh * DH_ * N_ + (size_t)(d0 + dd) * N_ + j0 + tx;
        g_hTh[idx] = hi;
        g_hTl[idx] = bfround(rem);
    }
}

// ---------------- attention: tensorized P @ h, factorized P build ----------------
__global__ __launch_bounds__(256) void attn_kernel(const float* __restrict__ x) {
    __shared__ unsigned short ph_s[128 * 40], pl_s[128 * 40];
    __shared__ unsigned short bh_s[64 * 40],  bl_s[64 * 40];
    __shared__ float us_[32], vs_[32];
    __shared__ float As_[128], Cs_[128], Ts_[128], dens[128];

    int b = blockIdx.z, h = blockIdx.y;
    int i0 = blockIdx.x * 128;
    int bh = b * H_ + h;
    int t = threadIdx.x, warp = t >> 5, lane = t & 31;
    int ibase = warp * 16;
    int il = t >> 1, s = t & 1;
    int bd = t >> 2, bq = t & 3;

    if (t < 128) {
        int gi = bh * N_ + i0 + t;
        As_[t] = g_A[gi];
        Cs_[t] = g_C[gi];
        Ts_[t] = g_T[gi];
    }

    float acc[8][4];
#pragma unroll
    for (int i = 0; i < 8; i++)
#pragma unroll
        for (int j = 0; j < 4; j++) acc[i][j] = 0.0f;
    float den = 0.0f;

    // prefetch chunk 0
    float4 nuv;
    unsigned nadj;
    uint4 nBh, nBl;
    {
        if (t < 8)       nuv = *(const float4*)(g_u + bh * N_ + t * 4);
        else if (t < 16) nuv = *(const float4*)(g_v + bh * N_ + (t - 8) * 4);
        nadj = g_adjb[(size_t)(b * N_ + i0 + il) * NW_ + 0];
        const unsigned short* pb = g_hTh + (size_t)bh * DH_ * N_ + (size_t)bd * N_ + bq * 8;
        const unsigned short* qb = g_hTl + (size_t)bh * DH_ * N_ + (size_t)bd * N_ + bq * 8;
        nBh = *(const uint4*)pb; nBl = *(const uint4*)qb;
    }
    __syncthreads();
    float fA = As_[il], fC = Cs_[il], fT = Ts_[il];

    for (int jt = 0; jt < 32; jt++) {
        __syncthreads();                         // (A) prev mma done
        if (t < 8)       *(float4*)&us_[t * 4]       = nuv;
        else if (t < 16) *(float4*)&vs_[(t - 8) * 4] = nuv;
        *(uint4*)&bh_s[bd * 40 + bq * 8] = nBh;
        *(uint4*)&bl_s[bd * 40 + bq * 8] = nBl;
        unsigned w = nadj;
        int jn = (jt + 1 < 32) ? jt + 1 : jt;
        {
            if (t < 8)       nuv = *(const float4*)(g_u + bh * N_ + jn * 32 + t * 4);
            else if (t < 16) nuv = *(const float4*)(g_v + bh * N_ + jn * 32 + (t - 8) * 4);
            nadj = g_adjb[(size_t)(b * N_ + i0 + il) * NW_ + jn];
            const unsigned short* pb = g_hTh + (size_t)bh * DH_ * N_ + (size_t)bd * N_ + jn * 32 + bq * 8;
            const unsigned short* qb = g_hTl + (size_t)bh * DH_ * N_ + (size_t)bd * N_ + jn * 32 + bq * 8;
            nBh = *(const uint4*)pb; nBl = *(const uint4*)qb;
        }
        __syncthreads();                         // (B) tiles visible

        // build P tile: row il, cols s*16 .. s*16+15  (no exp, no rounding net)
        int jb = s * 16;
#pragma unroll
        for (int qq = 0; qq < 16; qq += 4) {
            float4 u4 = *(const float4*)&us_[jb + qq];
            float4 v4 = *(const float4*)&vs_[jb + qq];
            float uu[4] = {u4.x, u4.y, u4.z, u4.w};
            float vv[4] = {v4.x, v4.y, v4.z, v4.w};
            unsigned pb_[4], lb_[4];
#pragma unroll
            for (int e = 0; e < 4; e++) {
                bool c = uu[e] > fT;
                float p = (c ? fA : fC) * (c ? uu[e] : vv[e]);
                p = ((w >> (jb + qq + e)) & 1u) ? p : 0.0f;
                den += p;
                unsigned pi = __float_as_uint(p);
                unsigned hb = pi & 0xffff0000u;
                float lo = p - __uint_as_float(hb);
                pb_[e] = hb;
                lb_[e] = __float_as_uint(lo);
            }
            uint2 vhw = make_uint2(__byte_perm(pb_[0], pb_[1], 0x7632),
                                   __byte_perm(pb_[2], pb_[3], 0x7632));
            uint2 vlw = make_uint2(__byte_perm(lb_[0], lb_[1], 0x7632),
                                   __byte_perm(lb_[2], lb_[3], 0x7632));
            *(uint2*)&ph_s[il * 40 + jb + qq] = vhw;
            *(uint2*)&pl_s[il * 40 + jb + qq] = vlw;
        }
        __syncthreads();                         // (C) P visible
        mma_chunk(acc, ph_s, pl_s, bh_s, bl_s, ibase, lane);
    }

    den += __shfl_xor_sync(0xffffffffu, den, 1);
    dens[il] = den;
    __syncthreads();

    int r = lane >> 2, c2 = (lane & 3) * 2;
    float inv1 = 1.0f / dens[ibase + r];
    float inv2 = 1.0f / dens[ibase + r + 8];
#pragma unroll
    for (int nt = 0; nt < 8; nt++) {
        size_t i1 = (size_t)(b * N_ + i0 + ibase + r) * D_ + h * DH_ + nt * 8 + c2;
        size_t i2 = (size_t)(b * N_ + i0 + ibase + r + 8) * D_ + h * DH_ + nt * 8 + c2;
        float2 x1 = *(const float2*)(x + i1);
        float2 x2 = *(const float2*)(x + i2);
        float2 o1 = make_float2(x1.x + elu1(acc[nt][0] * inv1),
                                x1.y + elu1(acc[nt][1] * inv1));
        float2 o2 = make_float2(x2.x + elu1(acc[nt][2] * inv2),
                                x2.y + elu1(acc[nt][3] * inv2));
        *(float2*)&g_y[i1] = o1;
        *(float2*)&g_y[i2] = o2;
    }
}

// ---------------- launch ----------------
extern "C" void kernel_launch(void* const* d_in, const int* in_sizes, int n_in,
                              void* d_out, int out_size) {
    const float* x     = (const float*)d_in[0];
    const int*   adj   = (const int*)  d_in[2];
    const float* W     = (const float*)d_in[3];
    const float* a_src = (const float*)d_in[4];
    const float* a_dst = (const float*)d_in[5];
    const float* ln1g  = (const float*)d_in[6];
    const float* ln1b  = (const float*)d_in[7];
    const float* ln2g  = (const float*)d_in[8];
    const float* ln2b  = (const float*)d_in[9];
    float* out = (float*)d_out;

    ln1_kernel   <<<B_*N_, 128>>>(x, ln1g, ln1b);
    pack_adj_kernel<<<(B_*N_*N_) / 256, 256>>>(adj);
    prep_w_kernel<<<H_*DH_, 128>>>(W);
    gemm1t_kernel<<<dim3(B_*N_/128, H_), 256>>>();
    fsd_kernel   <<<B_*N_*H_/8, 256>>>(a_src, a_dst);
    gmax_kernel  <<<B_*H_, 256>>>();
    uv_kernel    <<<B_*H_*N_/256, 256>>>();
    htrans_kernel<<<dim3(N_/32, DH_/32, B_*H_), dim3(32, 8)>>>();
    attn_kernel  <<<dim3(N_/128, H_, B_), 256>>>(x);
    ln2_kernel   <<<B_*N_, 128>>>(ln2g, ln2b, out);
}

// round 4
// speedup vs baseline: 2.8188x; 1.0043x over previous
#include <cuda_runtime.h>

#define B_ 8
#define N_ 1024
#define D_ 512
#define H_ 8
#define DH_ 64
#define NW_ (N_/32)
#define L2E 1.4426950408889634f

// ---------------- scratch ----------------
__device__ unsigned short g_xnh[B_*N_*D_];   // LN1 out, bf16 hi
__device__ unsigned short g_xnl[B_*N_*D_];   // LN1 out, bf16 lo
__device__ unsigned short g_Wth[H_*DH_*D_];  // W^T [h][d][k] bf16 hi
__device__ unsigned short g_Wtl[H_*DH_*D_];
__device__ float    g_h [B_*N_*D_];          // h fp32, [b][n][h][k]
__device__ unsigned short g_hTh[B_*H_*DH_*N_]; // h^T [b][h][d][j] bf16 hi
__device__ unsigned short g_hTl[B_*H_*DH_*N_];
__device__ float    g_fs[B_*H_*N_];          // f_src * log2(e)
__device__ float    g_fd[B_*H_*N_];          // f_dst * log2(e)
__device__ float    g_gmax[B_*H_];
__device__ unsigned g_adjb[B_*N_*NW_];
__device__ float    g_y [B_*N_*D_];
// factorized softmax terms
__device__ float    g_A[B_*H_*N_];           // exp2(fs+gm-m)
__device__ float    g_C[B_*H_*N_];           // exp2(0.2(fs+gm)-m)
__device__ float    g_T[B_*H_*N_];           // exp2(-(fs+gm)) threshold
__device__ float    g_u[B_*H_*N_];           // exp2(fd-gm)
__device__ float    g_v[B_*H_*N_];           // exp2(0.2(fd-gm))

// ---------------- helpers ----------------
__device__ __forceinline__ float fexp2f(float t) {   // 2^t, FMA pipe only
    t = fmaxf(t, -125.0f);
    float r = t + 12582912.0f;
    int   n = __float_as_int(r) - 0x4B400000;
    float f = t - (r - 12582912.0f);
    float p = 1.3333558146e-3f;
    p = fmaf(p, f, 9.6181291298e-3f);
    p = fmaf(p, f, 5.5504108664e-2f);
    p = fmaf(p, f, 2.4022650696e-1f);
    p = fmaf(p, f, 6.9314718056e-1f);
    p = fmaf(p, f, 1.0f);
    return __int_as_float(__float_as_int(p) + (n << 23));
}
__device__ __forceinline__ float elu1(float v) {
    return v > 0.0f ? v : (fexp2f(v * L2E) - 1.0f);
}
__device__ __forceinline__ unsigned short bfsplit(float x, float &rem) {
    unsigned xi = __float_as_uint(x);
    unsigned hb = (xi + 0x8000u) & 0xffff0000u;
    rem = x - __uint_as_float(hb);
    return (unsigned short)(hb >> 16);
}
__device__ __forceinline__ unsigned short bfround(float x) {
    return (unsigned short)(((__float_as_uint(x) + 0x8000u) & 0xffff0000u) >> 16);
}
__device__ __forceinline__ void mma16816(float* c, unsigned a0, unsigned a1,
                                         unsigned a2, unsigned a3,
                                         unsigned b0, unsigned b1) {
    asm volatile(
        "mma.sync.aligned.m16n8k16.row.col.f32.bf16.bf16.f32 "
        "{%0,%1,%2,%3}, {%4,%5,%6,%7}, {%8,%9}, {%0,%1,%2,%3};\n"
        : "+f"(c[0]), "+f"(c[1]), "+f"(c[2]), "+f"(c[3])
        : "r"(a0), "r"(a1), "r"(a2), "r"(a3), "r"(b0), "r"(b1));
}

// mma tile step, REORDERED for ILP: B frags for 4 accumulators loaded, then
// hh x4, hl x4, lh x4 issued -> same-acc dependency distance = 4 HMMA.
__device__ __forceinline__ void mma_chunk(float acc[8][4],
        const unsigned short* __restrict__ Ah, const unsigned short* __restrict__ Al,
        const unsigned short* __restrict__ Bh, const unsigned short* __restrict__ Bl,
        int ibase, int lane) {
    int r  = lane >> 2;
    int c2 = (lane & 3) * 2;
#pragma unroll
    for (int kk = 0; kk < 2; kk++) {
        const unsigned short* pA = Ah + (ibase + r) * 40 + kk * 16 + c2;
        const unsigned short* qA = Al + (ibase + r) * 40 + kk * 16 + c2;
        unsigned ah0 = *(const unsigned*)(pA);
        unsigned ah1 = *(const unsigned*)(pA + 8 * 40);
        unsigned ah2 = *(const unsigned*)(pA + 8);
        unsigned ah3 = *(const unsigned*)(pA + 8 * 40 + 8);
        unsigned al0 = *(const unsigned*)(qA);
        unsigned al1 = *(const unsigned*)(qA + 8 * 40);
        unsigned al2 = *(const unsigned*)(qA + 8);
        unsigned al3 = *(const unsigned*)(qA + 8 * 40 + 8);
#pragma unroll
        for (int g = 0; g < 2; g++) {
            unsigned bh[4][2], bl[4][2];
#pragma unroll
            for (int q = 0; q < 4; q++) {
                int nt = g * 4 + q;
                const unsigned short* pB = Bh + (nt * 8 + r) * 40 + kk * 16 + c2;
                const unsigned short* qB = Bl + (nt * 8 + r) * 40 + kk * 16 + c2;
                bh[q][0] = *(const unsigned*)(pB);
                bh[q][1] = *(const unsigned*)(pB + 8);
                bl[q][0] = *(const unsigned*)(qB);
                bl[q][1] = *(const unsigned*)(qB + 8);
            }
#pragma unroll
            for (int q = 0; q < 4; q++)
                mma16816(acc[g*4+q], ah0, ah1, ah2, ah3, bh[q][0], bh[q][1]);
#pragma unroll
            for (int q = 0; q < 4; q++)
                mma16816(acc[g*4+q], ah0, ah1, ah2, ah3, bl[q][0], bl[q][1]);
#pragma unroll
            for (int q = 0; q < 4; q++)
                mma16816(acc[g*4+q], al0, al1, al2, al3, bh[q][0], bh[q][1]);
        }
    }
}

// ---------------- LN1 (writes bf16 split) ----------------
__global__ void ln1_kernel(const float* __restrict__ x, const float* __restrict__ gw,
                           const float* __restrict__ bw) {
    int row = blockIdx.x, t = threadIdx.x;
    const float4 v = ((const float4*)(x + (size_t)row * D_))[t];
    float s = v.x + v.y + v.z + v.w;
    float q = v.x*v.x + v.y*v.y + v.z*v.z + v.w*v.w;
#pragma unroll
    for (int o = 16; o; o >>= 1) {
        s += __shfl_xor_sync(0xffffffffu, s, o);
        q += __shfl_xor_sync(0xffffffffu, q, o);
    }
    __shared__ float ss[4], qs[4];
    if ((t & 31) == 0) { ss[t >> 5] = s; qs[t >> 5] = q; }
    __syncthreads();
    s = ss[0] + ss[1] + ss[2] + ss[3];
    q = qs[0] + qs[1] + qs[2] + qs[3];
    float mean = s * (1.0f / D_);
    float var  = fmaxf(q * (1.0f / D_) - mean * mean, 0.0f);
    float inv  = 1.0f / (sqrtf(var) + 1e-6f);
    const float4 g4 = ((const float4*)gw)[t];
    const float4 b4 = ((const float4*)bw)[t];
    float o0 = fmaf(g4.x * (v.x - mean), inv, b4.x);
    float o1 = fmaf(g4.y * (v.y - mean), inv, b4.y);
    float o2 = fmaf(g4.z * (v.z - mean), inv, b4.z);
    float o3 = fmaf(g4.w * (v.w - mean), inv, b4.w);
    float r0, r1, r2, r3;
    unsigned short h0 = bfsplit(o0, r0), h1 = bfsplit(o1, r1);
    unsigned short h2 = bfsplit(o2, r2), h3 = bfsplit(o3, r3);
    uint2 vh = make_uint2((unsigned)h0 | ((unsigned)h1 << 16),
                          (unsigned)h2 | ((unsigned)h3 << 16));
    uint2 vl = make_uint2((unsigned)bfround(r0) | ((unsigned)bfround(r1) << 16),
                          (unsigned)bfround(r2) | ((unsigned)bfround(r3) << 16));
    *(uint2*)&g_xnh[(size_t)row * D_ + t * 4] = vh;
    *(uint2*)&g_xnl[(size_t)row * D_ + t * 4] = vl;
}

// ---------------- LN2 ----------------
__global__ void ln2_kernel(const float* __restrict__ gw, const float* __restrict__ bw,
                           float* __restrict__ out) {
    int row = blockIdx.x, t = threadIdx.x;
    const float4 v = ((const float4*)(g_y + (size_t)row * D_))[t];
    float s = v.x + v.y + v.z + v.w;
    float q = v.x*v.x + v.y*v.y + v.z*v.z + v.w*v.w;
#pragma unroll
    for (int o = 16; o; o >>= 1) {
        s += __shfl_xor_sync(0xffffffffu, s, o);
        q += __shfl_xor_sync(0xffffffffu, q, o);
    }
    __shared__ float ss[4], qs[4];
    if ((t & 31) == 0) { ss[t >> 5] = s; qs[t >> 5] = q; }
    __syncthreads();
    s = ss[0] + ss[1] + ss[2] + ss[3];
    q = qs[0] + qs[1] + qs[2] + qs[3];
    float mean = s * (1.0f / D_);
    float var  = fmaxf(q * (1.0f / D_) - mean * mean, 0.0f);
    float inv  = 1.0f / (sqrtf(var) + 1e-6f);
    const float4 g4 = ((const float4*)gw)[t];
    const float4 b4 = ((const float4*)bw)[t];
    float4 o;
    o.x = fmaf(g4.x * (v.x - mean), inv, b4.x);
    o.y = fmaf(g4.y * (v.y - mean), inv, b4.y);
    o.z = fmaf(g4.z * (v.z - mean), inv, b4.z);
    o.w = fmaf(g4.w * (v.w - mean), inv, b4.w);
    ((float4*)(out + (size_t)row * D_))[t] = o;
}

// ---------------- pack adj ----------------
__global__ void pack_adj_kernel(const int* __restrict__ adj) {
    int gw   = (blockIdx.x * blockDim.x + threadIdx.x) >> 5;
    int lane = threadIdx.x & 31;
    int v = adj[(size_t)gw * 32 + lane];
    unsigned m = __ballot_sync(0xffffffffu, v > 0);
    if (lane == 0) g_adjb[gw] = m;
}

// ---------------- W -> W^T bf16 split ----------------
__global__ void prep_w_kernel(const float* __restrict__ W) {
    int hd = blockIdx.x;             // 0..511 : h*64+d
    int h = hd >> 6, d = hd & 63;
    for (int k = threadIdx.x; k < D_; k += 128) {
        float v = W[(size_t)h * D_ * DH_ + (size_t)k * DH_ + d];
        float rem;
        unsigned short hi = bfsplit(v, rem);
        g_Wth[(size_t)hd * D_ + k] = hi;
        g_Wtl[(size_t)hd * D_ + k] = bfround(rem);
    }
}

// ---------------- GEMM1: h = xn @ W, tensorized bf16x3 ----------------
__global__ __launch_bounds__(256) void gemm1t_kernel() {
    __shared__ unsigned short ah_s[128 * 40], al_s[128 * 40];
    __shared__ unsigned short bh_s[64 * 40],  bl_s[64 * 40];

    int m0 = blockIdx.x * 128;
    int h  = blockIdx.y;
    int t = threadIdx.x, warp = t >> 5, lane = t & 31;
    int ibase = warp * 16;

    float acc[8][4];
#pragma unroll
    for (int i = 0; i < 8; i++)
#pragma unroll
        for (int j = 0; j < 4; j++) acc[i][j] = 0.0f;

    int ai = t >> 1, asg = t & 1;
    int bd = t >> 2, bq = t & 3;
    uint4 nA0h, nA1h, nA0l, nA1l, nBh, nBl;
    {
        const unsigned short* pa = g_xnh + (size_t)(m0 + ai) * D_ + asg * 16;
        const unsigned short* qa = g_xnl + (size_t)(m0 + ai) * D_ + asg * 16;
        nA0h = ((const uint4*)pa)[0]; nA1h = ((const uint4*)pa)[1];
        nA0l = ((const uint4*)qa)[0]; nA1l = ((const uint4*)qa)[1];
        const unsigned short* pb = g_Wth + (size_t)(h * 64 + bd) * D_ + bq * 8;
        const unsigned short* qb = g_Wtl + (size_t)(h * 64 + bd) * D_ + bq * 8;
        nBh = *(const uint4*)pb; nBl = *(const uint4*)qb;
    }

    for (int kc = 0; kc < 16; kc++) {
        __syncthreads();
        *(uint4*)&ah_s[ai * 40 + asg * 16]     = nA0h;
        *(uint4*)&ah_s[ai * 40 + asg * 16 + 8] = nA1h;
        *(uint4*)&al_s[ai * 40 + asg * 16]     = nA0l;
        *(uint4*)&al_s[ai * 40 + asg * 16 + 8] = nA1l;
        *(uint4*)&bh_s[bd * 40 + bq * 8] = nBh;
        *(uint4*)&bl_s[bd * 40 + bq * 8] = nBl;
        int kn = (kc + 1 < 16) ? (kc + 1) * 32 : kc * 32;
        {
            const unsigned short* pa = g_xnh + (size_t)(m0 + ai) * D_ + kn + asg * 16;
            const unsigned short* qa = g_xnl + (size_t)(m0 + ai) * D_ + kn + asg * 16;
            nA0h = ((const uint4*)pa)[0]; nA1h = ((const uint4*)pa)[1];
            nA0l = ((const uint4*)qa)[0]; nA1l = ((const uint4*)qa)[1];
            const unsigned short* pb = g_Wth + (size_t)(h * 64 + bd) * D_ + kn + bq * 8;
            const unsigned short* qb = g_Wtl + (size_t)(h * 64 + bd) * D_ + kn + bq * 8;
            nBh = *(const uint4*)pb; nBl = *(const uint4*)qb;
        }
        __syncthreads();
        mma_chunk(acc, ah_s, al_s, bh_s, bl_s, ibase, lane);
    }

    int r = lane >> 2, c2 = (lane & 3) * 2;
#pragma unroll
    for (int nt = 0; nt < 8; nt++) {
        size_t i1 = (size_t)(m0 + ibase + r) * D_ + h * DH_ + nt * 8 + c2;
        size_t i2 = (size_t)(m0 + ibase + r + 8) * D_ + h * DH_ + nt * 8 + c2;
        *(float2*)&g_h[i1] = make_float2(acc[nt][0], acc[nt][1]);
        *(float2*)&g_h[i2] = make_float2(acc[nt][2], acc[nt][3]);
    }
}

// ---------------- f_src/f_dst (pre-scaled by log2 e) ----------------
__global__ void fsd_kernel(const float* __restrict__ a_src, const float* __restrict__ a_dst) {
    int gw   = (blockIdx.x * blockDim.x + threadIdx.x) >> 5;
    int lane = threadIdx.x & 31;
    int h = gw & 7, bn = gw >> 3;
    float2 hv = *(const float2*)(g_h + (size_t)bn * D_ + h * DH_ + lane * 2);
    float2 as = *(const float2*)(a_src + h * DH_ + lane * 2);
    float2 ad = *(const float2*)(a_dst + h * DH_ + lane * 2);
    float s = hv.x * as.x + hv.y * as.y;
    float d = hv.x * ad.x + hv.y * ad.y;
#pragma unroll
    for (int o = 16; o; o >>= 1) {
        s += __shfl_xor_sync(0xffffffffu, s, o);
        d += __shfl_xor_sync(0xffffffffu, d, o);
    }
    if (lane == 0) {
        int b = bn >> 10, n = bn & 1023;
        g_fs[(b * H_ + h) * N_ + n] = s * L2E;
        g_fd[(b * H_ + h) * N_ + n] = d * L2E;
    }
}

__global__ void gmax_kernel() {
    int bh = blockIdx.x, t = threadIdx.x;
    float m = -1e30f;
    for (int i = t; i < N_; i += 256) m = fmaxf(m, g_fd[bh * N_ + i]);
#pragma unroll
    for (int o = 16; o; o >>= 1) m = fmaxf(m, __shfl_xor_sync(0xffffffffu, m, o));
    __shared__ float sm[8];
    if ((t & 31) == 0) sm[t >> 5] = m;
    __syncthreads();
    if (t == 0) {
        float mm = sm[0];
#pragma unroll
        for (int i = 1; i < 8; i++) mm = fmaxf(mm, sm[i]);
        g_gmax[bh] = mm;
    }
}

// ---------------- factorized softmax terms ----------------
// p_ij = adj * ( e>0 ? A_i*u_j : C_i*v_j ),  e>0  <=>  u_j > T_i
__global__ void uv_kernel() {
    int idx = blockIdx.x * 256 + threadIdx.x;     // bh*N + n
    int bh = idx >> 10;
    float gm = g_gmax[bh];
    float fs = g_fs[idx], fd = g_fd[idx];
    float bound = fs + gm;
    float m = fmaxf(bound, 0.2f * bound);
    g_A[idx] = fexp2f(bound - m);
    g_C[idx] = fexp2f(0.2f * bound - m);
    g_T[idx] = fexp2f(-bound);
    g_u[idx] = fexp2f(fd - gm);
    g_v[idx] = fexp2f(0.2f * (fd - gm));
}

// ---------------- h -> h^T bf16 split  [b][h][d][j] ----------------
__global__ void htrans_kernel() {
    __shared__ float s[32][33];
    int bh = blockIdx.z, j0 = blockIdx.x * 32, d0 = blockIdx.y * 32;
    int b = bh >> 3, h = bh & 7;
    int tx = threadIdx.x, ty = threadIdx.y;
#pragma unroll
    for (int k = 0; k < 4; k++) {
        int jj = ty + k * 8;
        s[jj][tx] = g_h[(size_t)(b * N_ + j0 + jj) * D_ + h * DH_ + d0 + tx];
    }
    __syncthreads();
#pragma unroll
    for (int k = 0; k < 4; k++) {
        int dd = ty + k * 8;
        float v = s[tx][dd];
        float rem;
        unsigned short hi = bfsplit(v, rem);
        size_t idx = (size_t)bh * DH_ * N_ + (size_t)(d0 + dd) * N_ + j0 + tx;
        g_hTh[idx] = hi;
        g_hTl[idx] = bfround(rem);
    }
}

// ---------------- attention: tensorized P @ h, factorized P build ----------------
__global__ __launch_bounds__(256) void attn_kernel(const float* __restrict__ x) {
    __shared__ unsigned short ph_s[128 * 40], pl_s[128 * 40];
    __shared__ unsigned short bh_s[64 * 40],  bl_s[64 * 40];
    __shared__ float us_[32], vs_[32];
    __shared__ float As_[128], Cs_[128], Ts_[128], dens[128];

    int b = blockIdx.z, h = blockIdx.y;
    int i0 = blockIdx.x * 128;
    int bh = b * H_ + h;
    int t = threadIdx.x, warp = t >> 5, lane = t & 31;
    int ibase = warp * 16;
    int il = t >> 1, s = t & 1;
    int bd = t >> 2, bq = t & 3;

    if (t < 128) {
        int gi = bh * N_ + i0 + t;
        As_[t] = g_A[gi];
        Cs_[t] = g_C[gi];
        Ts_[t] = g_T[gi];
    }

    float acc[8][4];
#pragma unroll
    for (int i = 0; i < 8; i++)
#pragma unroll
        for (int j = 0; j < 4; j++) acc[i][j] = 0.0f;
    float den = 0.0f;

    // prefetch chunk 0
    float4 nuv;
    unsigned nadj;
    uint4 nBh, nBl;
    {
        if (t < 8)       nuv = *(const float4*)(g_u + bh * N_ + t * 4);
        else if (t < 16) nuv = *(const float4*)(g_v + bh * N_ + (t - 8) * 4);
        nadj = g_adjb[(size_t)(b * N_ + i0 + il) * NW_ + 0];
        const unsigned short* pb = g_hTh + (size_t)bh * DH_ * N_ + (size_t)bd * N_ + bq * 8;
        const unsigned short* qb = g_hTl + (size_t)bh * DH_ * N_ + (size_t)bd * N_ + bq * 8;
        nBh = *(const uint4*)pb; nBl = *(const uint4*)qb;
    }
    __syncthreads();
    float fA = As_[il], fC = Cs_[il], fT = Ts_[il];

    for (int jt = 0; jt < 32; jt++) {
        __syncthreads();                         // (A) prev mma done
        if (t < 8)       *(float4*)&us_[t * 4]       = nuv;
        else if (t < 16) *(float4*)&vs_[(t - 8) * 4] = nuv;
        *(uint4*)&bh_s[bd * 40 + bq * 8] = nBh;
        *(uint4*)&bl_s[bd * 40 + bq * 8] = nBl;
        unsigned w = nadj;
        int jn = (jt + 1 < 32) ? jt + 1 : jt;
        {
            if (t < 8)       nuv = *(const float4*)(g_u + bh * N_ + jn * 32 + t * 4);
            else if (t < 16) nuv = *(const float4*)(g_v + bh * N_ + jn * 32 + (t - 8) * 4);
            nadj = g_adjb[(size_t)(b * N_ + i0 + il) * NW_ + jn];
            const unsigned short* pb = g_hTh + (size_t)bh * DH_ * N_ + (size_t)bd * N_ + jn * 32 + bq * 8;
            const unsigned short* qb = g_hTl + (size_t)bh * DH_ * N_ + (size_t)bd * N_ + jn * 32 + bq * 8;
            nBh = *(const uint4*)pb; nBl = *(const uint4*)qb;
        }
        __syncthreads();                         // (B) tiles visible

        // build P tile: row il, cols s*16 .. s*16+15  (no exp, no rounding net)
        int jb = s * 16;
#pragma unroll
        for (int qq = 0; qq < 16; qq += 4) {
            float4 u4 = *(const float4*)&us_[jb + qq];
            float4 v4 = *(const float4*)&vs_[jb + qq];
            float uu[4] = {u4.x, u4.y, u4.z, u4.w};
            float vv[4] = {v4.x, v4.y, v4.z, v4.w};
            unsigned pb_[4], lb_[4];
#pragma unroll
            for (int e = 0; e < 4; e++) {
                bool c = uu[e] > fT;
                float p = (c ? fA : fC) * (c ? uu[e] : vv[e]);
                p = ((w >> (jb + qq + e)) & 1u) ? p : 0.0f;
                den += p;
                unsigned pi = __float_as_uint(p);
                unsigned hb = pi & 0xffff0000u;
                float lo = p - __uint_as_float(hb);
                pb_[e] = hb;
                lb_[e] = __float_as_uint(lo);
            }
            uint2 vhw = make_uint2(__byte_perm(pb_[0], pb_[1], 0x7632),
                                   __byte_perm(pb_[2], pb_[3], 0x7632));
            uint2 vlw = make_uint2(__byte_perm(lb_[0], lb_[1], 0x7632),
                                   __byte_perm(lb_[2], lb_[3], 0x7632));
            *(uint2*)&ph_s[il * 40 + jb + qq] = vhw;
            *(uint2*)&pl_s[il * 40 + jb + qq] = vlw;
        }
        __syncthreads();                         // (C) P visible
        mma_chunk(acc, ph_s, pl_s, bh_s, bl_s, ibase, lane);
    }

    den += __shfl_xor_sync(0xffffffffu, den, 1);
    dens[il] = den;
    __syncthreads();

    int r = lane >> 2, c2 = (lane & 3) * 2;
    float inv1 = 1.0f / dens[ibase + r];
    float inv2 = 1.0f / dens[ibase + r + 8];
#pragma unroll
    for (int nt = 0; nt < 8; nt++) {
        size_t i1 = (size_t)(b * N_ + i0 + ibase + r) * D_ + h * DH_ + nt * 8 + c2;
        size_t i2 = (size_t)(b * N_ + i0 + ibase + r + 8) * D_ + h * DH_ + nt * 8 + c2;
        float2 x1 = *(const float2*)(x + i1);
        float2 x2 = *(const float2*)(x + i2);
        float2 o1 = make_float2(x1.x + elu1(acc[nt][0] * inv1),
                                x1.y + elu1(acc[nt][1] * inv1));
        float2 o2 = make_float2(x2.x + elu1(acc[nt][2] * inv2),
                                x2.y + elu1(acc[nt][3] * inv2));
        *(float2*)&g_y[i1] = o1;
        *(float2*)&g_y[i2] = o2;
    }
}

// ---------------- launch ----------------
extern "C" void kernel_launch(void* const* d_in, const int* in_sizes, int n_in,
                              void* d_out, int out_size) {
    const float* x     = (const float*)d_in[0];
    const int*   adj   = (const int*)  d_in[2];
    const float* W     = (const float*)d_in[3];
    const float* a_src = (const float*)d_in[4];
    const float* a_dst = (const float*)d_in[5];
    const float* ln1g  = (const float*)d_in[6];
    const float* ln1b  = (const float*)d_in[7];
    const float* ln2g  = (const float*)d_in[8];
    const float* ln2b  = (const float*)d_in[9];
    float* out = (float*)d_out;

    ln1_kernel   <<<B_*N_, 128>>>(x, ln1g, ln1b);
    pack_adj_kernel<<<(B_*N_*N_) / 256, 256>>>(adj);
    prep_w_kernel<<<H_*DH_, 128>>>(W);
    gemm1t_kernel<<<dim3(B_*N_/128, H_), 256>>>();
    fsd_kernel   <<<B_*N_*H_/8, 256>>>(a_src, a_dst);
    gmax_kernel  <<<B_*H_, 256>>>();
    uv_kernel    <<<B_*H_*N_/256, 256>>>();
    htrans_kernel<<<dim3(N_/32, DH_/32, B_*H_), dim3(32, 8)>>>();
    attn_kernel  <<<dim3(N_/128, H_, B_), 256>>>(x);
    ln2_kernel   <<<B_*N_, 128>>>(ln2g, ln2b, out);
}

// round 6
// speedup vs baseline: 2.9437x; 1.0443x over previous
#include <cuda_runtime.h>
#include <cstdint>

#define B_ 8
#define N_ 1024
#define D_ 512
#define H_ 8
#define DH_ 64
#define NW_ (N_/32)
#define L2E 1.4426950408889634f

// ---------------- scratch ----------------
__device__ unsigned short g_xnh[B_*N_*D_];   // LN1 out, bf16 hi
__device__ unsigned short g_xnl[B_*N_*D_];   // LN1 out, bf16 lo
__device__ unsigned short g_Wth[H_*DH_*D_];  // W^T [h][d][k] bf16 hi
__device__ unsigned short g_Wtl[H_*DH_*D_];
__device__ float    g_h [B_*N_*D_];          // h fp32, [b][n][h][k]
__device__ unsigned short g_hTh[B_*H_*DH_*N_]; // h^T [b][h][d][j] bf16 hi
__device__ unsigned short g_hTl[B_*H_*DH_*N_];
__device__ float    g_fs[B_*H_*N_];          // f_src * log2(e)
__device__ float    g_fd[B_*H_*N_];          // f_dst * log2(e)
__device__ float    g_gmax[B_*H_];
__device__ unsigned g_adjb[B_*N_*NW_];
__device__ float    g_y [B_*N_*D_];
__device__ float    g_A[B_*H_*N_];
__device__ float    g_C[B_*H_*N_];
__device__ float    g_T[B_*H_*N_];
__device__ float    g_u[B_*H_*N_];
__device__ float    g_v[B_*H_*N_];

// ---------------- helpers ----------------
__device__ __forceinline__ float fexp2f(float t) {
    t = fmaxf(t, -125.0f);
    float r = t + 12582912.0f;
    int   n = __float_as_int(r) - 0x4B400000;
    float f = t - (r - 12582912.0f);
    float p = 1.3333558146e-3f;
    p = fmaf(p, f, 9.6181291298e-3f);
    p = fmaf(p, f, 5.5504108664e-2f);
    p = fmaf(p, f, 2.4022650696e-1f);
    p = fmaf(p, f, 6.9314718056e-1f);
    p = fmaf(p, f, 1.0f);
    return __int_as_float(__float_as_int(p) + (n << 23));
}
__device__ __forceinline__ float elu1(float v) {
    return v > 0.0f ? v : (fexp2f(v * L2E) - 1.0f);
}
__device__ __forceinline__ unsigned short bfsplit(float x, float &rem) {
    unsigned xi = __float_as_uint(x);
    unsigned hb = (xi + 0x8000u) & 0xffff0000u;
    rem = x - __uint_as_float(hb);
    return (unsigned short)(hb >> 16);
}
__device__ __forceinline__ unsigned short bfround(float x) {
    return (unsigned short)(((__float_as_uint(x) + 0x8000u) & 0xffff0000u) >> 16);
}
__device__ __forceinline__ unsigned smem_u32(const void* p) {
    unsigned a;
    asm("{ .reg .u64 t; cvta.to.shared.u64 t, %1; cvt.u32.u64 %0, t; }" : "=r"(a) : "l"(p));
    return a;
}
__device__ __forceinline__ void cpa16(unsigned s, const void* g) {
    asm volatile("cp.async.cg.shared.global [%0], [%1], 16;" :: "r"(s), "l"(g) : "memory");
}
#define CP_COMMIT() asm volatile("cp.async.commit_group;" ::: "memory")
#define CP_WAIT1()  asm volatile("cp.async.wait_group 1;" ::: "memory")

__device__ __forceinline__ void mma16816(float* c, unsigned a0, unsigned a1,
                                         unsigned a2, unsigned a3,
                                         unsigned b0, unsigned b1) {
    asm volatile(
        "mma.sync.aligned.m16n8k16.row.col.f32.bf16.bf16.f32 "
        "{%0,%1,%2,%3}, {%4,%5,%6,%7}, {%8,%9}, {%0,%1,%2,%3};\n"
        : "+f"(c[0]), "+f"(c[1]), "+f"(c[2]), "+f"(c[3])
        : "r"(a0), "r"(a1), "r"(a2), "r"(a3), "r"(b0), "r"(b1));
}

// mma tile step: A[128][32] (stride 40), B[64][32] (stride 40), hi/lo split.
// acc[8][4] per warp: rows ibase..ibase+15, cols 0..63.
__device__ __forceinline__ void mma_chunk(float acc[8][4],
        const unsigned short* __restrict__ Ah, const unsigned short* __restrict__ Al,
        const unsigned short* __restrict__ Bh, const unsigned short* __restrict__ Bl,
        int ibase, int lane) {
    int r  = lane >> 2;
    int c2 = (lane & 3) * 2;
#pragma unroll
    for (int kk = 0; kk < 2; kk++) {
        const unsigned short* pA = Ah + (ibase + r) * 40 + kk * 16 + c2;
        const unsigned short* qA = Al + (ibase + r) * 40 + kk * 16 + c2;
        unsigned ah0 = *(const unsigned*)(pA);
        unsigned ah1 = *(const unsigned*)(pA + 8 * 40);
        unsigned ah2 = *(const unsigned*)(pA + 8);
        unsigned ah3 = *(const unsigned*)(pA + 8 * 40 + 8);
        unsigned al0 = *(const unsigned*)(qA);
        unsigned al1 = *(const unsigned*)(qA + 8 * 40);
        unsigned al2 = *(const unsigned*)(qA + 8);
        unsigned al3 = *(const unsigned*)(qA + 8 * 40 + 8);
#pragma unroll
        for (int g = 0; g < 2; g++) {
            unsigned bh[4][2], bl[4][2];
#pragma unroll
            for (int q = 0; q < 4; q++) {
                int nt = g * 4 + q;
                const unsigned short* pB = Bh + (nt * 8 + r) * 40 + kk * 16 + c2;
                const unsigned short* qB = Bl + (nt * 8 + r) * 40 + kk * 16 + c2;
                bh[q][0] = *(const unsigned*)(pB);
                bh[q][1] = *(const unsigned*)(pB + 8);
                bl[q][0] = *(const unsigned*)(qB);
                bl[q][1] = *(const unsigned*)(qB + 8);
            }
#pragma unroll
            for (int q = 0; q < 4; q++)
                mma16816(acc[g*4+q], ah0, ah1, ah2, ah3, bh[q][0], bh[q][1]);
#pragma unroll
            for (int q = 0; q < 4; q++)
                mma16816(acc[g*4+q], ah0, ah1, ah2, ah3, bl[q][0], bl[q][1]);
#pragma unroll
            for (int q = 0; q < 4; q++)
                mma16816(acc[g*4+q], al0, al1, al2, al3, bh[q][0], bh[q][1]);
        }
    }
}

// ---------------- LN1 ----------------
__global__ void ln1_kernel(const float* __restrict__ x, const float* __restrict__ gw,
                           const float* __restrict__ bw) {
    int row = blockIdx.x, t = threadIdx.x;
    const float4 v = ((const float4*)(x + (size_t)row * D_))[t];
    float s = v.x + v.y + v.z + v.w;
    float q = v.x*v.x + v.y*v.y + v.z*v.z + v.w*v.w;
#pragma unroll
    for (int o = 16; o; o >>= 1) {
        s += __shfl_xor_sync(0xffffffffu, s, o);
        q += __shfl_xor_sync(0xffffffffu, q, o);
    }
    __shared__ float ss[4], qs[4];
    if ((t & 31) == 0) { ss[t >> 5] = s; qs[t >> 5] = q; }
    __syncthreads();
    s = ss[0] + ss[1] + ss[2] + ss[3];
    q = qs[0] + qs[1] + qs[2] + qs[3];
    float mean = s * (1.0f / D_);
    float var  = fmaxf(q * (1.0f / D_) - mean * mean, 0.0f);
    float inv  = 1.0f / (sqrtf(var) + 1e-6f);
    const float4 g4 = ((const float4*)gw)[t];
    const float4 b4 = ((const float4*)bw)[t];
    float o0 = fmaf(g4.x * (v.x - mean), inv, b4.x);
    float o1 = fmaf(g4.y * (v.y - mean), inv, b4.y);
    float o2 = fmaf(g4.z * (v.z - mean), inv, b4.z);
    float o3 = fmaf(g4.w * (v.w - mean), inv, b4.w);
    float r0, r1, r2, r3;
    unsigned short h0 = bfsplit(o0, r0), h1 = bfsplit(o1, r1);
    unsigned short h2 = bfsplit(o2, r2), h3 = bfsplit(o3, r3);
    uint2 vh = make_uint2((unsigned)h0 | ((unsigned)h1 << 16),
                          (unsigned)h2 | ((unsigned)h3 << 16));
    uint2 vl = make_uint2((unsigned)bfround(r0) | ((unsigned)bfround(r1) << 16),
                          (unsigned)bfround(r2) | ((unsigned)bfround(r3) << 16));
    *(uint2*)&g_xnh[(size_t)row * D_ + t * 4] = vh;
    *(uint2*)&g_xnl[(size_t)row * D_ + t * 4] = vl;
}

// ---------------- LN2 ----------------
__global__ void ln2_kernel(const float* __restrict__ gw, const float* __restrict__ bw,
                           float* __restrict__ out) {
    int row = blockIdx.x, t = threadIdx.x;
    const float4 v = ((const float4*)(g_y + (size_t)row * D_))[t];
    float s = v.x + v.y + v.z + v.w;
    float q = v.x*v.x + v.y*v.y + v.z*v.z + v.w*v.w;
#pragma unroll
    for (int o = 16; o; o >>= 1) {
        s += __shfl_xor_sync(0xffffffffu, s, o);
        q += __shfl_xor_sync(0xffffffffu, q, o);
    }
    __shared__ float ss[4], qs[4];
    if ((t & 31) == 0) { ss[t >> 5] = s; qs[t >> 5] = q; }
    __syncthreads();
    s = ss[0] + ss[1] + ss[2] + ss[3];
    q = qs[0] + qs[1] + qs[2] + qs[3];
    float mean = s * (1.0f / D_);
    float var  = fmaxf(q * (1.0f / D_) - mean * mean, 0.0f);
    float inv  = 1.0f / (sqrtf(var) + 1e-6f);
    const float4 g4 = ((const float4*)gw)[t];
    const float4 b4 = ((const float4*)bw)[t];
    float4 o;
    o.x = fmaf(g4.x * (v.x - mean), inv, b4.x);
    o.y = fmaf(g4.y * (v.y - mean), inv, b4.y);
    o.z = fmaf(g4.z * (v.z - mean), inv, b4.z);
    o.w = fmaf(g4.w * (v.w - mean), inv, b4.w);
    ((float4*)(out + (size_t)row * D_))[t] = o;
}

// ---------------- pack adj ----------------
__global__ void pack_adj_kernel(const int* __restrict__ adj) {
    int gw   = (blockIdx.x * blockDim.x + threadIdx.x) >> 5;
    int lane = threadIdx.x & 31;
    int v = adj[(size_t)gw * 32 + lane];
    unsigned m = __ballot_sync(0xffffffffu, v > 0);
    if (lane == 0) g_adjb[gw] = m;
}

// ---------------- W^T bf16 split ----------------
__global__ void prep_w_kernel(const float* __restrict__ W) {
    int hd = blockIdx.x;
    int h = hd >> 6, d = hd & 63;
    for (int k = threadIdx.x; k < D_; k += 128) {
        float v = W[(size_t)h * D_ * DH_ + (size_t)k * DH_ + d];
        float rem;
        g_Wth[(size_t)hd * D_ + k] = bfsplit(v, rem);
        g_Wtl[(size_t)hd * D_ + k] = bfround(rem);
    }
}

// ---------------- GEMM1: cp.async 3-stage ring, 1 sync/chunk ----------------
// stage (shorts): Ah@0 (128*40), Al@5120, Bh@10240 (64*40), Bl@12800; 15360 shorts
#define GM_DSM (3 * 15360 * 2)
__device__ __forceinline__ void g1_issue(unsigned sbase, int st, int c, int m0, int h, int t) {
    unsigned sb = sbase + (unsigned)st * 30720u;
    int k0 = c * 32;
#pragma unroll
    for (int i = t; i < 1536; i += 256) {
        if (i < 1024) {
            int tensor = i >> 9;
            int idx = i & 511;
            int row = idx >> 2, seg = idx & 3;
            const unsigned short* g = (tensor ? g_xnl : g_xnh) +
                                      (size_t)(m0 + row) * D_ + k0 + seg * 8;
            cpa16(sb + tensor * 10240u + row * 80u + seg * 16u, g);
        } else {
            int idx = i - 1024;
            int tensor = idx >> 8;
            idx &= 255;
            int row = idx >> 2, seg = idx & 3;
            const unsigned short* g = (tensor ? g_Wtl : g_Wth) +
                                      (size_t)(h * 64 + row) * D_ + k0 + seg * 8;
            cpa16(sb + 20480u + tensor * 5120u + row * 80u + seg * 16u, g);
        }
    }
}
__global__ __launch_bounds__(256) void gemm1t_kernel() {
    extern __shared__ unsigned short dsm[];
    unsigned sbase = smem_u32(dsm);
    int t = threadIdx.x, warp = t >> 5, lane = t & 31;
    int m0 = blockIdx.x * 128, h = blockIdx.y;
    int ibase = warp * 16;

    float acc[8][4];
#pragma unroll
    for (int i = 0; i < 8; i++)
#pragma unroll
        for (int j = 0; j < 4; j++) acc[i][j] = 0.0f;

    g1_issue(sbase, 0, 0, m0, h, t); CP_COMMIT();
    g1_issue(sbase, 1, 1, m0, h, t); CP_COMMIT();

    for (int c = 0; c < 16; c++) {
        CP_WAIT1();
        __syncthreads();
        if (c + 2 < 16) g1_issue(sbase, (c + 2) % 3, c + 2, m0, h, t);
        CP_COMMIT();
        unsigned short* stg = dsm + (c % 3) * 15360;
        mma_chunk(acc, stg, stg + 5120, stg + 10240, stg + 12800, ibase, lane);
    }

    int r = lane >> 2, c2 = (lane & 3) * 2;
#pragma unroll
    for (int nt = 0; nt < 8; nt++) {
        size_t i1 = (size_t)(m0 + ibase + r) * D_ + h * DH_ + nt * 8 + c2;
        size_t i2 = (size_t)(m0 + ibase + r + 8) * D_ + h * DH_ + nt * 8 + c2;
        *(float2*)&g_h[i1] = make_float2(acc[nt][0], acc[nt][1]);
        *(float2*)&g_h[i2] = make_float2(acc[nt][2], acc[nt][3]);
    }
}

// ---------------- fsd ----------------
__global__ void fsd_kernel(const float* __restrict__ a_src, const float* __restrict__ a_dst) {
    int gw   = (blockIdx.x * blockDim.x + threadIdx.x) >> 5;
    int lane = threadIdx.x & 31;
    int h = gw & 7, bn = gw >> 3;
    float2 hv = *(const float2*)(g_h + (size_t)bn * D_ + h * DH_ + lane * 2);
    float2 as = *(const float2*)(a_src + h * DH_ + lane * 2);
    float2 ad = *(const float2*)(a_dst + h * DH_ + lane * 2);
    float s = hv.x * as.x + hv.y * as.y;
    float d = hv.x * ad.x + hv.y * ad.y;
#pragma unroll
    for (int o = 16; o; o >>= 1) {
        s += __shfl_xor_sync(0xffffffffu, s, o);
        d += __shfl_xor_sync(0xffffffffu, d, o);
    }
    if (lane == 0) {
        int b = bn >> 10, n = bn & 1023;
        g_fs[(b * H_ + h) * N_ + n] = s * L2E;
        g_fd[(b * H_ + h) * N_ + n] = d * L2E;
    }
}

__global__ void gmax_kernel() {
    int bh = blockIdx.x, t = threadIdx.x;
    float m = -1e30f;
    for (int i = t; i < N_; i += 256) m = fmaxf(m, g_fd[bh * N_ + i]);
#pragma unroll
    for (int o = 16; o; o >>= 1) m = fmaxf(m, __shfl_xor_sync(0xffffffffu, m, o));
    __shared__ float sm[8];
    if ((t & 31) == 0) sm[t >> 5] = m;
    __syncthreads();
    if (t == 0) {
        float mm = sm[0];
#pragma unroll
        for (int i = 1; i < 8; i++) mm = fmaxf(mm, sm[i]);
        g_gmax[bh] = mm;
    }
}

__global__ void uv_kernel() {
    int idx = blockIdx.x * 256 + threadIdx.x;
    int bh = idx >> 10;
    float gm = g_gmax[bh];
    float fs = g_fs[idx], fd = g_fd[idx];
    float bound = fs + gm;
    float m = fmaxf(bound, 0.2f * bound);
    g_A[idx] = fexp2f(bound - m);
    g_C[idx] = fexp2f(0.2f * bound - m);
    g_T[idx] = fexp2f(-bound);
    g_u[idx] = fexp2f(fd - gm);
    g_v[idx] = fexp2f(0.2f * (fd - gm));
}

// ---------------- h -> h^T bf16 split ----------------
__global__ void htrans_kernel() {
    __shared__ float s[32][33];
    int bh = blockIdx.z, j0 = blockIdx.x * 32, d0 = blockIdx.y * 32;
    int b = bh >> 3, h = bh & 7;
    int tx = threadIdx.x, ty = threadIdx.y;
#pragma unroll
    for (int k = 0; k < 4; k++) {
        int jj = ty + k * 8;
        s[jj][tx] = g_h[(size_t)(b * N_ + j0 + jj) * D_ + h * DH_ + d0 + tx];
    }
    __syncthreads();
#pragma unroll
    for (int k = 0; k < 4; k++) {
        int dd = ty + k * 8;
        float v = s[tx][dd];
        float rem;
        size_t idx = (size_t)bh * DH_ * N_ + (size_t)(d0 + dd) * N_ + j0 + tx;
        g_hTh[idx] = bfsplit(v, rem);
        g_hTl[idx] = bfround(rem);
    }
}

// ---------------- attention: 3-stage h ring + double-buffered P, 1 sync/chunk ----
// dsm shorts: h stages 3*5120 (Bh@0, Bl@2560 per stage); P stages @15360: 2*10240
#define AT_DSM ((3 * 5120 + 2 * 10240) * 2)
__device__ __forceinline__ void at_issue(unsigned sbase, int st, int c, int bh, int t) {
    unsigned sb = sbase + (unsigned)st * 10240u;
    int j0 = c * 32;
#pragma unroll
    for (int i = t; i < 512; i += 256) {
        int tensor = i >> 8;
        int idx = i & 255;
        int row = idx >> 2, seg = idx & 3;
        const unsigned short* g = (tensor ? g_hTl : g_hTh) +
                                  (size_t)bh * DH_ * N_ + (size_t)row * N_ + j0 + seg * 8;
        cpa16(sb + tensor * 5120u + row * 80u + seg * 16u, g);
    }
}
__global__ __launch_bounds__(256, 3) void attn_kernel(const float* __restrict__ x) {
    extern __shared__ unsigned short dsm[];
    __shared__ float As_[128], Cs_[128], Ts_[128], dens[128];
    unsigned sbase = smem_u32(dsm);
    int t = threadIdx.x, warp = t >> 5, lane = t & 31;
    int b = blockIdx.z, h = blockIdx.y, i0 = blockIdx.x * 128;
    int bh = b * H_ + h;
    int ibase = warp * 16;
    int il = t >> 1, s = t & 1, jb = s * 16;

    if (t < 128) {
        int gi = bh * N_ + i0 + t;
        As_[t] = g_A[gi]; Cs_[t] = g_C[gi]; Ts_[t] = g_T[gi];
    }

    float acc[8][4];
#pragma unroll
    for (int i = 0; i < 8; i++)
#pragma unroll
        for (int j = 0; j < 4; j++) acc[i][j] = 0.0f;
    float den = 0.0f;

    at_issue(sbase, 0, 0, bh, t); CP_COMMIT();
    at_issue(sbase, 1, 1, bh, t); CP_COMMIT();
    __syncthreads();                       // As_/Cs_/Ts_ visible
    float fA = As_[il], fC = Cs_[il], fT = Ts_[il];

    // build P for chunk c into P stage (c&1)
    unsigned short* const P0 = dsm + 15360;
    auto buildP = [&](int c) {
        unsigned short* Ph = P0 + (c & 1) * 10240;
        unsigned short* Pl = Ph + 5120;
        unsigned w = g_adjb[(size_t)(b * N_ + i0 + il) * NW_ + c];
        const float* up = g_u + bh * N_ + c * 32 + jb;
        const float* vp = g_v + bh * N_ + c * 32 + jb;
#pragma unroll
        for (int qq = 0; qq < 16; qq += 4) {
            float4 u4 = *(const float4*)(up + qq);
            float4 v4 = *(const float4*)(vp + qq);
            float uu[4] = {u4.x, u4.y, u4.z, u4.w};
            float vv[4] = {v4.x, v4.y, v4.z, v4.w};
            unsigned pb_[4], lb_[4];
#pragma unroll
            for (int e = 0; e < 4; e++) {
                bool cs = uu[e] > fT;
                float p = (cs ? fA : fC) * (cs ? uu[e] : vv[e]);
                p = ((w >> (jb + qq + e)) & 1u) ? p : 0.0f;
                den += p;
                unsigned pi = __float_as_uint(p);
                unsigned hb = pi & 0xffff0000u;
                lb_[e] = __float_as_uint(p - __uint_as_float(hb));
                pb_[e] = hb;
            }
            *(uint2*)&Ph[il * 40 + jb + qq] =
                make_uint2(__byte_perm(pb_[0], pb_[1], 0x7632),
                           __byte_perm(pb_[2], pb_[3], 0x7632));
            *(uint2*)&Pl[il * 40 + jb + qq] =
                make_uint2(__byte_perm(lb_[0], lb_[1], 0x7632),
                           __byte_perm(lb_[2], lb_[3], 0x7632));
        }
    };
    buildP(0);

    for (int c = 0; c < 32; c++) {
        CP_WAIT1();
        __syncthreads();                   // h chunk c + P chunk c visible
        if (c + 2 < 32) at_issue(sbase, (c + 2) % 3, c + 2, bh, t);
        CP_COMMIT();
        if (c + 1 < 32) buildP(c + 1);
        unsigned short* hs = dsm + (c % 3) * 5120;
        unsigned short* Ph = P0 + (c & 1) * 10240;
        mma_chunk(acc, Ph, Ph + 5120, hs, hs + 2560, ibase, lane);
    }

    den += __shfl_xor_sync(0xffffffffu, den, 1);
    dens[il] = den;
    __syncthreads();

    int r = lane >> 2, c2 = (lane & 3) * 2;
    float inv1 = 1.0f / dens[ibase + r];
    float inv2 = 1.0f / dens[ibase + r + 8];
#pragma unroll
    for (int nt = 0; nt < 8; nt++) {
        size_t i1 = (size_t)(b * N_ + i0 + ibase + r) * D_ + h * DH_ + nt * 8 + c2;
        size_t i2 = (size_t)(b * N_ + i0 + ibase + r + 8) * D_ + h * DH_ + nt * 8 + c2;
        float2 x1 = *(const float2*)(x + i1);
        float2 x2 = *(const float2*)(x + i2);
        float2 o1 = make_float2(x1.x + elu1(acc[nt][0] * inv1),
                                x1.y + elu1(acc[nt][1] * inv1));
        float2 o2 = make_float2(x2.x + elu1(acc[nt][2] * inv2),
                                x2.y + elu1(acc[nt][3] * inv2));
        *(float2*)&g_y[i1] = o1;
        *(float2*)&g_y[i2] = o2;
    }
}

// ---------------- launch ----------------
extern "C" void kernel_launch(void* const* d_in, const int* in_sizes, int n_in,
                              void* d_out, int out_size) {
    const float* x     = (const float*)d_in[0];
    const int*   adj   = (const int*)  d_in[2];
    const float* W     = (const float*)d_in[3];
    const float* a_src = (const float*)d_in[4];
    const float* a_dst = (const float*)d_in[5];
    const float* ln1g  = (const float*)d_in[6];
    const float* ln1b  = (const float*)d_in[7];
    const float* ln2g  = (const float*)d_in[8];
    const float* ln2b  = (const float*)d_in[9];
    float* out = (float*)d_out;

    cudaFuncSetAttribute(gemm1t_kernel, cudaFuncAttributeMaxDynamicSharedMemorySize, GM_DSM);
    cudaFuncSetAttribute(attn_kernel,   cudaFuncAttributeMaxDynamicSharedMemorySize, AT_DSM);

    ln1_kernel   <<<B_*N_, 128>>>(x, ln1g, ln1b);
    pack_adj_kernel<<<(B_*N_*N_) / 256, 256>>>(adj);
    prep_w_kernel<<<H_*DH_, 128>>>(W);
    gemm1t_kernel<<<dim3(B_*N_/128, H_), 256, GM_DSM>>>();
    fsd_kernel   <<<B_*N_*H_/8, 256>>>(a_src, a_dst);
    gmax_kernel  <<<B_*H_, 256>>>();
    uv_kernel    <<<B_*H_*N_/256, 256>>>();
    htrans_kernel<<<dim3(N_/32, DH_/32, B_*H_), dim3(32, 8)>>>();
    attn_kernel  <<<dim3(N_/128, H_, B_), 256, AT_DSM>>>(x);
    ln2_kernel   <<<B_*N_, 128>>>(ln2g, ln2b, out);
}

// round 7
// speedup vs baseline: 3.1988x; 1.0867x over previous
#include <cuda_runtime.h>
#include <cstdint>

#define B_ 8
#define N_ 1024
#define D_ 512
#define H_ 8
#define DH_ 64
#define NW_ (N_/32)
#define L2E 1.4426950408889634f

// ---------------- scratch ----------------
__device__ unsigned short g_xnh[B_*N_*D_];
__device__ unsigned short g_xnl[B_*N_*D_];
__device__ unsigned short g_Wth[H_*DH_*D_];
__device__ unsigned short g_Wtl[H_*DH_*D_];
__device__ float    g_h [B_*N_*D_];
__device__ unsigned short g_hTh[B_*H_*DH_*N_];
__device__ unsigned short g_hTl[B_*H_*DH_*N_];
__device__ float    g_fs[B_*H_*N_];
__device__ float    g_fd[B_*H_*N_];
__device__ float    g_gmax[B_*H_];
__device__ unsigned g_adjb[B_*N_*NW_];
__device__ float    g_y [B_*N_*D_];
__device__ float    g_A[B_*H_*N_];
__device__ float    g_C[B_*H_*N_];
__device__ float    g_T[B_*H_*N_];
__device__ float    g_u[B_*H_*N_];
__device__ float    g_v[B_*H_*N_];

// ---------------- helpers ----------------
__device__ __forceinline__ float fexp2f(float t) {
    t = fmaxf(t, -125.0f);
    float r = t + 12582912.0f;
    int   n = __float_as_int(r) - 0x4B400000;
    float f = t - (r - 12582912.0f);
    float p = 1.3333558146e-3f;
    p = fmaf(p, f, 9.6181291298e-3f);
    p = fmaf(p, f, 5.5504108664e-2f);
    p = fmaf(p, f, 2.4022650696e-1f);
    p = fmaf(p, f, 6.9314718056e-1f);
    p = fmaf(p, f, 1.0f);
    return __int_as_float(__float_as_int(p) + (n << 23));
}
__device__ __forceinline__ float elu1(float v) {
    return v > 0.0f ? v : (fexp2f(v * L2E) - 1.0f);
}
__device__ __forceinline__ unsigned short bfsplit(float x, float &rem) {
    unsigned xi = __float_as_uint(x);
    unsigned hb = (xi + 0x8000u) & 0xffff0000u;
    rem = x - __uint_as_float(hb);
    return (unsigned short)(hb >> 16);
}
__device__ __forceinline__ unsigned short bfround(float x) {
    return (unsigned short)(((__float_as_uint(x) + 0x8000u) & 0xffff0000u) >> 16);
}
__device__ __forceinline__ unsigned smem_u32(const void* p) {
    unsigned a;
    asm("{ .reg .u64 t; cvta.to.shared.u64 t, %1; cvt.u32.u64 %0, t; }" : "=r"(a) : "l"(p));
    return a;
}
__device__ __forceinline__ void cpa16(unsigned s, const void* g) {
    asm volatile("cp.async.cg.shared.global [%0], [%1], 16;" :: "r"(s), "l"(g) : "memory");
}
#define CP_COMMIT() asm volatile("cp.async.commit_group;" ::: "memory")
#define CP_WAIT1()  asm volatile("cp.async.wait_group 1;" ::: "memory")
#define CP_WAIT2()  asm volatile("cp.async.wait_group 2;" ::: "memory")

__device__ __forceinline__ void mma16816(float* c, unsigned a0, unsigned a1,
                                         unsigned a2, unsigned a3,
                                         unsigned b0, unsigned b1) {
    asm volatile(
        "mma.sync.aligned.m16n8k16.row.col.f32.bf16.bf16.f32 "
        "{%0,%1,%2,%3}, {%4,%5,%6,%7}, {%8,%9}, {%0,%1,%2,%3};\n"
        : "+f"(c[0]), "+f"(c[1]), "+f"(c[2]), "+f"(c[3])
        : "r"(a0), "r"(a1), "r"(a2), "r"(a3), "r"(b0), "r"(b1));
}

// ---- k32 mma step (stride 40 shorts): used by attn ----
__device__ __forceinline__ void mma_chunk(float acc[8][4],
        const unsigned short* __restrict__ Ah, const unsigned short* __restrict__ Al,
        const unsigned short* __restrict__ Bh, const unsigned short* __restrict__ Bl,
        int ibase, int lane) {
    int r  = lane >> 2;
    int c2 = (lane & 3) * 2;
#pragma unroll
    for (int kk = 0; kk < 2; kk++) {
        const unsigned short* pA = Ah + (ibase + r) * 40 + kk * 16 + c2;
        const unsigned short* qA = Al + (ibase + r) * 40 + kk * 16 + c2;
        unsigned ah0 = *(const unsigned*)(pA);
        unsigned ah1 = *(const unsigned*)(pA + 8 * 40);
        unsigned ah2 = *(const unsigned*)(pA + 8);
        unsigned ah3 = *(const unsigned*)(pA + 8 * 40 + 8);
        unsigned al0 = *(const unsigned*)(qA);
        unsigned al1 = *(const unsigned*)(qA + 8 * 40);
        unsigned al2 = *(const unsigned*)(qA + 8);
        unsigned al3 = *(const unsigned*)(qA + 8 * 40 + 8);
#pragma unroll
        for (int g = 0; g < 2; g++) {
            unsigned bh[4][2], bl[4][2];
#pragma unroll
            for (int q = 0; q < 4; q++) {
                int nt = g * 4 + q;
                const unsigned short* pB = Bh + (nt * 8 + r) * 40 + kk * 16 + c2;
                const unsigned short* qB = Bl + (nt * 8 + r) * 40 + kk * 16 + c2;
                bh[q][0] = *(const unsigned*)(pB);
                bh[q][1] = *(const unsigned*)(pB + 8);
                bl[q][0] = *(const unsigned*)(qB);
                bl[q][1] = *(const unsigned*)(qB + 8);
            }
#pragma unroll
            for (int q = 0; q < 4; q++)
                mma16816(acc[g*4+q], ah0, ah1, ah2, ah3, bh[q][0], bh[q][1]);
#pragma unroll
            for (int q = 0; q < 4; q++)
                mma16816(acc[g*4+q], ah0, ah1, ah2, ah3, bl[q][0], bl[q][1]);
#pragma unroll
            for (int q = 0; q < 4; q++)
                mma16816(acc[g*4+q], al0, al1, al2, al3, bh[q][0], bh[q][1]);
        }
    }
}

// ---- k16 mma step (stride 24 shorts, 48B rows): used by gemm1 ----
__device__ __forceinline__ void mma_chunk16(float acc[8][4], const unsigned short* stg,
                                            int ibase, int lane) {
    const unsigned short* Ah = stg;
    const unsigned short* Al = stg + 3072;
    const unsigned short* Bh = stg + 6144;
    const unsigned short* Bl = stg + 7680;
    int r = lane >> 2, c2 = (lane & 3) * 2;
    const unsigned short* pA = Ah + (ibase + r) * 24 + c2;
    const unsigned short* qA = Al + (ibase + r) * 24 + c2;
    unsigned ah0 = *(const unsigned*)(pA);
    unsigned ah1 = *(const unsigned*)(pA + 192);
    unsigned ah2 = *(const unsigned*)(pA + 8);
    unsigned ah3 = *(const unsigned*)(pA + 200);
    unsigned al0 = *(const unsigned*)(qA);
    unsigned al1 = *(const unsigned*)(qA + 192);
    unsigned al2 = *(const unsigned*)(qA + 8);
    unsigned al3 = *(const unsigned*)(qA + 200);
#pragma unroll
    for (int g = 0; g < 2; g++) {
        unsigned bh[4][2], bl[4][2];
#pragma unroll
        for (int q = 0; q < 4; q++) {
            int nt = g * 4 + q;
            const unsigned short* pB = Bh + (nt * 8 + r) * 24 + c2;
            const unsigned short* qB = Bl + (nt * 8 + r) * 24 + c2;
            bh[q][0] = *(const unsigned*)(pB);
            bh[q][1] = *(const unsigned*)(pB + 8);
            bl[q][0] = *(const unsigned*)(qB);
            bl[q][1] = *(const unsigned*)(qB + 8);
        }
#pragma unroll
        for (int q = 0; q < 4; q++)
            mma16816(acc[g*4+q], ah0, ah1, ah2, ah3, bh[q][0], bh[q][1]);
#pragma unroll
        for (int q = 0; q < 4; q++)
            mma16816(acc[g*4+q], ah0, ah1, ah2, ah3, bl[q][0], bl[q][1]);
#pragma unroll
        for (int q = 0; q < 4; q++)
            mma16816(acc[g*4+q], al0, al1, al2, al3, bh[q][0], bh[q][1]);
    }
}

// ---------------- LN1 ----------------
__global__ void ln1_kernel(const float* __restrict__ x, const float* __restrict__ gw,
                           const float* __restrict__ bw) {
    int row = blockIdx.x, t = threadIdx.x;
    const float4 v = ((const float4*)(x + (size_t)row * D_))[t];
    float s = v.x + v.y + v.z + v.w;
    float q = v.x*v.x + v.y*v.y + v.z*v.z + v.w*v.w;
#pragma unroll
    for (int o = 16; o; o >>= 1) {
        s += __shfl_xor_sync(0xffffffffu, s, o);
        q += __shfl_xor_sync(0xffffffffu, q, o);
    }
    __shared__ float ss[4], qs[4];
    if ((t & 31) == 0) { ss[t >> 5] = s; qs[t >> 5] = q; }
    __syncthreads();
    s = ss[0] + ss[1] + ss[2] + ss[3];
    q = qs[0] + qs[1] + qs[2] + qs[3];
    float mean = s * (1.0f / D_);
    float var  = fmaxf(q * (1.0f / D_) - mean * mean, 0.0f);
    float inv  = 1.0f / (sqrtf(var) + 1e-6f);
    const float4 g4 = ((const float4*)gw)[t];
    const float4 b4 = ((const float4*)bw)[t];
    float o0 = fmaf(g4.x * (v.x - mean), inv, b4.x);
    float o1 = fmaf(g4.y * (v.y - mean), inv, b4.y);
    float o2 = fmaf(g4.z * (v.z - mean), inv, b4.z);
    float o3 = fmaf(g4.w * (v.w - mean), inv, b4.w);
    float r0, r1, r2, r3;
    unsigned short h0 = bfsplit(o0, r0), h1 = bfsplit(o1, r1);
    unsigned short h2 = bfsplit(o2, r2), h3 = bfsplit(o3, r3);
    uint2 vh = make_uint2((unsigned)h0 | ((unsigned)h1 << 16),
                          (unsigned)h2 | ((unsigned)h3 << 16));
    uint2 vl = make_uint2((unsigned)bfround(r0) | ((unsigned)bfround(r1) << 16),
                          (unsigned)bfround(r2) | ((unsigned)bfround(r3) << 16));
    *(uint2*)&g_xnh[(size_t)row * D_ + t * 4] = vh;
    *(uint2*)&g_xnl[(size_t)row * D_ + t * 4] = vl;
}

// ---------------- LN2 ----------------
__global__ void ln2_kernel(const float* __restrict__ gw, const float* __restrict__ bw,
                           float* __restrict__ out) {
    int row = blockIdx.x, t = threadIdx.x;
    const float4 v = ((const float4*)(g_y + (size_t)row * D_))[t];
    float s = v.x + v.y + v.z + v.w;
    float q = v.x*v.x + v.y*v.y + v.z*v.z + v.w*v.w;
#pragma unroll
    for (int o = 16; o; o >>= 1) {
        s += __shfl_xor_sync(0xffffffffu, s, o);
        q += __shfl_xor_sync(0xffffffffu, q, o);
    }
    __shared__ float ss[4], qs[4];
    if ((t & 31) == 0) { ss[t >> 5] = s; qs[t >> 5] = q; }
    __syncthreads();
    s = ss[0] + ss[1] + ss[2] + ss[3];
    q = qs[0] + qs[1] + qs[2] + qs[3];
    float mean = s * (1.0f / D_);
    float var  = fmaxf(q * (1.0f / D_) - mean * mean, 0.0f);
    float inv  = 1.0f / (sqrtf(var) + 1e-6f);
    const float4 g4 = ((const float4*)gw)[t];
    const float4 b4 = ((const float4*)bw)[t];
    float4 o;
    o.x = fmaf(g4.x * (v.x - mean), inv, b4.x);
    o.y = fmaf(g4.y * (v.y - mean), inv, b4.y);
    o.z = fmaf(g4.z * (v.z - mean), inv, b4.z);
    o.w = fmaf(g4.w * (v.w - mean), inv, b4.w);
    ((float4*)(out + (size_t)row * D_))[t] = o;
}

// ---------------- pack adj ----------------
__global__ void pack_adj_kernel(const int* __restrict__ adj) {
    int gw   = (blockIdx.x * blockDim.x + threadIdx.x) >> 5;
    int lane = threadIdx.x & 31;
    int v = adj[(size_t)gw * 32 + lane];
    unsigned m = __ballot_sync(0xffffffffu, v > 0);
    if (lane == 0) g_adjb[gw] = m;
}

// ---------------- W^T bf16 split ----------------
__global__ void prep_w_kernel(const float* __restrict__ W) {
    int hd = blockIdx.x;
    int h = hd >> 6, d = hd & 63;
    for (int k = threadIdx.x; k < D_; k += 128) {
        float v = W[(size_t)h * D_ * DH_ + (size_t)k * DH_ + d];
        float rem;
        g_Wth[(size_t)hd * D_ + k] = bfsplit(v, rem);
        g_Wtl[(size_t)hd * D_ + k] = bfround(rem);
    }
}

// ---------------- GEMM1: k16, 3-stage ring, fused fs/fd epilogue ----------------
// stage (shorts): Ah@0 (128*24), Al@3072, Bh@6144 (64*24), Bl@7680; 9216 sh = 18432 B
#define GM_DSM (3 * 9216 * 2)
__device__ __forceinline__ void g1_issue(unsigned sbase, int st, int c, int m0, int h, int t) {
    unsigned sb = sbase + (unsigned)st * 18432u;
    int k0 = c * 16;
#pragma unroll
    for (int i = t; i < 768; i += 256) {
        const unsigned short* g;
        unsigned dst;
        if (i < 512) {
            int tensor = i >> 8;
            int idx = i & 255;
            int row = idx >> 1, seg = idx & 1;
            g = (tensor ? g_xnl : g_xnh) + (size_t)(m0 + row) * D_ + k0 + seg * 8;
            dst = sb + tensor * 6144u + row * 48u + seg * 16u;
        } else {
            int idx = i - 512;
            int tensor = idx >> 7;
            idx &= 127;
            int row = idx >> 1, seg = idx & 1;
            g = (tensor ? g_Wtl : g_Wth) + (size_t)(h * 64 + row) * D_ + k0 + seg * 8;
            dst = sb + 12288u + tensor * 3072u + row * 48u + seg * 16u;
        }
        cpa16(dst, g);
    }
}
__global__ __launch_bounds__(256, 3) void gemm1t_kernel(const float* __restrict__ a_src,
                                                        const float* __restrict__ a_dst) {
    extern __shared__ unsigned short dsm[];
    __shared__ float as_s[64], ad_s[64];
    unsigned sbase = smem_u32(dsm);
    int t = threadIdx.x, warp = t >> 5, lane = t & 31;
    int m0 = blockIdx.x * 128, h = blockIdx.y;
    int ibase = warp * 16;

    if (t < 64) as_s[t] = a_src[h * 64 + t];
    else if (t < 128) ad_s[t - 64] = a_dst[h * 64 + t - 64];

    float acc[8][4];
#pragma unroll
    for (int i = 0; i < 8; i++)
#pragma unroll
        for (int j = 0; j < 4; j++) acc[i][j] = 0.0f;

    g1_issue(sbase, 0, 0, m0, h, t); CP_COMMIT();
    g1_issue(sbase, 1, 1, m0, h, t); CP_COMMIT();

    for (int c = 0; c < 32; c++) {
        CP_WAIT1();
        __syncthreads();
        if (c + 2 < 32) g1_issue(sbase, (c + 2) % 3, c + 2, m0, h, t);
        CP_COMMIT();
        mma_chunk16(acc, dsm + (c % 3) * 9216, ibase, lane);
    }

    int r = lane >> 2, q = lane & 3, c2 = q * 2;
    // fused fs/fd
    float fs1 = 0.f, fd1 = 0.f, fs2 = 0.f, fd2 = 0.f;
#pragma unroll
    for (int nt = 0; nt < 8; nt++) {
        float a0 = as_s[nt * 8 + c2], a1 = as_s[nt * 8 + c2 + 1];
        float d0 = ad_s[nt * 8 + c2], d1 = ad_s[nt * 8 + c2 + 1];
        fs1 = fmaf(acc[nt][0], a0, fmaf(acc[nt][1], a1, fs1));
        fd1 = fmaf(acc[nt][0], d0, fmaf(acc[nt][1], d1, fd1));
        fs2 = fmaf(acc[nt][2], a0, fmaf(acc[nt][3], a1, fs2));
        fd2 = fmaf(acc[nt][2], d0, fmaf(acc[nt][3], d1, fd2));
    }
#pragma unroll
    for (int o = 1; o <= 2; o <<= 1) {
        fs1 += __shfl_xor_sync(0xffffffffu, fs1, o);
        fd1 += __shfl_xor_sync(0xffffffffu, fd1, o);
        fs2 += __shfl_xor_sync(0xffffffffu, fs2, o);
        fd2 += __shfl_xor_sync(0xffffffffu, fd2, o);
    }
    if (q == 0) {
        int m1 = m0 + ibase + r, m2 = m1 + 8;
        int b1 = m1 >> 10, n1 = m1 & 1023;
        int b2 = m2 >> 10, n2 = m2 & 1023;
        g_fs[(b1 * H_ + h) * N_ + n1] = fs1 * L2E;
        g_fd[(b1 * H_ + h) * N_ + n1] = fd1 * L2E;
        g_fs[(b2 * H_ + h) * N_ + n2] = fs2 * L2E;
        g_fd[(b2 * H_ + h) * N_ + n2] = fd2 * L2E;
    }
#pragma unroll
    for (int nt = 0; nt < 8; nt++) {
        size_t i1 = (size_t)(m0 + ibase + r) * D_ + h * DH_ + nt * 8 + c2;
        size_t i2 = (size_t)(m0 + ibase + r + 8) * D_ + h * DH_ + nt * 8 + c2;
        *(float2*)&g_h[i1] = make_float2(acc[nt][0], acc[nt][1]);
        *(float2*)&g_h[i2] = make_float2(acc[nt][2], acc[nt][3]);
    }
}

// ---------------- gmax / uv ----------------
__global__ void gmax_kernel() {
    int bh = blockIdx.x, t = threadIdx.x;
    float m = -1e30f;
    for (int i = t; i < N_; i += 256) m = fmaxf(m, g_fd[bh * N_ + i]);
#pragma unroll
    for (int o = 16; o; o >>= 1) m = fmaxf(m, __shfl_xor_sync(0xffffffffu, m, o));
    __shared__ float sm[8];
    if ((t & 31) == 0) sm[t >> 5] = m;
    __syncthreads();
    if (t == 0) {
        float mm = sm[0];
#pragma unroll
        for (int i = 1; i < 8; i++) mm = fmaxf(mm, sm[i]);
        g_gmax[bh] = mm;
    }
}
__global__ void uv_kernel() {
    int idx = blockIdx.x * 256 + threadIdx.x;
    int bh = idx >> 10;
    float gm = g_gmax[bh];
    float fs = g_fs[idx], fd = g_fd[idx];
    float bound = fs + gm;
    float m = fmaxf(bound, 0.2f * bound);
    g_A[idx] = fexp2f(bound - m);
    g_C[idx] = fexp2f(0.2f * bound - m);
    g_T[idx] = fexp2f(-bound);
    g_u[idx] = fexp2f(fd - gm);
    g_v[idx] = fexp2f(0.2f * (fd - gm));
}

// ---------------- h -> h^T bf16 split ----------------
__global__ void htrans_kernel() {
    __shared__ float s[32][33];
    int bh = blockIdx.z, j0 = blockIdx.x * 32, d0 = blockIdx.y * 32;
    int b = bh >> 3, h = bh & 7;
    int tx = threadIdx.x, ty = threadIdx.y;
#pragma unroll
    for (int k = 0; k < 4; k++) {
        int jj = ty + k * 8;
        s[jj][tx] = g_h[(size_t)(b * N_ + j0 + jj) * D_ + h * DH_ + d0 + tx];
    }
    __syncthreads();
#pragma unroll
    for (int k = 0; k < 4; k++) {
        int dd = ty + k * 8;
        float v = s[tx][dd];
        float rem;
        size_t idx = (size_t)bh * DH_ * N_ + (size_t)(d0 + dd) * N_ + j0 + tx;
        g_hTh[idx] = bfsplit(v, rem);
        g_hTl[idx] = bfround(rem);
    }
}

// ---------------- attention ----------------
// dsm (shorts): h stages 3*5120 (Bh, Bl@+2560); P @15360: Ph 5120, Pl 5120; uv floats @25600
#define AT_DSM (25600 * 2 + 8192)
__device__ __forceinline__ void at_issue(unsigned sbase, int st, int c, int bh, int t) {
    unsigned sb = sbase + (unsigned)st * 10240u;
    int j0 = c * 32;
#pragma unroll
    for (int i = t; i < 512; i += 256) {
        int tensor = i >> 8;
        int idx = i & 255;
        int row = idx >> 2, seg = idx & 3;
        const unsigned short* g = (tensor ? g_hTl : g_hTh) +
                                  (size_t)bh * DH_ * N_ + (size_t)row * N_ + j0 + seg * 8;
        cpa16(sb + tensor * 5120u + row * 80u + seg * 16u, g);
    }
}
__global__ __launch_bounds__(256, 3) void attn_kernel(const float* __restrict__ x) {
    extern __shared__ unsigned short dsm[];
    __shared__ float As_[128], Cs_[128], Ts_[128], dens[128];
    unsigned sbase = smem_u32(dsm);
    int t = threadIdx.x, warp = t >> 5, lane = t & 31;
    int b = blockIdx.z, h = blockIdx.y, i0 = blockIdx.x * 128;
    int bh = b * H_ + h;
    int ibase = warp * 16;
    int il = t >> 1, s = t & 1, jb = s * 16;

    unsigned short* const Ph = dsm + 15360;
    unsigned short* const Pl = dsm + 20480;
    const float* uvf = (const float*)(dsm + 25600);

    // uv preload (8KB) then h chunks 0,1
#pragma unroll
    for (int i = t; i < 512; i += 256) {
        const float* g = (i < 256) ? (g_u + bh * N_ + i * 4)
                                   : (g_v + bh * N_ + (i - 256) * 4);
        cpa16(sbase + 51200u + (unsigned)i * 16u, g);
    }
    CP_COMMIT();
    at_issue(sbase, 0, 0, bh, t); CP_COMMIT();
    at_issue(sbase, 1, 1, bh, t); CP_COMMIT();

    if (t < 128) {
        int gi = bh * N_ + i0 + t;
        As_[t] = g_A[gi]; Cs_[t] = g_C[gi]; Ts_[t] = g_T[gi];
    }
    unsigned adjn = g_adjb[(size_t)(b * N_ + i0 + il) * NW_ + 0];

    float acc[8][4];
#pragma unroll
    for (int i = 0; i < 8; i++)
#pragma unroll
        for (int j = 0; j < 4; j++) acc[i][j] = 0.0f;
    float den = 0.0f;

    CP_WAIT2();               // uv complete (h0,h1 may be in flight)
    __syncthreads();          // uv + As/Cs/Ts visible
    float fA = As_[il], fC = Cs_[il], fT = Ts_[il];

    auto buildP = [&](int c, unsigned w) {
        const float* us = uvf + c * 32 + jb;
        const float* vs = uvf + 1024 + c * 32 + jb;
#pragma unroll
        for (int qq = 0; qq < 16; qq += 4) {
            float4 u4 = *(const float4*)(us + qq);
            float4 v4 = *(const float4*)(vs + qq);
            float uu[4] = {u4.x, u4.y, u4.z, u4.w};
            float vv[4] = {v4.x, v4.y, v4.z, v4.w};
            unsigned pb_[4], lb_[4];
#pragma unroll
            for (int e = 0; e < 4; e++) {
                bool cs = uu[e] > fT;
                float p = (cs ? fA : fC) * (cs ? uu[e] : vv[e]);
                p = ((w >> (jb + qq + e)) & 1u) ? p : 0.0f;
                den += p;
                unsigned pi = __float_as_uint(p);
                unsigned hb = pi & 0xffff0000u;
                lb_[e] = __float_as_uint(p - __uint_as_float(hb));
                pb_[e] = hb;
            }
            *(uint2*)&Ph[il * 40 + jb + qq] =
                make_uint2(__byte_perm(pb_[0], pb_[1], 0x7632),
                           __byte_perm(pb_[2], pb_[3], 0x7632));
            *(uint2*)&Pl[il * 40 + jb + qq] =
                make_uint2(__byte_perm(lb_[0], lb_[1], 0x7632),
                           __byte_perm(lb_[2], lb_[3], 0x7632));
        }
    };
    buildP(0, adjn);
    adjn = g_adjb[(size_t)(b * N_ + i0 + il) * NW_ + 1];

    for (int c = 0; c < 32; c++) {
        CP_WAIT1();
        __syncthreads();                // h(c) + P(c) ready
        if (c + 2 < 32) at_issue(sbase, (c + 2) % 3, c + 2, bh, t);
        CP_COMMIT();
        unsigned short* hs = dsm + (c % 3) * 5120;
        mma_chunk(acc, Ph, Pl, hs, hs + 2560, ibase, lane);
        __syncthreads();                // all done reading P
        if (c < 31) {
            buildP(c + 1, adjn);
            if (c < 30) adjn = g_adjb[(size_t)(b * N_ + i0 + il) * NW_ + c + 2];
        }
    }

    den += __shfl_xor_sync(0xffffffffu, den, 1);
    dens[il] = den;
    __syncthreads();

    int r = lane >> 2, c2 = (lane & 3) * 2;
    float inv1 = 1.0f / dens[ibase + r];
    float inv2 = 1.0f / dens[ibase + r + 8];
#pragma unroll
    for (int nt = 0; nt < 8; nt++) {
        size_t i1 = (size_t)(b * N_ + i0 + ibase + r) * D_ + h * DH_ + nt * 8 + c2;
        size_t i2 = (size_t)(b * N_ + i0 + ibase + r + 8) * D_ + h * DH_ + nt * 8 + c2;
        float2 x1 = *(const float2*)(x + i1);
        float2 x2 = *(const float2*)(x + i2);
        float2 o1 = make_float2(x1.x + elu1(acc[nt][0] * inv1),
                                x1.y + elu1(acc[nt][1] * inv1));
        float2 o2 = make_float2(x2.x + elu1(acc[nt][2] * inv2),
                                x2.y + elu1(acc[nt][3] * inv2));
        *(float2*)&g_y[i1] = o1;
        *(float2*)&g_y[i2] = o2;
    }
}

// ---------------- launch ----------------
extern "C" void kernel_launch(void* const* d_in, const int* in_sizes, int n_in,
                              void* d_out, int out_size) {
    const float* x     = (const float*)d_in[0];
    const int*   adj   = (const int*)  d_in[2];
    const float* W     = (const float*)d_in[3];
    const float* a_src = (const float*)d_in[4];
    const float* a_dst = (const float*)d_in[5];
    const float* ln1g  = (const float*)d_in[6];
    const float* ln1b  = (const float*)d_in[7];
    const float* ln2g  = (const float*)d_in[8];
    const float* ln2b  = (const float*)d_in[9];
    float* out = (float*)d_out;

    cudaFuncSetAttribute(gemm1t_kernel, cudaFuncAttributeMaxDynamicSharedMemorySize, GM_DSM);
    cudaFuncSetAttribute(attn_kernel,   cudaFuncAttributeMaxDynamicSharedMemorySize, AT_DSM);

    ln1_kernel   <<<B_*N_, 128>>>(x, ln1g, ln1b);
    pack_adj_kernel<<<(B_*N_*N_) / 256, 256>>>(adj);
    prep_w_kernel<<<H_*DH_, 128>>>(W);
    gemm1t_kernel<<<dim3(B_*N_/128, H_), 256, GM_DSM>>>(a_src, a_dst);
    gmax_kernel  <<<B_*H_, 256>>>();
    uv_kernel    <<<B_*H_*N_/256, 256>>>();
    htrans_kernel<<<dim3(N_/32, DH_/32, B_*H_), dim3(32, 8)>>>();
    attn_kernel  <<<dim3(N_/128, H_, B_), 256, AT_DSM>>>(x);
    ln2_kernel   <<<B_*N_, 128>>>(ln2g, ln2b, out);
}

// round 8
// speedup vs baseline: 3.2929x; 1.0294x over previous
#include <cuda_runtime.h>
#include <cstdint>

#define B_ 8
#define N_ 1024
#define D_ 512
#define H_ 8
#define DH_ 64
#define NW_ (N_/32)
#define L2E 1.4426950408889634f

// ---------------- scratch ----------------
__device__ unsigned short g_xnh[B_*N_*D_];
__device__ unsigned short g_xnl[B_*N_*D_];
__device__ unsigned short g_Wth[H_*DH_*D_];
__device__ unsigned short g_Wtl[H_*DH_*D_];
__device__ float    g_h [B_*N_*D_];
__device__ unsigned short g_hTh[B_*H_*DH_*N_];
__device__ unsigned short g_hTl[B_*H_*DH_*N_];
__device__ float    g_fs[B_*H_*N_];
__device__ float    g_fd[B_*H_*N_];
__device__ float    g_gmax[B_*H_];
__device__ unsigned g_adjb[B_*N_*NW_];
__device__ float    g_y [B_*N_*D_];
__device__ float    g_A[B_*H_*N_];
__device__ float    g_C[B_*H_*N_];
__device__ float    g_T[B_*H_*N_];
__device__ float    g_u[B_*H_*N_];
__device__ float    g_v[B_*H_*N_];

// ---------------- helpers ----------------
__device__ __forceinline__ float fexp2f(float t) {
    t = fmaxf(t, -125.0f);
    float r = t + 12582912.0f;
    int   n = __float_as_int(r) - 0x4B400000;
    float f = t - (r - 12582912.0f);
    float p = 1.3333558146e-3f;
    p = fmaf(p, f, 9.6181291298e-3f);
    p = fmaf(p, f, 5.5504108664e-2f);
    p = fmaf(p, f, 2.4022650696e-1f);
    p = fmaf(p, f, 6.9314718056e-1f);
    p = fmaf(p, f, 1.0f);
    return __int_as_float(__float_as_int(p) + (n << 23));
}
__device__ __forceinline__ float elu1(float v) {
    return v > 0.0f ? v : (fexp2f(v * L2E) - 1.0f);
}
__device__ __forceinline__ unsigned short bfsplit(float x, float &rem) {
    unsigned xi = __float_as_uint(x);
    unsigned hb = (xi + 0x8000u) & 0xffff0000u;
    rem = x - __uint_as_float(hb);
    return (unsigned short)(hb >> 16);
}
__device__ __forceinline__ unsigned short bfround(float x) {
    return (unsigned short)(((__float_as_uint(x) + 0x8000u) & 0xffff0000u) >> 16);
}
__device__ __forceinline__ unsigned smem_u32(const void* p) {
    unsigned a;
    asm("{ .reg .u64 t; cvta.to.shared.u64 t, %1; cvt.u32.u64 %0, t; }" : "=r"(a) : "l"(p));
    return a;
}
__device__ __forceinline__ void cpa16(unsigned s, const void* g) {
    asm volatile("cp.async.cg.shared.global [%0], [%1], 16;" :: "r"(s), "l"(g) : "memory");
}
#define CP_COMMIT() asm volatile("cp.async.commit_group;" ::: "memory")
#define CP_WAIT0()  asm volatile("cp.async.wait_group 0;" ::: "memory")
#define CP_WAIT1()  asm volatile("cp.async.wait_group 1;" ::: "memory")

__device__ __forceinline__ void mma16816(float* c, unsigned a0, unsigned a1,
                                         unsigned a2, unsigned a3,
                                         unsigned b0, unsigned b1) {
    asm volatile(
        "mma.sync.aligned.m16n8k16.row.col.f32.bf16.bf16.f32 "
        "{%0,%1,%2,%3}, {%4,%5,%6,%7}, {%8,%9}, {%0,%1,%2,%3};\n"
        : "+f"(c[0]), "+f"(c[1]), "+f"(c[2]), "+f"(c[3])
        : "r"(a0), "r"(a1), "r"(a2), "r"(a3), "r"(b0), "r"(b1));
}

// ---- k32 mma step (stride 40 shorts): A[128][32], B[64][32], hi/lo split ----
__device__ __forceinline__ void mma_chunk(float acc[8][4],
        const unsigned short* __restrict__ Ah, const unsigned short* __restrict__ Al,
        const unsigned short* __restrict__ Bh, const unsigned short* __restrict__ Bl,
        int ibase, int lane) {
    int r  = lane >> 2;
    int c2 = (lane & 3) * 2;
#pragma unroll
    for (int kk = 0; kk < 2; kk++) {
        const unsigned short* pA = Ah + (ibase + r) * 40 + kk * 16 + c2;
        const unsigned short* qA = Al + (ibase + r) * 40 + kk * 16 + c2;
        unsigned ah0 = *(const unsigned*)(pA);
        unsigned ah1 = *(const unsigned*)(pA + 8 * 40);
        unsigned ah2 = *(const unsigned*)(pA + 8);
        unsigned ah3 = *(const unsigned*)(pA + 8 * 40 + 8);
        unsigned al0 = *(const unsigned*)(qA);
        unsigned al1 = *(const unsigned*)(qA + 8 * 40);
        unsigned al2 = *(const unsigned*)(qA + 8);
        unsigned al3 = *(const unsigned*)(qA + 8 * 40 + 8);
#pragma unroll
        for (int g = 0; g < 2; g++) {
            unsigned bh[4][2], bl[4][2];
#pragma unroll
            for (int q = 0; q < 4; q++) {
                int nt = g * 4 + q;
                const unsigned short* pB = Bh + (nt * 8 + r) * 40 + kk * 16 + c2;
                const unsigned short* qB = Bl + (nt * 8 + r) * 40 + kk * 16 + c2;
                bh[q][0] = *(const unsigned*)(pB);
                bh[q][1] = *(const unsigned*)(pB + 8);
                bl[q][0] = *(const unsigned*)(qB);
                bl[q][1] = *(const unsigned*)(qB + 8);
            }
#pragma unroll
            for (int q = 0; q < 4; q++)
                mma16816(acc[g*4+q], ah0, ah1, ah2, ah3, bh[q][0], bh[q][1]);
#pragma unroll
            for (int q = 0; q < 4; q++)
                mma16816(acc[g*4+q], ah0, ah1, ah2, ah3, bl[q][0], bl[q][1]);
#pragma unroll
            for (int q = 0; q < 4; q++)
                mma16816(acc[g*4+q], al0, al1, al2, al3, bh[q][0], bh[q][1]);
        }
    }
}

// ---------------- LN1 ----------------
__global__ void ln1_kernel(const float* __restrict__ x, const float* __restrict__ gw,
                           const float* __restrict__ bw) {
    int row = blockIdx.x, t = threadIdx.x;
    const float4 v = ((const float4*)(x + (size_t)row * D_))[t];
    float s = v.x + v.y + v.z + v.w;
    float q = v.x*v.x + v.y*v.y + v.z*v.z + v.w*v.w;
#pragma unroll
    for (int o = 16; o; o >>= 1) {
        s += __shfl_xor_sync(0xffffffffu, s, o);
        q += __shfl_xor_sync(0xffffffffu, q, o);
    }
    __shared__ float ss[4], qs[4];
    if ((t & 31) == 0) { ss[t >> 5] = s; qs[t >> 5] = q; }
    __syncthreads();
    s = ss[0] + ss[1] + ss[2] + ss[3];
    q = qs[0] + qs[1] + qs[2] + qs[3];
    float mean = s * (1.0f / D_);
    float var  = fmaxf(q * (1.0f / D_) - mean * mean, 0.0f);
    float inv  = 1.0f / (sqrtf(var) + 1e-6f);
    const float4 g4 = ((const float4*)gw)[t];
    const float4 b4 = ((const float4*)bw)[t];
    float o0 = fmaf(g4.x * (v.x - mean), inv, b4.x);
    float o1 = fmaf(g4.y * (v.y - mean), inv, b4.y);
    float o2 = fmaf(g4.z * (v.z - mean), inv, b4.z);
    float o3 = fmaf(g4.w * (v.w - mean), inv, b4.w);
    float r0, r1, r2, r3;
    unsigned short h0 = bfsplit(o0, r0), h1 = bfsplit(o1, r1);
    unsigned short h2 = bfsplit(o2, r2), h3 = bfsplit(o3, r3);
    uint2 vh = make_uint2((unsigned)h0 | ((unsigned)h1 << 16),
                          (unsigned)h2 | ((unsigned)h3 << 16));
    uint2 vl = make_uint2((unsigned)bfround(r0) | ((unsigned)bfround(r1) << 16),
                          (unsigned)bfround(r2) | ((unsigned)bfround(r3) << 16));
    *(uint2*)&g_xnh[(size_t)row * D_ + t * 4] = vh;
    *(uint2*)&g_xnl[(size_t)row * D_ + t * 4] = vl;
}

// ---------------- LN2 ----------------
__global__ void ln2_kernel(const float* __restrict__ gw, const float* __restrict__ bw,
                           float* __restrict__ out) {
    int row = blockIdx.x, t = threadIdx.x;
    const float4 v = ((const float4*)(g_y + (size_t)row * D_))[t];
    float s = v.x + v.y + v.z + v.w;
    float q = v.x*v.x + v.y*v.y + v.z*v.z + v.w*v.w;
#pragma unroll
    for (int o = 16; o; o >>= 1) {
        s += __shfl_xor_sync(0xffffffffu, s, o);
        q += __shfl_xor_sync(0xffffffffu, q, o);
    }
    __shared__ float ss[4], qs[4];
    if ((t & 31) == 0) { ss[t >> 5] = s; qs[t >> 5] = q; }
    __syncthreads();
    s = ss[0] + ss[1] + ss[2] + ss[3];
    q = qs[0] + qs[1] + qs[2] + qs[3];
    float mean = s * (1.0f / D_);
    float var  = fmaxf(q * (1.0f / D_) - mean * mean, 0.0f);
    float inv  = 1.0f / (sqrtf(var) + 1e-6f);
    const float4 g4 = ((const float4*)gw)[t];
    const float4 b4 = ((const float4*)bw)[t];
    float4 o;
    o.x = fmaf(g4.x * (v.x - mean), inv, b4.x);
    o.y = fmaf(g4.y * (v.y - mean), inv, b4.y);
    o.z = fmaf(g4.z * (v.z - mean), inv, b4.z);
    o.w = fmaf(g4.w * (v.w - mean), inv, b4.w);
    ((float4*)(out + (size_t)row * D_))[t] = o;
}

// ---------------- pack adj ----------------
__global__ void pack_adj_kernel(const int* __restrict__ adj) {
    int gw   = (blockIdx.x * blockDim.x + threadIdx.x) >> 5;
    int lane = threadIdx.x & 31;
    int v = adj[(size_t)gw * 32 + lane];
    unsigned m = __ballot_sync(0xffffffffu, v > 0);
    if (lane == 0) g_adjb[gw] = m;
}

// ---------------- W^T bf16 split ----------------
__global__ void prep_w_kernel(const float* __restrict__ W) {
    int hd = blockIdx.x;
    int h = hd >> 6, d = hd & 63;
    for (int k = threadIdx.x; k < D_; k += 128) {
        float v = W[(size_t)h * D_ * DH_ + (size_t)k * DH_ + d];
        float rem;
        g_Wth[(size_t)hd * D_ + k] = bfsplit(v, rem);
        g_Wtl[(size_t)hd * D_ + k] = bfround(rem);
    }
}

// ---------------- GEMM1: k32, 2-stage ring (3 CTAs/SM), fused fs/fd ----------------
// stage (bytes): Ah@0 (10240), Al@10240, Bh@20480 (5120), Bl@25600; 30720 B
#define GM_DSM (2 * 30720)
__device__ __forceinline__ void g1_issue(unsigned sbase, int st, int c, int m0, int h, int t) {
    unsigned sb = sbase + (unsigned)st * 30720u;
    int k0 = c * 32;
#pragma unroll
    for (int i = t; i < 1536; i += 256) {
        const unsigned short* g;
        unsigned dst;
        if (i < 1024) {
            int tensor = i >> 9;
            int idx = i & 511;
            int row = idx >> 2, seg = idx & 3;
            g = (tensor ? g_xnl : g_xnh) + (size_t)(m0 + row) * D_ + k0 + seg * 8;
            dst = sb + tensor * 10240u + row * 80u + seg * 16u;
        } else {
            int idx = i - 1024;
            int tensor = idx >> 8;
            idx &= 255;
            int row = idx >> 2, seg = idx & 3;
            g = (tensor ? g_Wtl : g_Wth) + (size_t)(h * 64 + row) * D_ + k0 + seg * 8;
            dst = sb + 20480u + tensor * 5120u + row * 80u + seg * 16u;
        }
        cpa16(dst, g);
    }
}
__global__ __launch_bounds__(256, 3) void gemm1t_kernel(const float* __restrict__ a_src,
                                                        const float* __restrict__ a_dst) {
    extern __shared__ unsigned short dsm[];
    __shared__ float as_s[64], ad_s[64];
    unsigned sbase = smem_u32(dsm);
    int t = threadIdx.x, warp = t >> 5, lane = t & 31;
    int m0 = blockIdx.x * 128, h = blockIdx.y;
    int ibase = warp * 16;

    if (t < 64) as_s[t] = a_src[h * 64 + t];
    else if (t < 128) ad_s[t - 64] = a_dst[h * 64 + t - 64];

    float acc[8][4];
#pragma unroll
    for (int i = 0; i < 8; i++)
#pragma unroll
        for (int j = 0; j < 4; j++) acc[i][j] = 0.0f;

    g1_issue(sbase, 0, 0, m0, h, t); CP_COMMIT();

    for (int c = 0; c < 16; c++) {
        CP_WAIT0();
        __syncthreads();                    // chunk c visible; stage (c+1)%2 drained
        if (c + 1 < 16) { g1_issue(sbase, (c + 1) & 1, c + 1, m0, h, t); CP_COMMIT(); }
        unsigned short* stg = dsm + (c & 1) * 15360;
        mma_chunk(acc, stg, stg + 5120, stg + 10240, stg + 12800, ibase, lane);
    }

    int r = lane >> 2, q = lane & 3, c2 = q * 2;
    float fs1 = 0.f, fd1 = 0.f, fs2 = 0.f, fd2 = 0.f;
#pragma unroll
    for (int nt = 0; nt < 8; nt++) {
        float a0 = as_s[nt * 8 + c2], a1 = as_s[nt * 8 + c2 + 1];
        float d0 = ad_s[nt * 8 + c2], d1 = ad_s[nt * 8 + c2 + 1];
        fs1 = fmaf(acc[nt][0], a0, fmaf(acc[nt][1], a1, fs1));
        fd1 = fmaf(acc[nt][0], d0, fmaf(acc[nt][1], d1, fd1));
        fs2 = fmaf(acc[nt][2], a0, fmaf(acc[nt][3], a1, fs2));
        fd2 = fmaf(acc[nt][2], d0, fmaf(acc[nt][3], d1, fd2));
    }
#pragma unroll
    for (int o = 1; o <= 2; o <<= 1) {
        fs1 += __shfl_xor_sync(0xffffffffu, fs1, o);
        fd1 += __shfl_xor_sync(0xffffffffu, fd1, o);
        fs2 += __shfl_xor_sync(0xffffffffu, fs2, o);
        fd2 += __shfl_xor_sync(0xffffffffu, fd2, o);
    }
    if (q == 0) {
        int m1 = m0 + ibase + r, m2 = m1 + 8;
        int b1 = m1 >> 10, n1 = m1 & 1023;
        int b2 = m2 >> 10, n2 = m2 & 1023;
        g_fs[(b1 * H_ + h) * N_ + n1] = fs1 * L2E;
        g_fd[(b1 * H_ + h) * N_ + n1] = fd1 * L2E;
        g_fs[(b2 * H_ + h) * N_ + n2] = fs2 * L2E;
        g_fd[(b2 * H_ + h) * N_ + n2] = fd2 * L2E;
    }
#pragma unroll
    for (int nt = 0; nt < 8; nt++) {
        size_t i1 = (size_t)(m0 + ibase + r) * D_ + h * DH_ + nt * 8 + c2;
        size_t i2 = (size_t)(m0 + ibase + r + 8) * D_ + h * DH_ + nt * 8 + c2;
        *(float2*)&g_h[i1] = make_float2(acc[nt][0], acc[nt][1]);
        *(float2*)&g_h[i2] = make_float2(acc[nt][2], acc[nt][3]);
    }
}

// ---------------- gmax / uv ----------------
__global__ void gmax_kernel() {
    int bh = blockIdx.x, t = threadIdx.x;
    float m = -1e30f;
    for (int i = t; i < N_; i += 256) m = fmaxf(m, g_fd[bh * N_ + i]);
#pragma unroll
    for (int o = 16; o; o >>= 1) m = fmaxf(m, __shfl_xor_sync(0xffffffffu, m, o));
    __shared__ float sm[8];
    if ((t & 31) == 0) sm[t >> 5] = m;
    __syncthreads();
    if (t == 0) {
        float mm = sm[0];
#pragma unroll
        for (int i = 1; i < 8; i++) mm = fmaxf(mm, sm[i]);
        g_gmax[bh] = mm;
    }
}
__global__ void uv_kernel() {
    int idx = blockIdx.x * 256 + threadIdx.x;
    int bh = idx >> 10;
    float gm = g_gmax[bh];
    float fs = g_fs[idx], fd = g_fd[idx];
    float bound = fs + gm;
    float m = fmaxf(bound, 0.2f * bound);
    g_A[idx] = fexp2f(bound - m);
    g_C[idx] = fexp2f(0.2f * bound - m);
    g_T[idx] = fexp2f(-bound);
    g_u[idx] = fexp2f(fd - gm);
    g_v[idx] = fexp2f(0.2f * (fd - gm));
}

// ---------------- h -> h^T bf16 split ----------------
__global__ void htrans_kernel() {
    __shared__ float s[32][33];
    int bh = blockIdx.z, j0 = blockIdx.x * 32, d0 = blockIdx.y * 32;
    int b = bh >> 3, h = bh & 7;
    int tx = threadIdx.x, ty = threadIdx.y;
#pragma unroll
    for (int k = 0; k < 4; k++) {
        int jj = ty + k * 8;
        s[jj][tx] = g_h[(size_t)(b * N_ + j0 + jj) * D_ + h * DH_ + d0 + tx];
    }
    __syncthreads();
#pragma unroll
    for (int k = 0; k < 4; k++) {
        int dd = ty + k * 8;
        float v = s[tx][dd];
        float rem;
        size_t idx = (size_t)bh * DH_ * N_ + (size_t)(d0 + dd) * N_ + j0 + tx;
        g_hTh[idx] = bfsplit(v, rem);
        g_hTl[idx] = bfround(rem);
    }
}

// ---------------- attention: 2-stage h ring + double-buffered P, ONE sync/chunk ----
// dsm (shorts): h0@0 (5120: Bh 2560 | Bl 2560), h1@5120,
//               P0@10240 (Ph 5120 | Pl 5120), P1@20480, uv floats @30720 (4096 sh)
#define AT_DSM ((30720 + 4096) * 2)
__device__ __forceinline__ void at_issue(unsigned sbase, int st, int c, int bh, int t) {
    unsigned sb = sbase + (unsigned)st * 10240u;
    int j0 = c * 32;
#pragma unroll
    for (int i = t; i < 512; i += 256) {
        int tensor = i >> 8;
        int idx = i & 255;
        int row = idx >> 2, seg = idx & 3;
        const unsigned short* g = (tensor ? g_hTl : g_hTh) +
                                  (size_t)bh * DH_ * N_ + (size_t)row * N_ + j0 + seg * 8;
        cpa16(sb + tensor * 5120u + row * 80u + seg * 16u, g);
    }
}
__global__ __launch_bounds__(256, 3) void attn_kernel(const float* __restrict__ x) {
    extern __shared__ unsigned short dsm[];
    __shared__ float As_[128], Cs_[128], Ts_[128], dens[128];
    unsigned sbase = smem_u32(dsm);
    int t = threadIdx.x, warp = t >> 5, lane = t & 31;
    int b = blockIdx.z, h = blockIdx.y, i0 = blockIdx.x * 128;
    int bh = b * H_ + h;
    int ibase = warp * 16;
    int il = t >> 1, s = t & 1, jb = s * 16;

    const float* uvf = (const float*)(dsm + 30720);

    // uv preload (8KB), then h chunk 0
#pragma unroll
    for (int i = t; i < 512; i += 256) {
        const float* g = (i < 256) ? (g_u + bh * N_ + i * 4)
                                   : (g_v + bh * N_ + (i - 256) * 4);
        cpa16(sbase + 61440u + (unsigned)i * 16u, g);
    }
    CP_COMMIT();
    at_issue(sbase, 0, 0, bh, t); CP_COMMIT();

    if (t < 128) {
        int gi = bh * N_ + i0 + t;
        As_[t] = g_A[gi]; Cs_[t] = g_C[gi]; Ts_[t] = g_T[gi];
    }
    unsigned adjn = g_adjb[(size_t)(b * N_ + i0 + il) * NW_ + 0];

    float acc[8][4];
#pragma unroll
    for (int i = 0; i < 8; i++)
#pragma unroll
        for (int j = 0; j < 4; j++) acc[i][j] = 0.0f;
    float den = 0.0f;

    CP_WAIT1();               // uv complete (h0 may still be in flight)
    __syncthreads();          // uv + As/Cs/Ts visible
    float fA = As_[il], fC = Cs_[il], fT = Ts_[il];

    auto buildP = [&](int c, unsigned w) {
        unsigned short* Ph = dsm + 10240 + (c & 1) * 10240;
        unsigned short* Pl = Ph + 5120;
        const float* us = uvf + c * 32 + jb;
        const float* vs = uvf + 1024 + c * 32 + jb;
#pragma unroll
        for (int qq = 0; qq < 16; qq += 4) {
            float4 u4 = *(const float4*)(us + qq);
            float4 v4 = *(const float4*)(vs + qq);
            float uu[4] = {u4.x, u4.y, u4.z, u4.w};
            float vv[4] = {v4.x, v4.y, v4.z, v4.w};
            unsigned pb_[4], lb_[4];
#pragma unroll
            for (int e = 0; e < 4; e++) {
                bool cs = uu[e] > fT;
                float p = (cs ? fA : fC) * (cs ? uu[e] : vv[e]);
                p = ((w >> (jb + qq + e)) & 1u) ? p : 0.0f;
                den += p;
                unsigned pi = __float_as_uint(p);
                unsigned hb = pi & 0xffff0000u;
                lb_[e] = __float_as_uint(p - __uint_as_float(hb));
                pb_[e] = hb;
            }
            *(uint2*)&Ph[il * 40 + jb + qq] =
                make_uint2(__byte_perm(pb_[0], pb_[1], 0x7632),
                           __byte_perm(pb_[2], pb_[3], 0x7632));
            *(uint2*)&Pl[il * 40 + jb + qq] =
                make_uint2(__byte_perm(lb_[0], lb_[1], 0x7632),
                           __byte_perm(lb_[2], lb_[3], 0x7632));
        }
    };
    buildP(0, adjn);
    adjn = g_adjb[(size_t)(b * N_ + i0 + il) * NW_ + 1];

    for (int c = 0; c < 32; c++) {
        CP_WAIT0();
        __syncthreads();                 // h(c) ready; P(c) built by all threads
        if (c + 1 < 32) { at_issue(sbase, (c + 1) & 1, c + 1, bh, t); CP_COMMIT(); }
        unsigned short* hs = dsm + (c & 1) * 5120;
        unsigned short* Ph = dsm + 10240 + (c & 1) * 10240;
        mma_chunk(acc, Ph, Ph + 5120, hs, hs + 2560, ibase, lane);
        if (c + 1 < 32) {
            buildP(c + 1, adjn);         // writes other P buffer, no barrier needed
            if (c + 2 < 32) adjn = g_adjb[(size_t)(b * N_ + i0 + il) * NW_ + c + 2];
        }
    }

    den += __shfl_xor_sync(0xffffffffu, den, 1);
    dens[il] = den;
    __syncthreads();

    int r = lane >> 2, c2 = (lane & 3) * 2;
    float inv1 = 1.0f / dens[ibase + r];
    float inv2 = 1.0f / dens[ibase + r + 8];
#pragma unroll
    for (int nt = 0; nt < 8; nt++) {
        size_t i1 = (size_t)(b * N_ + i0 + ibase + r) * D_ + h * DH_ + nt * 8 + c2;
        size_t i2 = (size_t)(b * N_ + i0 + ibase + r + 8) * D_ + h * DH_ + nt * 8 + c2;
        float2 x1 = *(const float2*)(x + i1);
        float2 x2 = *(const float2*)(x + i2);
        float2 o1 = make_float2(x1.x + elu1(acc[nt][0] * inv1),
                                x1.y + elu1(acc[nt][1] * inv1));
        float2 o2 = make_float2(x2.x + elu1(acc[nt][2] * inv2),
                                x2.y + elu1(acc[nt][3] * inv2));
        *(float2*)&g_y[i1] = o1;
        *(float2*)&g_y[i2] = o2;
    }
}

// ---------------- launch ----------------
extern "C" void kernel_launch(void* const* d_in, const int* in_sizes, int n_in,
                              void* d_out, int out_size) {
    const float* x     = (const float*)d_in[0];
    const int*   adj   = (const int*)  d_in[2];
    const float* W     = (const float*)d_in[3];
    const float* a_src = (const float*)d_in[4];
    const float* a_dst = (const float*)d_in[5];
    const float* ln1g  = (const float*)d_in[6];
    const float* ln1b  = (const float*)d_in[7];
    const float* ln2g  = (const float*)d_in[8];
    const float* ln2b  = (const float*)d_in[9];
    float* out = (float*)d_out;

    cudaFuncSetAttribute(gemm1t_kernel, cudaFuncAttributeMaxDynamicSharedMemorySize, GM_DSM);
    cudaFuncSetAttribute(attn_kernel,   cudaFuncAttributeMaxDynamicSharedMemorySize, AT_DSM);

    ln1_kernel   <<<B_*N_, 128>>>(x, ln1g, ln1b);
    pack_adj_kernel<<<(B_*N_*N_) / 256, 256>>>(adj);
    prep_w_kernel<<<H_*DH_, 128>>>(W);
    gemm1t_kernel<<<dim3(B_*N_/128, H_), 256, GM_DSM>>>(a_src, a_dst);
    gmax_kernel  <<<B_*H_, 256>>>();
    uv_kernel    <<<B_*H_*N_/256, 256>>>();
    htrans_kernel<<<dim3(N_/32, DH_/32, B_*H_), dim3(32, 8)>>>();
    attn_kernel  <<<dim3(N_/128, H_, B_), 256, AT_DSM>>>(x);
    ln2_kernel   <<<B_*N_, 128>>>(ln2g, ln2b, out);
}

// round 9
// speedup vs baseline: 3.6873x; 1.1198x over previous
#include <cuda_runtime.h>
#include <cuda_fp16.h>
#include <cstdint>

#define B_ 8
#define N_ 1024
#define D_ 512
#define H_ 8
#define DH_ 64
#define NW_ (N_/32)
#define L2E 1.4426950408889634f

// ---------------- scratch ----------------
__device__ unsigned short g_xnh[B_*N_*D_];
__device__ unsigned short g_xnl[B_*N_*D_];
__device__ unsigned short g_Wth[H_*DH_*D_];
__device__ unsigned short g_Wtl[H_*DH_*D_];
__device__ float    g_h [B_*N_*D_];
__device__ unsigned short g_hTh[B_*H_*DH_*N_];   // fp16 hi
__device__ unsigned short g_hTl[B_*H_*DH_*N_];   // fp16 lo
__device__ float    g_fs[B_*H_*N_];
__device__ float    g_fd[B_*H_*N_];
__device__ float    g_gmax[B_*H_];
__device__ unsigned g_adjb[B_*N_*NW_];
__device__ float    g_y [B_*N_*D_];
__device__ float    g_A[B_*H_*N_];
__device__ float    g_C[B_*H_*N_];
__device__ float    g_T[B_*H_*N_];
__device__ float    g_u[B_*H_*N_];
__device__ float    g_v[B_*H_*N_];

// ---------------- helpers ----------------
__device__ __forceinline__ float fexp2f(float t) {
    t = fmaxf(t, -125.0f);
    float r = t + 12582912.0f;
    int   n = __float_as_int(r) - 0x4B400000;
    float f = t - (r - 12582912.0f);
    float p = 1.3333558146e-3f;
    p = fmaf(p, f, 9.6181291298e-3f);
    p = fmaf(p, f, 5.5504108664e-2f);
    p = fmaf(p, f, 2.4022650696e-1f);
    p = fmaf(p, f, 6.9314718056e-1f);
    p = fmaf(p, f, 1.0f);
    return __int_as_float(__float_as_int(p) + (n << 23));
}
__device__ __forceinline__ float elu1(float v) {
    return v > 0.0f ? v : (fexp2f(v * L2E) - 1.0f);
}
__device__ __forceinline__ unsigned short bfsplit(float x, float &rem) {
    unsigned xi = __float_as_uint(x);
    unsigned hb = (xi + 0x8000u) & 0xffff0000u;
    rem = x - __uint_as_float(hb);
    return (unsigned short)(hb >> 16);
}
__device__ __forceinline__ unsigned short bfround(float x) {
    return (unsigned short)(((__float_as_uint(x) + 0x8000u) & 0xffff0000u) >> 16);
}
__device__ __forceinline__ unsigned smem_u32(const void* p) {
    unsigned a;
    asm("{ .reg .u64 t; cvta.to.shared.u64 t, %1; cvt.u32.u64 %0, t; }" : "=r"(a) : "l"(p));
    return a;
}
__device__ __forceinline__ void cpa16(unsigned s, const void* g) {
    asm volatile("cp.async.cg.shared.global [%0], [%1], 16;" :: "r"(s), "l"(g) : "memory");
}
#define CP_COMMIT() asm volatile("cp.async.commit_group;" ::: "memory")
#define CP_WAIT0()  asm volatile("cp.async.wait_group 0;" ::: "memory")
#define CP_WAIT1()  asm volatile("cp.async.wait_group 1;" ::: "memory")

__device__ __forceinline__ void mma16816(float* c, unsigned a0, unsigned a1,
                                         unsigned a2, unsigned a3,
                                         unsigned b0, unsigned b1) {
    asm volatile(
        "mma.sync.aligned.m16n8k16.row.col.f32.bf16.bf16.f32 "
        "{%0,%1,%2,%3}, {%4,%5,%6,%7}, {%8,%9}, {%0,%1,%2,%3};\n"
        : "+f"(c[0]), "+f"(c[1]), "+f"(c[2]), "+f"(c[3])
        : "r"(a0), "r"(a1), "r"(a2), "r"(a3), "r"(b0), "r"(b1));
}
__device__ __forceinline__ void mma16816h(float* c, unsigned a0, unsigned a1,
                                          unsigned a2, unsigned a3,
                                          unsigned b0, unsigned b1) {
    asm volatile(
        "mma.sync.aligned.m16n8k16.row.col.f32.f16.f16.f32 "
        "{%0,%1,%2,%3}, {%4,%5,%6,%7}, {%8,%9}, {%0,%1,%2,%3};\n"
        : "+f"(c[0]), "+f"(c[1]), "+f"(c[2]), "+f"(c[3])
        : "r"(a0), "r"(a1), "r"(a2), "r"(a3), "r"(b0), "r"(b1));
}

// ---- bf16 3-term k32 step (gemm1): A[128][32], B[64][32], stride 40 ----
__device__ __forceinline__ void mma_chunk(float acc[8][4],
        const unsigned short* __restrict__ Ah, const unsigned short* __restrict__ Al,
        const unsigned short* __restrict__ Bh, const unsigned short* __restrict__ Bl,
        int ibase, int lane) {
    int r  = lane >> 2;
    int c2 = (lane & 3) * 2;
#pragma unroll
    for (int kk = 0; kk < 2; kk++) {
        const unsigned short* pA = Ah + (ibase + r) * 40 + kk * 16 + c2;
        const unsigned short* qA = Al + (ibase + r) * 40 + kk * 16 + c2;
        unsigned ah0 = *(const unsigned*)(pA);
        unsigned ah1 = *(const unsigned*)(pA + 8 * 40);
        unsigned ah2 = *(const unsigned*)(pA + 8);
        unsigned ah3 = *(const unsigned*)(pA + 8 * 40 + 8);
        unsigned al0 = *(const unsigned*)(qA);
        unsigned al1 = *(const unsigned*)(qA + 8 * 40);
        unsigned al2 = *(const unsigned*)(qA + 8);
        unsigned al3 = *(const unsigned*)(qA + 8 * 40 + 8);
#pragma unroll
        for (int g = 0; g < 2; g++) {
            unsigned bh[4][2], bl[4][2];
#pragma unroll
            for (int q = 0; q < 4; q++) {
                int nt = g * 4 + q;
                const unsigned short* pB = Bh + (nt * 8 + r) * 40 + kk * 16 + c2;
                const unsigned short* qB = Bl + (nt * 8 + r) * 40 + kk * 16 + c2;
                bh[q][0] = *(const unsigned*)(pB);
                bh[q][1] = *(const unsigned*)(pB + 8);
                bl[q][0] = *(const unsigned*)(qB);
                bl[q][1] = *(const unsigned*)(qB + 8);
            }
#pragma unroll
            for (int q = 0; q < 4; q++)
                mma16816(acc[g*4+q], ah0, ah1, ah2, ah3, bh[q][0], bh[q][1]);
#pragma unroll
            for (int q = 0; q < 4; q++)
                mma16816(acc[g*4+q], ah0, ah1, ah2, ah3, bl[q][0], bl[q][1]);
#pragma unroll
            for (int q = 0; q < 4; q++)
                mma16816(acc[g*4+q], al0, al1, al2, al3, bh[q][0], bh[q][1]);
        }
    }
}

// ---- fp16 2-term k32 step (attn): A=P single fp16, B=h hi/lo fp16 ----
__device__ __forceinline__ void mma_chunk_h(float acc[8][4],
        const unsigned short* __restrict__ A,
        const unsigned short* __restrict__ Bh, const unsigned short* __restrict__ Bl,
        int ibase, int lane) {
    int r  = lane >> 2;
    int c2 = (lane & 3) * 2;
#pragma unroll
    for (int kk = 0; kk < 2; kk++) {
        const unsigned short* pA = A + (ibase + r) * 40 + kk * 16 + c2;
        unsigned a0 = *(const unsigned*)(pA);
        unsigned a1 = *(const unsigned*)(pA + 8 * 40);
        unsigned a2 = *(const unsigned*)(pA + 8);
        unsigned a3 = *(const unsigned*)(pA + 8 * 40 + 8);
#pragma unroll
        for (int g = 0; g < 2; g++) {
            unsigned bh[4][2], bl[4][2];
#pragma unroll
            for (int q = 0; q < 4; q++) {
                int nt = g * 4 + q;
                const unsigned short* pB = Bh + (nt * 8 + r) * 40 + kk * 16 + c2;
                const unsigned short* qB = Bl + (nt * 8 + r) * 40 + kk * 16 + c2;
                bh[q][0] = *(const unsigned*)(pB);
                bh[q][1] = *(const unsigned*)(pB + 8);
                bl[q][0] = *(const unsigned*)(qB);
                bl[q][1] = *(const unsigned*)(qB + 8);
            }
#pragma unroll
            for (int q = 0; q < 4; q++)
                mma16816h(acc[g*4+q], a0, a1, a2, a3, bh[q][0], bh[q][1]);
#pragma unroll
            for (int q = 0; q < 4; q++)
                mma16816h(acc[g*4+q], a0, a1, a2, a3, bl[q][0], bl[q][1]);
        }
    }
}

// ---------------- LN1 ----------------
__global__ void ln1_kernel(const float* __restrict__ x, const float* __restrict__ gw,
                           const float* __restrict__ bw) {
    int row = blockIdx.x, t = threadIdx.x;
    const float4 v = ((const float4*)(x + (size_t)row * D_))[t];
    float s = v.x + v.y + v.z + v.w;
    float q = v.x*v.x + v.y*v.y + v.z*v.z + v.w*v.w;
#pragma unroll
    for (int o = 16; o; o >>= 1) {
        s += __shfl_xor_sync(0xffffffffu, s, o);
        q += __shfl_xor_sync(0xffffffffu, q, o);
    }
    __shared__ float ss[4], qs[4];
    if ((t & 31) == 0) { ss[t >> 5] = s; qs[t >> 5] = q; }
    __syncthreads();
    s = ss[0] + ss[1] + ss[2] + ss[3];
    q = qs[0] + qs[1] + qs[2] + qs[3];
    float mean = s * (1.0f / D_);
    float var  = fmaxf(q * (1.0f / D_) - mean * mean, 0.0f);
    float inv  = 1.0f / (sqrtf(var) + 1e-6f);
    const float4 g4 = ((const float4*)gw)[t];
    const float4 b4 = ((const float4*)bw)[t];
    float o0 = fmaf(g4.x * (v.x - mean), inv, b4.x);
    float o1 = fmaf(g4.y * (v.y - mean), inv, b4.y);
    float o2 = fmaf(g4.z * (v.z - mean), inv, b4.z);
    float o3 = fmaf(g4.w * (v.w - mean), inv, b4.w);
    float r0, r1, r2, r3;
    unsigned short h0 = bfsplit(o0, r0), h1 = bfsplit(o1, r1);
    unsigned short h2 = bfsplit(o2, r2), h3 = bfsplit(o3, r3);
    uint2 vh = make_uint2((unsigned)h0 | ((unsigned)h1 << 16),
                          (unsigned)h2 | ((unsigned)h3 << 16));
    uint2 vl = make_uint2((unsigned)bfround(r0) | ((unsigned)bfround(r1) << 16),
                          (unsigned)bfround(r2) | ((unsigned)bfround(r3) << 16));
    *(uint2*)&g_xnh[(size_t)row * D_ + t * 4] = vh;
    *(uint2*)&g_xnl[(size_t)row * D_ + t * 4] = vl;
}

// ---------------- LN2 ----------------
__global__ void ln2_kernel(const float* __restrict__ gw, const float* __restrict__ bw,
                           float* __restrict__ out) {
    int row = blockIdx.x, t = threadIdx.x;
    const float4 v = ((const float4*)(g_y + (size_t)row * D_))[t];
    float s = v.x + v.y + v.z + v.w;
    float q = v.x*v.x + v.y*v.y + v.z*v.z + v.w*v.w;
#pragma unroll
    for (int o = 16; o; o >>= 1) {
        s += __shfl_xor_sync(0xffffffffu, s, o);
        q += __shfl_xor_sync(0xffffffffu, q, o);
    }
    __shared__ float ss[4], qs[4];
    if ((t & 31) == 0) { ss[t >> 5] = s; qs[t >> 5] = q; }
    __syncthreads();
    s = ss[0] + ss[1] + ss[2] + ss[3];
    q = qs[0] + qs[1] + qs[2] + qs[3];
    float mean = s * (1.0f / D_);
    float var  = fmaxf(q * (1.0f / D_) - mean * mean, 0.0f);
    float inv  = 1.0f / (sqrtf(var) + 1e-6f);
    const float4 g4 = ((const float4*)gw)[t];
    const float4 b4 = ((const float4*)bw)[t];
    float4 o;
    o.x = fmaf(g4.x * (v.x - mean), inv, b4.x);
    o.y = fmaf(g4.y * (v.y - mean), inv, b4.y);
    o.z = fmaf(g4.z * (v.z - mean), inv, b4.z);
    o.w = fmaf(g4.w * (v.w - mean), inv, b4.w);
    ((float4*)(out + (size_t)row * D_))[t] = o;
}

// ---------------- pack adj ----------------
__global__ void pack_adj_kernel(const int* __restrict__ adj) {
    int gw   = (blockIdx.x * blockDim.x + threadIdx.x) >> 5;
    int lane = threadIdx.x & 31;
    int v = adj[(size_t)gw * 32 + lane];
    unsigned m = __ballot_sync(0xffffffffu, v > 0);
    if (lane == 0) g_adjb[gw] = m;
}

// ---------------- W^T bf16 split ----------------
__global__ void prep_w_kernel(const float* __restrict__ W) {
    int hd = blockIdx.x;
    int h = hd >> 6, d = hd & 63;
    for (int k = threadIdx.x; k < D_; k += 128) {
        float v = W[(size_t)h * D_ * DH_ + (size_t)k * DH_ + d];
        float rem;
        g_Wth[(size_t)hd * D_ + k] = bfsplit(v, rem);
        g_Wtl[(size_t)hd * D_ + k] = bfround(rem);
    }
}

// ---------------- GEMM1: k32, 2-stage ring, fused fs/fd (unchanged from R8) ----
#define GM_DSM (2 * 30720)
__device__ __forceinline__ void g1_issue(unsigned sbase, int st, int c, int m0, int h, int t) {
    unsigned sb = sbase + (unsigned)st * 30720u;
    int k0 = c * 32;
#pragma unroll
    for (int i = t; i < 1536; i += 256) {
        const unsigned short* g;
        unsigned dst;
        if (i < 1024) {
            int tensor = i >> 9;
            int idx = i & 511;
            int row = idx >> 2, seg = idx & 3;
            g = (tensor ? g_xnl : g_xnh) + (size_t)(m0 + row) * D_ + k0 + seg * 8;
            dst = sb + tensor * 10240u + row * 80u + seg * 16u;
        } else {
            int idx = i - 1024;
            int tensor = idx >> 8;
            idx &= 255;
            int row = idx >> 2, seg = idx & 3;
            g = (tensor ? g_Wtl : g_Wth) + (size_t)(h * 64 + row) * D_ + k0 + seg * 8;
            dst = sb + 20480u + tensor * 5120u + row * 80u + seg * 16u;
        }
        cpa16(dst, g);
    }
}
__global__ __launch_bounds__(256, 3) void gemm1t_kernel(const float* __restrict__ a_src,
                                                        const float* __restrict__ a_dst) {
    extern __shared__ unsigned short dsm[];
    __shared__ float as_s[64], ad_s[64];
    unsigned sbase = smem_u32(dsm);
    int t = threadIdx.x, warp = t >> 5, lane = t & 31;
    int m0 = blockIdx.x * 128, h = blockIdx.y;
    int ibase = warp * 16;

    if (t < 64) as_s[t] = a_src[h * 64 + t];
    else if (t < 128) ad_s[t - 64] = a_dst[h * 64 + t - 64];

    float acc[8][4];
#pragma unroll
    for (int i = 0; i < 8; i++)
#pragma unroll
        for (int j = 0; j < 4; j++) acc[i][j] = 0.0f;

    g1_issue(sbase, 0, 0, m0, h, t); CP_COMMIT();

    for (int c = 0; c < 16; c++) {
        CP_WAIT0();
        __syncthreads();
        if (c + 1 < 16) { g1_issue(sbase, (c + 1) & 1, c + 1, m0, h, t); CP_COMMIT(); }
        unsigned short* stg = dsm + (c & 1) * 15360;
        mma_chunk(acc, stg, stg + 5120, stg + 10240, stg + 12800, ibase, lane);
    }

    int r = lane >> 2, q = lane & 3, c2 = q * 2;
    float fs1 = 0.f, fd1 = 0.f, fs2 = 0.f, fd2 = 0.f;
#pragma unroll
    for (int nt = 0; nt < 8; nt++) {
        float a0 = as_s[nt * 8 + c2], a1 = as_s[nt * 8 + c2 + 1];
        float d0 = ad_s[nt * 8 + c2], d1 = ad_s[nt * 8 + c2 + 1];
        fs1 = fmaf(acc[nt][0], a0, fmaf(acc[nt][1], a1, fs1));
        fd1 = fmaf(acc[nt][0], d0, fmaf(acc[nt][1], d1, fd1));
        fs2 = fmaf(acc[nt][2], a0, fmaf(acc[nt][3], a1, fs2));
        fd2 = fmaf(acc[nt][2], d0, fmaf(acc[nt][3], d1, fd2));
    }
#pragma unroll
    for (int o = 1; o <= 2; o <<= 1) {
        fs1 += __shfl_xor_sync(0xffffffffu, fs1, o);
        fd1 += __shfl_xor_sync(0xffffffffu, fd1, o);
        fs2 += __shfl_xor_sync(0xffffffffu, fs2, o);
        fd2 += __shfl_xor_sync(0xffffffffu, fd2, o);
    }
    if (q == 0) {
        int m1 = m0 + ibase + r, m2 = m1 + 8;
        int b1 = m1 >> 10, n1 = m1 & 1023;
        int b2 = m2 >> 10, n2 = m2 & 1023;
        g_fs[(b1 * H_ + h) * N_ + n1] = fs1 * L2E;
        g_fd[(b1 * H_ + h) * N_ + n1] = fd1 * L2E;
        g_fs[(b2 * H_ + h) * N_ + n2] = fs2 * L2E;
        g_fd[(b2 * H_ + h) * N_ + n2] = fd2 * L2E;
    }
#pragma unroll
    for (int nt = 0; nt < 8; nt++) {
        size_t i1 = (size_t)(m0 + ibase + r) * D_ + h * DH_ + nt * 8 + c2;
        size_t i2 = (size_t)(m0 + ibase + r + 8) * D_ + h * DH_ + nt * 8 + c2;
        *(float2*)&g_h[i1] = make_float2(acc[nt][0], acc[nt][1]);
        *(float2*)&g_h[i2] = make_float2(acc[nt][2], acc[nt][3]);
    }
}

// ---------------- merged gmax + uv ----------------
__global__ void gmaxuv_kernel() {
    __shared__ float sm[8];
    __shared__ float gmv;
    int bh = blockIdx.x, t = threadIdx.x;
    float fdv[4];
    float m = -1e30f;
#pragma unroll
    for (int k = 0; k < 4; k++) {
        fdv[k] = g_fd[bh * N_ + t + k * 256];
        m = fmaxf(m, fdv[k]);
    }
#pragma unroll
    for (int o = 16; o; o >>= 1) m = fmaxf(m, __shfl_xor_sync(0xffffffffu, m, o));
    if ((t & 31) == 0) sm[t >> 5] = m;
    __syncthreads();
    if (t == 0) {
        float mm = sm[0];
#pragma unroll
        for (int i = 1; i < 8; i++) mm = fmaxf(mm, sm[i]);
        gmv = mm;
    }
    __syncthreads();
    float gm = gmv;
#pragma unroll
    for (int k = 0; k < 4; k++) {
        int idx = bh * N_ + t + k * 256;
        float fs = g_fs[idx];
        float bound = fs + gm;
        float mx = fmaxf(bound, 0.2f * bound);
        g_A[idx] = fexp2f(bound - mx);
        g_C[idx] = fexp2f(0.2f * bound - mx);
        g_T[idx] = fexp2f(-bound);
        g_u[idx] = fexp2f(fdv[k] - gm);
        g_v[idx] = fexp2f(0.2f * (fdv[k] - gm));
    }
}

// ---------------- h -> h^T fp16 split ----------------
__global__ void htrans_kernel() {
    __shared__ float s[32][33];
    int bh = blockIdx.z, j0 = blockIdx.x * 32, d0 = blockIdx.y * 32;
    int b = bh >> 3, h = bh & 7;
    int tx = threadIdx.x, ty = threadIdx.y;
#pragma unroll
    for (int k = 0; k < 4; k++) {
        int jj = ty + k * 8;
        s[jj][tx] = g_h[(size_t)(b * N_ + j0 + jj) * D_ + h * DH_ + d0 + tx];
    }
    __syncthreads();
#pragma unroll
    for (int k = 0; k < 4; k++) {
        int dd = ty + k * 8;
        float v = s[tx][dd];
        __half hh = __float2half_rn(v);
        __half hl = __float2half_rn(v - __half2float(hh));
        size_t idx = (size_t)bh * DH_ * N_ + (size_t)(d0 + dd) * N_ + j0 + tx;
        g_hTh[idx] = __half_as_ushort(hh);
        g_hTl[idx] = __half_as_ushort(hl);
    }
}

// ---------------- attention: fp16 P(single) x h(hi/lo), 2-stage h + 2-stage P ----
// dsm (shorts): h0@0 (5120: Bh 2560 | Bl 2560), h1@5120,
//               P0@10240 (5120), P1@15360 (5120), uv floats @20480 (4096 sh)
#define AT_DSM ((20480 + 4096) * 2)
__device__ __forceinline__ void at_issue(unsigned sbase, int st, int c, int bh, int t) {
    unsigned sb = sbase + (unsigned)st * 10240u;
    int j0 = c * 32;
#pragma unroll
    for (int i = t; i < 512; i += 256) {
        int tensor = i >> 8;
        int idx = i & 255;
        int row = idx >> 2, seg = idx & 3;
        const unsigned short* g = (tensor ? g_hTl : g_hTh) +
                                  (size_t)bh * DH_ * N_ + (size_t)row * N_ + j0 + seg * 8;
        cpa16(sb + tensor * 5120u + row * 80u + seg * 16u, g);
    }
}
__global__ __launch_bounds__(256, 3) void attn_kernel(const float* __restrict__ x) {
    extern __shared__ unsigned short dsm[];
    __shared__ float As_[128], Cs_[128], Ts_[128], dens[128];
    unsigned sbase = smem_u32(dsm);
    int t = threadIdx.x, warp = t >> 5, lane = t & 31;
    int b = blockIdx.z, h = blockIdx.y, i0 = blockIdx.x * 128;
    int bh = b * H_ + h;
    int ibase = warp * 16;
    int il = t >> 1, s = t & 1, jb = s * 16;

    const float* uvf = (const float*)(dsm + 20480);

    // uv preload (8KB), then h chunk 0
#pragma unroll
    for (int i = t; i < 512; i += 256) {
        const float* g = (i < 256) ? (g_u + bh * N_ + i * 4)
                                   : (g_v + bh * N_ + (i - 256) * 4);
        cpa16(sbase + 40960u + (unsigned)i * 16u, g);
    }
    CP_COMMIT();
    at_issue(sbase, 0, 0, bh, t); CP_COMMIT();

    if (t < 128) {
        int gi = bh * N_ + i0 + t;
        As_[t] = g_A[gi]; Cs_[t] = g_C[gi]; Ts_[t] = g_T[gi];
    }
    unsigned adjn = g_adjb[(size_t)(b * N_ + i0 + il) * NW_ + 0];

    float acc[8][4];
#pragma unroll
    for (int i = 0; i < 8; i++)
#pragma unroll
        for (int j = 0; j < 4; j++) acc[i][j] = 0.0f;
    float den = 0.0f;

    CP_WAIT1();               // uv complete
    __syncthreads();          // uv + As/Cs/Ts visible
    float fA = As_[il], fC = Cs_[il], fT = Ts_[il];

    auto buildP = [&](int c, unsigned w) {
        unsigned short* Ph = dsm + 10240 + (c & 1) * 5120;
        const float* us = uvf + c * 32 + jb;
        const float* vs = uvf + 1024 + c * 32 + jb;
#pragma unroll
        for (int qq = 0; qq < 16; qq += 4) {
            float4 u4 = *(const float4*)(us + qq);
            float4 v4 = *(const float4*)(vs + qq);
            float uu[4] = {u4.x, u4.y, u4.z, u4.w};
            float vv[4] = {v4.x, v4.y, v4.z, v4.w};
            float pv[4];
#pragma unroll
            for (int e = 0; e < 4; e++) {
                bool cs = uu[e] > fT;
                float p = (cs ? fA : fC) * (cs ? uu[e] : vv[e]);
                p = ((w >> (jb + qq + e)) & 1u) ? p : 0.0f;
                den += p;
                pv[e] = p;
            }
            __half2 h01 = __floats2half2_rn(pv[0], pv[1]);
            __half2 h23 = __floats2half2_rn(pv[2], pv[3]);
            *(uint2*)&Ph[il * 40 + jb + qq] =
                make_uint2(*(unsigned*)&h01, *(unsigned*)&h23);
        }
    };
    buildP(0, adjn);
    adjn = g_adjb[(size_t)(b * N_ + i0 + il) * NW_ + 1];

    for (int c = 0; c < 32; c++) {
        CP_WAIT0();
        __syncthreads();                 // h(c) ready; P(c) built by all threads
        if (c + 1 < 32) { at_issue(sbase, (c + 1) & 1, c + 1, bh, t); CP_COMMIT(); }
        unsigned short* hs = dsm + (c & 1) * 5120;
        unsigned short* Ph = dsm + 10240 + (c & 1) * 5120;
        mma_chunk_h(acc, Ph, hs, hs + 2560, ibase, lane);
        if (c + 1 < 32) {
            buildP(c + 1, adjn);         // other P buffer, no barrier needed
            if (c + 2 < 32) adjn = g_adjb[(size_t)(b * N_ + i0 + il) * NW_ + c + 2];
        }
    }

    den += __shfl_xor_sync(0xffffffffu, den, 1);
    dens[il] = den;
    __syncthreads();

    int r = lane >> 2, c2 = (lane & 3) * 2;
    float inv1 = 1.0f / dens[ibase + r];
    float inv2 = 1.0f / dens[ibase + r + 8];
#pragma unroll
    for (int nt = 0; nt < 8; nt++) {
        size_t i1 = (size_t)(b * N_ + i0 + ibase + r) * D_ + h * DH_ + nt * 8 + c2;
        size_t i2 = (size_t)(b * N_ + i0 + ibase + r + 8) * D_ + h * DH_ + nt * 8 + c2;
        float2 x1 = *(const float2*)(x + i1);
        float2 x2 = *(const float2*)(x + i2);
        float2 o1 = make_float2(x1.x + elu1(acc[nt][0] * inv1),
                                x1.y + elu1(acc[nt][1] * inv1));
        float2 o2 = make_float2(x2.x + elu1(acc[nt][2] * inv2),
                                x2.y + elu1(acc[nt][3] * inv2));
        *(float2*)&g_y[i1] = o1;
        *(float2*)&g_y[i2] = o2;
    }
}

// ---------------- launch ----------------
extern "C" void kernel_launch(void* const* d_in, const int* in_sizes, int n_in,
                              void* d_out, int out_size) {
    const float* x     = (const float*)d_in[0];
    const int*   adj   = (const int*)  d_in[2];
    const float* W     = (const float*)d_in[3];
    const float* a_src = (const float*)d_in[4];
    const float* a_dst = (const float*)d_in[5];
    const float* ln1g  = (const float*)d_in[6];
    const float* ln1b  = (const float*)d_in[7];
    const float* ln2g  = (const float*)d_in[8];
    const float* ln2b  = (const float*)d_in[9];
    float* out = (float*)d_out;

    cudaFuncSetAttribute(gemm1t_kernel, cudaFuncAttributeMaxDynamicSharedMemorySize, GM_DSM);
    cudaFuncSetAttribute(attn_kernel,   cudaFuncAttributeMaxDynamicSharedMemorySize, AT_DSM);

    ln1_kernel   <<<B_*N_, 128>>>(x, ln1g, ln1b);
    pack_adj_kernel<<<(B_*N_*N_) / 256, 256>>>(adj);
    prep_w_kernel<<<H_*DH_, 128>>>(W);
    gemm1t_kernel<<<dim3(B_*N_/128, H_), 256, GM_DSM>>>(a_src, a_dst);
    gmaxuv_kernel<<<B_*H_, 256>>>();
    htrans_kernel<<<dim3(N_/32, DH_/32, B_*H_), dim3(32, 8)>>>();
    attn_kernel  <<<dim3(N_/128, H_, B_), 256, AT_DSM>>>(x);
    ln2_kernel   <<<B_*N_, 128>>>(ln2g, ln2b, out);
}

// round 10
// speedup vs baseline: 4.8917x; 1.3267x over previous
#include <cuda_runtime.h>
#include <cuda_fp16.h>
#include <cstdint>

#define B_ 8
#define N_ 1024
#define D_ 512
#define H_ 8
#define DH_ 64
#define NW_ (N_/32)
#define L2E 1.4426950408889634f

// ---------------- scratch ----------------
__device__ unsigned short g_xn16[B_*N_*D_];     // LN1 out, fp16
__device__ unsigned short g_W16 [H_*DH_*D_];    // W^T [h][d][k], fp16
__device__ float    g_h [B_*N_*D_];             // h fp32, [b][n][h][k]
__device__ unsigned short g_hT16[B_*H_*DH_*N_]; // h^T [b][h][d][j], fp16
__device__ float    g_fs[B_*H_*N_];
__device__ float    g_fd[B_*H_*N_];
__device__ unsigned g_adjb[B_*N_*NW_];
__device__ float    g_y [B_*N_*D_];
__device__ float    g_A[B_*H_*N_];
__device__ float    g_C[B_*H_*N_];
__device__ float    g_T[B_*H_*N_];
__device__ float    g_u[B_*H_*N_];
__device__ float    g_v[B_*H_*N_];

// ---------------- helpers ----------------
__device__ __forceinline__ float fexp2f(float t) {
    t = fmaxf(t, -125.0f);
    float r = t + 12582912.0f;
    int   n = __float_as_int(r) - 0x4B400000;
    float f = t - (r - 12582912.0f);
    float p = 1.3333558146e-3f;
    p = fmaf(p, f, 9.6181291298e-3f);
    p = fmaf(p, f, 5.5504108664e-2f);
    p = fmaf(p, f, 2.4022650696e-1f);
    p = fmaf(p, f, 6.9314718056e-1f);
    p = fmaf(p, f, 1.0f);
    return __int_as_float(__float_as_int(p) + (n << 23));
}
__device__ __forceinline__ float elu1(float v) {
    return v > 0.0f ? v : (fexp2f(v * L2E) - 1.0f);
}
__device__ __forceinline__ unsigned smem_u32(const void* p) {
    unsigned a;
    asm("{ .reg .u64 t; cvta.to.shared.u64 t, %1; cvt.u32.u64 %0, t; }" : "=r"(a) : "l"(p));
    return a;
}
__device__ __forceinline__ void cpa16(unsigned s, const void* g) {
    asm volatile("cp.async.cg.shared.global [%0], [%1], 16;" :: "r"(s), "l"(g) : "memory");
}
#define CP_COMMIT() asm volatile("cp.async.commit_group;" ::: "memory")
#define CP_WAIT0()  asm volatile("cp.async.wait_group 0;" ::: "memory")
#define CP_WAIT1()  asm volatile("cp.async.wait_group 1;" ::: "memory")

__device__ __forceinline__ void mma16816h(float* c, unsigned a0, unsigned a1,
                                          unsigned a2, unsigned a3,
                                          unsigned b0, unsigned b1) {
    asm volatile(
        "mma.sync.aligned.m16n8k16.row.col.f32.f16.f16.f32 "
        "{%0,%1,%2,%3}, {%4,%5,%6,%7}, {%8,%9}, {%0,%1,%2,%3};\n"
        : "+f"(c[0]), "+f"(c[1]), "+f"(c[2]), "+f"(c[3])
        : "r"(a0), "r"(a1), "r"(a2), "r"(a3), "r"(b0), "r"(b1));
}

// ---- single x single fp16 k32 step: A[128][32] stride 40, B[64][32] stride 40 ----
__device__ __forceinline__ void mma_chunk_ss(float acc[8][4],
        const unsigned short* __restrict__ A, const unsigned short* __restrict__ B,
        int ibase, int lane) {
    int r  = lane >> 2;
    int c2 = (lane & 3) * 2;
#pragma unroll
    for (int kk = 0; kk < 2; kk++) {
        const unsigned short* pA = A + (ibase + r) * 40 + kk * 16 + c2;
        unsigned a0 = *(const unsigned*)(pA);
        unsigned a1 = *(const unsigned*)(pA + 8 * 40);
        unsigned a2 = *(const unsigned*)(pA + 8);
        unsigned a3 = *(const unsigned*)(pA + 8 * 40 + 8);
#pragma unroll
        for (int g = 0; g < 2; g++) {
            unsigned bh[4][2];
#pragma unroll
            for (int q = 0; q < 4; q++) {
                int nt = g * 4 + q;
                const unsigned short* pB = B + (nt * 8 + r) * 40 + kk * 16 + c2;
                bh[q][0] = *(const unsigned*)(pB);
                bh[q][1] = *(const unsigned*)(pB + 8);
            }
#pragma unroll
            for (int q = 0; q < 4; q++)
                mma16816h(acc[g*4+q], a0, a1, a2, a3, bh[q][0], bh[q][1]);
        }
    }
}

// ---------------- LN1 (fp16 out) ----------------
__global__ void ln1_kernel(const float* __restrict__ x, const float* __restrict__ gw,
                           const float* __restrict__ bw) {
    int row = blockIdx.x, t = threadIdx.x;
    const float4 v = ((const float4*)(x + (size_t)row * D_))[t];
    float s = v.x + v.y + v.z + v.w;
    float q = v.x*v.x + v.y*v.y + v.z*v.z + v.w*v.w;
#pragma unroll
    for (int o = 16; o; o >>= 1) {
        s += __shfl_xor_sync(0xffffffffu, s, o);
        q += __shfl_xor_sync(0xffffffffu, q, o);
    }
    __shared__ float ss[4], qs[4];
    if ((t & 31) == 0) { ss[t >> 5] = s; qs[t >> 5] = q; }
    __syncthreads();
    s = ss[0] + ss[1] + ss[2] + ss[3];
    q = qs[0] + qs[1] + qs[2] + qs[3];
    float mean = s * (1.0f / D_);
    float var  = fmaxf(q * (1.0f / D_) - mean * mean, 0.0f);
    float inv  = 1.0f / (sqrtf(var) + 1e-6f);
    const float4 g4 = ((const float4*)gw)[t];
    const float4 b4 = ((const float4*)bw)[t];
    float o0 = fmaf(g4.x * (v.x - mean), inv, b4.x);
    float o1 = fmaf(g4.y * (v.y - mean), inv, b4.y);
    float o2 = fmaf(g4.z * (v.z - mean), inv, b4.z);
    float o3 = fmaf(g4.w * (v.w - mean), inv, b4.w);
    __half2 h01 = __floats2half2_rn(o0, o1);
    __half2 h23 = __floats2half2_rn(o2, o3);
    *(uint2*)&g_xn16[(size_t)row * D_ + t * 4] =
        make_uint2(*(unsigned*)&h01, *(unsigned*)&h23);
}

// ---------------- LN2 ----------------
__global__ void ln2_kernel(const float* __restrict__ gw, const float* __restrict__ bw,
                           float* __restrict__ out) {
    int row = blockIdx.x, t = threadIdx.x;
    const float4 v = ((const float4*)(g_y + (size_t)row * D_))[t];
    float s = v.x + v.y + v.z + v.w;
    float q = v.x*v.x + v.y*v.y + v.z*v.z + v.w*v.w;
#pragma unroll
    for (int o = 16; o; o >>= 1) {
        s += __shfl_xor_sync(0xffffffffu, s, o);
        q += __shfl_xor_sync(0xffffffffu, q, o);
    }
    __shared__ float ss[4], qs[4];
    if ((t & 31) == 0) { ss[t >> 5] = s; qs[t >> 5] = q; }
    __syncthreads();
    s = ss[0] + ss[1] + ss[2] + ss[3];
    q = qs[0] + qs[1] + qs[2] + qs[3];
    float mean = s * (1.0f / D_);
    float var  = fmaxf(q * (1.0f / D_) - mean * mean, 0.0f);
    float inv  = 1.0f / (sqrtf(var) + 1e-6f);
    const float4 g4 = ((const float4*)gw)[t];
    const float4 b4 = ((const float4*)bw)[t];
    float4 o;
    o.x = fmaf(g4.x * (v.x - mean), inv, b4.x);
    o.y = fmaf(g4.y * (v.y - mean), inv, b4.y);
    o.z = fmaf(g4.z * (v.z - mean), inv, b4.z);
    o.w = fmaf(g4.w * (v.w - mean), inv, b4.w);
    ((float4*)(out + (size_t)row * D_))[t] = o;
}

// ---------------- pack adj ----------------
__global__ void pack_adj_kernel(const int* __restrict__ adj) {
    int gw   = (blockIdx.x * blockDim.x + threadIdx.x) >> 5;
    int lane = threadIdx.x & 31;
    int v = adj[(size_t)gw * 32 + lane];
    unsigned m = __ballot_sync(0xffffffffu, v > 0);
    if (lane == 0) g_adjb[gw] = m;
}

// ---------------- W^T fp16 ----------------
__global__ void prep_w_kernel(const float* __restrict__ W) {
    int hd = blockIdx.x;
    int h = hd >> 6, d = hd & 63;
    for (int k = threadIdx.x; k < D_; k += 128) {
        float v = W[(size_t)h * D_ * DH_ + (size_t)k * DH_ + d];
        g_W16[(size_t)hd * D_ + k] = __half_as_ushort(__float2half_rn(v));
    }
}

// ---------------- GEMM1: fp16 single, k64 chunks (2x k32 tiles), 2-stage ----------------
// stage (shorts): A0@0 (5120), A1@5120, B0@10240 (2560), B1@12800; 15360 sh = 30720 B
#define GM_DSM (2 * 30720)
__device__ __forceinline__ void g1_issue(unsigned sbase, int st, int c, int m0, int h, int t) {
    unsigned sb = sbase + (unsigned)st * 30720u;
    int k0 = c * 64;
#pragma unroll
    for (int i = t; i < 1536; i += 256) {
        const unsigned short* g;
        unsigned dst;
        if (i < 1024) {
            int tile = i >> 9;
            int idx = i & 511;
            int row = idx >> 2, seg = idx & 3;
            g = g_xn16 + (size_t)(m0 + row) * D_ + k0 + tile * 32 + seg * 8;
            dst = sb + tile * 10240u + row * 80u + seg * 16u;
        } else {
            int idx = i - 1024;
            int tile = idx >> 8;
            idx &= 255;
            int row = idx >> 2, seg = idx & 3;
            g = g_W16 + (size_t)(h * 64 + row) * D_ + k0 + tile * 32 + seg * 8;
            dst = sb + 20480u + tile * 5120u + row * 80u + seg * 16u;
        }
        cpa16(dst, g);
    }
}
__global__ __launch_bounds__(256, 3) void gemm1t_kernel(const float* __restrict__ a_src,
                                                        const float* __restrict__ a_dst) {
    extern __shared__ unsigned short dsm[];
    __shared__ float as_s[64], ad_s[64];
    unsigned sbase = smem_u32(dsm);
    int t = threadIdx.x, warp = t >> 5, lane = t & 31;
    int m0 = blockIdx.x * 128, h = blockIdx.y;
    int ibase = warp * 16;

    if (t < 64) as_s[t] = a_src[h * 64 + t];
    else if (t < 128) ad_s[t - 64] = a_dst[h * 64 + t - 64];

    float acc[8][4];
#pragma unroll
    for (int i = 0; i < 8; i++)
#pragma unroll
        for (int j = 0; j < 4; j++) acc[i][j] = 0.0f;

    g1_issue(sbase, 0, 0, m0, h, t); CP_COMMIT();

    for (int c = 0; c < 8; c++) {
        CP_WAIT0();
        __syncthreads();
        if (c + 1 < 8) { g1_issue(sbase, (c + 1) & 1, c + 1, m0, h, t); CP_COMMIT(); }
        unsigned short* stg = dsm + (c & 1) * 15360;
        mma_chunk_ss(acc, stg,        stg + 10240, ibase, lane);   // k 0..31
        mma_chunk_ss(acc, stg + 5120, stg + 12800, ibase, lane);   // k 32..63
    }

    int r = lane >> 2, q = lane & 3, c2 = q * 2;
    float fs1 = 0.f, fd1 = 0.f, fs2 = 0.f, fd2 = 0.f;
#pragma unroll
    for (int nt = 0; nt < 8; nt++) {
        float a0 = as_s[nt * 8 + c2], a1 = as_s[nt * 8 + c2 + 1];
        float d0 = ad_s[nt * 8 + c2], d1 = ad_s[nt * 8 + c2 + 1];
        fs1 = fmaf(acc[nt][0], a0, fmaf(acc[nt][1], a1, fs1));
        fd1 = fmaf(acc[nt][0], d0, fmaf(acc[nt][1], d1, fd1));
        fs2 = fmaf(acc[nt][2], a0, fmaf(acc[nt][3], a1, fs2));
        fd2 = fmaf(acc[nt][2], d0, fmaf(acc[nt][3], d1, fd2));
    }
#pragma unroll
    for (int o = 1; o <= 2; o <<= 1) {
        fs1 += __shfl_xor_sync(0xffffffffu, fs1, o);
        fd1 += __shfl_xor_sync(0xffffffffu, fd1, o);
        fs2 += __shfl_xor_sync(0xffffffffu, fs2, o);
        fd2 += __shfl_xor_sync(0xffffffffu, fd2, o);
    }
    if (q == 0) {
        int m1 = m0 + ibase + r, m2 = m1 + 8;
        int b1 = m1 >> 10, n1 = m1 & 1023;
        int b2 = m2 >> 10, n2 = m2 & 1023;
        g_fs[(b1 * H_ + h) * N_ + n1] = fs1 * L2E;
        g_fd[(b1 * H_ + h) * N_ + n1] = fd1 * L2E;
        g_fs[(b2 * H_ + h) * N_ + n2] = fs2 * L2E;
        g_fd[(b2 * H_ + h) * N_ + n2] = fd2 * L2E;
    }
#pragma unroll
    for (int nt = 0; nt < 8; nt++) {
        size_t i1 = (size_t)(m0 + ibase + r) * D_ + h * DH_ + nt * 8 + c2;
        size_t i2 = (size_t)(m0 + ibase + r + 8) * D_ + h * DH_ + nt * 8 + c2;
        *(float2*)&g_h[i1] = make_float2(acc[nt][0], acc[nt][1]);
        *(float2*)&g_h[i2] = make_float2(acc[nt][2], acc[nt][3]);
    }
}

// ---------------- merged gmax + uv ----------------
__global__ void gmaxuv_kernel() {
    __shared__ float sm[8];
    __shared__ float gmv;
    int bh = blockIdx.x, t = threadIdx.x;
    float fdv[4];
    float m = -1e30f;
#pragma unroll
    for (int k = 0; k < 4; k++) {
        fdv[k] = g_fd[bh * N_ + t + k * 256];
        m = fmaxf(m, fdv[k]);
    }
#pragma unroll
    for (int o = 16; o; o >>= 1) m = fmaxf(m, __shfl_xor_sync(0xffffffffu, m, o));
    if ((t & 31) == 0) sm[t >> 5] = m;
    __syncthreads();
    if (t == 0) {
        float mm = sm[0];
#pragma unroll
        for (int i = 1; i < 8; i++) mm = fmaxf(mm, sm[i]);
        gmv = mm;
    }
    __syncthreads();
    float gm = gmv;
#pragma unroll
    for (int k = 0; k < 4; k++) {
        int idx = bh * N_ + t + k * 256;
        float fs = g_fs[idx];
        float bound = fs + gm;
        float mx = fmaxf(bound, 0.2f * bound);
        g_A[idx] = fexp2f(bound - mx);
        g_C[idx] = fexp2f(0.2f * bound - mx);
        g_T[idx] = fexp2f(-bound);
        g_u[idx] = fexp2f(fdv[k] - gm);
        g_v[idx] = fexp2f(0.2f * (fdv[k] - gm));
    }
}

// ---------------- h -> h^T fp16 ----------------
__global__ void htrans_kernel() {
    __shared__ float s[32][33];
    int bh = blockIdx.z, j0 = blockIdx.x * 32, d0 = blockIdx.y * 32;
    int b = bh >> 3, h = bh & 7;
    int tx = threadIdx.x, ty = threadIdx.y;
#pragma unroll
    for (int k = 0; k < 4; k++) {
        int jj = ty + k * 8;
        s[jj][tx] = g_h[(size_t)(b * N_ + j0 + jj) * D_ + h * DH_ + d0 + tx];
    }
    __syncthreads();
#pragma unroll
    for (int k = 0; k < 4; k++) {
        int dd = ty + k * 8;
        size_t idx = (size_t)bh * DH_ * N_ + (size_t)(d0 + dd) * N_ + j0 + tx;
        g_hT16[idx] = __half_as_ushort(__float2half_rn(s[tx][dd]));
    }
}

// ---------------- attention: fp16 P(single) x h(single), 2-stage h + 2-stage P ----
// dsm (shorts): h0@0 (2560), h1@2560, P0@5120 (5120), P1@10240, uv floats @15360 (4096 sh)
#define AT_DSM (15360 * 2 + 8192)
__device__ __forceinline__ void at_issue(unsigned sbase, int st, int c, int bh, int t) {
    unsigned sb = sbase + (unsigned)st * 5120u;
    int j0 = c * 32;
#pragma unroll
    for (int i = t; i < 256; i += 256) {
        int row = i >> 2, seg = i & 3;
        const unsigned short* g = g_hT16 +
            (size_t)bh * DH_ * N_ + (size_t)row * N_ + j0 + seg * 8;
        cpa16(sb + row * 80u + seg * 16u, g);
    }
}
__global__ __launch_bounds__(256, 3) void attn_kernel(const float* __restrict__ x) {
    extern __shared__ unsigned short dsm[];
    __shared__ float As_[128], Cs_[128], Ts_[128], dens[128];
    unsigned sbase = smem_u32(dsm);
    int t = threadIdx.x, warp = t >> 5, lane = t & 31;
    int b = blockIdx.z, h = blockIdx.y, i0 = blockIdx.x * 128;
    int bh = b * H_ + h;
    int ibase = warp * 16;
    int il = t >> 1, s = t & 1, jb = s * 16;

    const float* uvf = (const float*)(dsm + 15360);

    // uv preload (8KB), then h chunk 0
#pragma unroll
    for (int i = t; i < 512; i += 256) {
        const float* g = (i < 256) ? (g_u + bh * N_ + i * 4)
                                   : (g_v + bh * N_ + (i - 256) * 4);
        cpa16(sbase + 30720u + (unsigned)i * 16u, g);
    }
    CP_COMMIT();
    at_issue(sbase, 0, 0, bh, t); CP_COMMIT();

    if (t < 128) {
        int gi = bh * N_ + i0 + t;
        As_[t] = g_A[gi]; Cs_[t] = g_C[gi]; Ts_[t] = g_T[gi];
    }
    unsigned adjn = g_adjb[(size_t)(b * N_ + i0 + il) * NW_ + 0];

    float acc[8][4];
#pragma unroll
    for (int i = 0; i < 8; i++)
#pragma unroll
        for (int j = 0; j < 4; j++) acc[i][j] = 0.0f;
    float den = 0.0f;

    CP_WAIT1();               // uv complete
    __syncthreads();          // uv + As/Cs/Ts visible
    float fA = As_[il], fC = Cs_[il], fT = Ts_[il];

    auto buildP = [&](int c, unsigned w) {
        unsigned short* Ph = dsm + 5120 + (c & 1) * 5120;
        const float* us = uvf + c * 32 + jb;
        const float* vs = uvf + 1024 + c * 32 + jb;
#pragma unroll
        for (int qq = 0; qq < 16; qq += 4) {
            float4 u4 = *(const float4*)(us + qq);
            float4 v4 = *(const float4*)(vs + qq);
            float uu[4] = {u4.x, u4.y, u4.z, u4.w};
            float vv[4] = {v4.x, v4.y, v4.z, v4.w};
            float pv[4];
#pragma unroll
            for (int e = 0; e < 4; e++) {
                bool cs = uu[e] > fT;
                float p = (cs ? fA : fC) * (cs ? uu[e] : vv[e]);
                p = ((w >> (jb + qq + e)) & 1u) ? p : 0.0f;
                den += p;
                pv[e] = p;
            }
            __half2 h01 = __floats2half2_rn(pv[0], pv[1]);
            __half2 h23 = __floats2half2_rn(pv[2], pv[3]);
            *(uint2*)&Ph[il * 40 + jb + qq] =
                make_uint2(*(unsigned*)&h01, *(unsigned*)&h23);
        }
    };
    buildP(0, adjn);
    adjn = g_adjb[(size_t)(b * N_ + i0 + il) * NW_ + 1];

    for (int c = 0; c < 32; c++) {
        CP_WAIT0();
        __syncthreads();                 // h(c) ready; P(c) built by all threads
        if (c + 1 < 32) { at_issue(sbase, (c + 1) & 1, c + 1, bh, t); CP_COMMIT(); }
        unsigned short* hs = dsm + (c & 1) * 2560;
        unsigned short* Ph = dsm + 5120 + (c & 1) * 5120;
        mma_chunk_ss(acc, Ph, hs, ibase, lane);
        if (c + 1 < 32) {
            buildP(c + 1, adjn);         // other P buffer, no barrier needed
            if (c + 2 < 32) adjn = g_adjb[(size_t)(b * N_ + i0 + il) * NW_ + c + 2];
        }
    }

    den += __shfl_xor_sync(0xffffffffu, den, 1);
    dens[il] = den;
    __syncthreads();

    int r = lane >> 2, c2 = (lane & 3) * 2;
    float inv1 = 1.0f / dens[ibase + r];
    float inv2 = 1.0f / dens[ibase + r + 8];
#pragma unroll
    for (int nt = 0; nt < 8; nt++) {
        size_t i1 = (size_t)(b * N_ + i0 + ibase + r) * D_ + h * DH_ + nt * 8 + c2;
        size_t i2 = (size_t)(b * N_ + i0 + ibase + r + 8) * D_ + h * DH_ + nt * 8 + c2;
        float2 x1 = *(const float2*)(x + i1);
        float2 x2 = *(const float2*)(x + i2);
        float2 o1 = make_float2(x1.x + elu1(acc[nt][0] * inv1),
                                x1.y + elu1(acc[nt][1] * inv1));
        float2 o2 = make_float2(x2.x + elu1(acc[nt][2] * inv2),
                                x2.y + elu1(acc[nt][3] * inv2));
        *(float2*)&g_y[i1] = o1;
        *(float2*)&g_y[i2] = o2;
    }
}

// ---------------- launch ----------------
extern "C" void kernel_launch(void* const* d_in, const int* in_sizes, int n_in,
                              void* d_out, int out_size) {
    const float* x     = (const float*)d_in[0];
    const int*   adj   = (const int*)  d_in[2];
    const float* W     = (const float*)d_in[3];
    const float* a_src = (const float*)d_in[4];
    const float* a_dst = (const float*)d_in[5];
    const float* ln1g  = (const float*)d_in[6];
    const float* ln1b  = (const float*)d_in[7];
    const float* ln2g  = (const float*)d_in[8];
    const float* ln2b  = (const float*)d_in[9];
    float* out = (float*)d_out;

    cudaFuncSetAttribute(gemm1t_kernel, cudaFuncAttributeMaxDynamicSharedMemorySize, GM_DSM);
    cudaFuncSetAttribute(attn_kernel,   cudaFuncAttributeMaxDynamicSharedMemorySize, AT_DSM);

    ln1_kernel   <<<B_*N_, 128>>>(x, ln1g, ln1b);
    pack_adj_kernel<<<(B_*N_*N_) / 256, 256>>>(adj);
    prep_w_kernel<<<H_*DH_, 128>>>(W);
    gemm1t_kernel<<<dim3(B_*N_/128, H_), 256, GM_DSM>>>(a_src, a_dst);
    gmaxuv_kernel<<<B_*H_, 256>>>();
    htrans_kernel<<<dim3(N_/32, DH_/32, B_*H_), dim3(32, 8)>>>();
    attn_kernel  <<<dim3(N_/128, H_, B_), 256, AT_DSM>>>(x);
    ln2_kernel   <<<B_*N_, 128>>>(ln2g, ln2b, out);
}

// round 11
// speedup vs baseline: 5.3243x; 1.0884x over previous
#include <cuda_runtime.h>
#include <cuda_fp16.h>
#include <cstdint>

#define B_ 8
#define N_ 1024
#define D_ 512
#define H_ 8
#define DH_ 64
#define NW_ (N_/32)
#define L2E 1.4426950408889634f

// ---------------- scratch ----------------
__device__ unsigned short g_xn16[B_*N_*D_];     // LN1 out, fp16
__device__ unsigned short g_W16 [H_*DH_*D_];    // W^T [h][d][k], fp16
__device__ unsigned short g_hT16[B_*H_*DH_*N_]; // h^T [b][h][d][j], fp16
__device__ float    g_fs[B_*H_*N_];
__device__ float    g_fd[B_*H_*N_];
__device__ unsigned g_adjb[B_*N_*NW_];
__device__ float    g_y [B_*N_*D_];
__device__ float    g_A[B_*H_*N_];
__device__ float    g_C[B_*H_*N_];
__device__ float    g_T[B_*H_*N_];
__device__ float    g_u[B_*H_*N_];
__device__ float    g_v[B_*H_*N_];

// ---------------- helpers ----------------
__device__ __forceinline__ float fexp2f(float t) {
    t = fmaxf(t, -125.0f);
    float r = t + 12582912.0f;
    int   n = __float_as_int(r) - 0x4B400000;
    float f = t - (r - 12582912.0f);
    float p = 1.3333558146e-3f;
    p = fmaf(p, f, 9.6181291298e-3f);
    p = fmaf(p, f, 5.5504108664e-2f);
    p = fmaf(p, f, 2.4022650696e-1f);
    p = fmaf(p, f, 6.9314718056e-1f);
    p = fmaf(p, f, 1.0f);
    return __int_as_float(__float_as_int(p) + (n << 23));
}
__device__ __forceinline__ float elu1(float v) {
    return v > 0.0f ? v : (fexp2f(v * L2E) - 1.0f);
}
__device__ __forceinline__ unsigned smem_u32(const void* p) {
    unsigned a;
    asm("{ .reg .u64 t; cvta.to.shared.u64 t, %1; cvt.u32.u64 %0, t; }" : "=r"(a) : "l"(p));
    return a;
}
__device__ __forceinline__ void cpa16(unsigned s, const void* g) {
    asm volatile("cp.async.cg.shared.global [%0], [%1], 16;" :: "r"(s), "l"(g) : "memory");
}
#define CP_COMMIT() asm volatile("cp.async.commit_group;" ::: "memory")
#define CP_WAIT0()  asm volatile("cp.async.wait_group 0;" ::: "memory")
#define CP_WAIT1()  asm volatile("cp.async.wait_group 1;" ::: "memory")

__device__ __forceinline__ void mma16816h(float* c, unsigned a0, unsigned a1,
                                          unsigned a2, unsigned a3,
                                          unsigned b0, unsigned b1) {
    asm volatile(
        "mma.sync.aligned.m16n8k16.row.col.f32.f16.f16.f32 "
        "{%0,%1,%2,%3}, {%4,%5,%6,%7}, {%8,%9}, {%0,%1,%2,%3};\n"
        : "+f"(c[0]), "+f"(c[1]), "+f"(c[2]), "+f"(c[3])
        : "r"(a0), "r"(a1), "r"(a2), "r"(a3), "r"(b0), "r"(b1));
}

// ---- single x single fp16 k32 step: A[128][32] stride 40, B[64][32] stride 40 ----
__device__ __forceinline__ void mma_chunk_ss(float acc[8][4],
        const unsigned short* __restrict__ A, const unsigned short* __restrict__ B,
        int ibase, int lane) {
    int r  = lane >> 2;
    int c2 = (lane & 3) * 2;
#pragma unroll
    for (int kk = 0; kk < 2; kk++) {
        const unsigned short* pA = A + (ibase + r) * 40 + kk * 16 + c2;
        unsigned a0 = *(const unsigned*)(pA);
        unsigned a1 = *(const unsigned*)(pA + 8 * 40);
        unsigned a2 = *(const unsigned*)(pA + 8);
        unsigned a3 = *(const unsigned*)(pA + 8 * 40 + 8);
#pragma unroll
        for (int g = 0; g < 2; g++) {
            unsigned bh[4][2];
#pragma unroll
            for (int q = 0; q < 4; q++) {
                int nt = g * 4 + q;
                const unsigned short* pB = B + (nt * 8 + r) * 40 + kk * 16 + c2;
                bh[q][0] = *(const unsigned*)(pB);
                bh[q][1] = *(const unsigned*)(pB + 8);
            }
#pragma unroll
            for (int q = 0; q < 4; q++)
                mma16816h(acc[g*4+q], a0, a1, a2, a3, bh[q][0], bh[q][1]);
        }
    }
}

// ---------------- LN1 (fp16 out) ----------------
__global__ void ln1_kernel(const float* __restrict__ x, const float* __restrict__ gw,
                           const float* __restrict__ bw) {
    int row = blockIdx.x, t = threadIdx.x;
    const float4 v = ((const float4*)(x + (size_t)row * D_))[t];
    float s = v.x + v.y + v.z + v.w;
    float q = v.x*v.x + v.y*v.y + v.z*v.z + v.w*v.w;
#pragma unroll
    for (int o = 16; o; o >>= 1) {
        s += __shfl_xor_sync(0xffffffffu, s, o);
        q += __shfl_xor_sync(0xffffffffu, q, o);
    }
    __shared__ float ss[4], qs[4];
    if ((t & 31) == 0) { ss[t >> 5] = s; qs[t >> 5] = q; }
    __syncthreads();
    s = ss[0] + ss[1] + ss[2] + ss[3];
    q = qs[0] + qs[1] + qs[2] + qs[3];
    float mean = s * (1.0f / D_);
    float var  = fmaxf(q * (1.0f / D_) - mean * mean, 0.0f);
    float inv  = 1.0f / (sqrtf(var) + 1e-6f);
    const float4 g4 = ((const float4*)gw)[t];
    const float4 b4 = ((const float4*)bw)[t];
    float o0 = fmaf(g4.x * (v.x - mean), inv, b4.x);
    float o1 = fmaf(g4.y * (v.y - mean), inv, b4.y);
    float o2 = fmaf(g4.z * (v.z - mean), inv, b4.z);
    float o3 = fmaf(g4.w * (v.w - mean), inv, b4.w);
    __half2 h01 = __floats2half2_rn(o0, o1);
    __half2 h23 = __floats2half2_rn(o2, o3);
    *(uint2*)&g_xn16[(size_t)row * D_ + t * 4] =
        make_uint2(*(unsigned*)&h01, *(unsigned*)&h23);
}

// ---------------- LN2 ----------------
__global__ void ln2_kernel(const float* __restrict__ gw, const float* __restrict__ bw,
                           float* __restrict__ out) {
    int row = blockIdx.x, t = threadIdx.x;
    const float4 v = ((const float4*)(g_y + (size_t)row * D_))[t];
    float s = v.x + v.y + v.z + v.w;
    float q = v.x*v.x + v.y*v.y + v.z*v.z + v.w*v.w;
#pragma unroll
    for (int o = 16; o; o >>= 1) {
        s += __shfl_xor_sync(0xffffffffu, s, o);
        q += __shfl_xor_sync(0xffffffffu, q, o);
    }
    __shared__ float ss[4], qs[4];
    if ((t & 31) == 0) { ss[t >> 5] = s; qs[t >> 5] = q; }
    __syncthreads();
    s = ss[0] + ss[1] + ss[2] + ss[3];
    q = qs[0] + qs[1] + qs[2] + qs[3];
    float mean = s * (1.0f / D_);
    float var  = fmaxf(q * (1.0f / D_) - mean * mean, 0.0f);
    float inv  = 1.0f / (sqrtf(var) + 1e-6f);
    const float4 g4 = ((const float4*)gw)[t];
    const float4 b4 = ((const float4*)bw)[t];
    float4 o;
    o.x = fmaf(g4.x * (v.x - mean), inv, b4.x);
    o.y = fmaf(g4.y * (v.y - mean), inv, b4.y);
    o.z = fmaf(g4.z * (v.z - mean), inv, b4.z);
    o.w = fmaf(g4.w * (v.w - mean), inv, b4.w);
    ((float4*)(out + (size_t)row * D_))[t] = o;
}

// ---------------- pack adj ----------------
__global__ void pack_adj_kernel(const int* __restrict__ adj) {
    int gw   = (blockIdx.x * blockDim.x + threadIdx.x) >> 5;
    int lane = threadIdx.x & 31;
    int v = adj[(size_t)gw * 32 + lane];
    unsigned m = __ballot_sync(0xffffffffu, v > 0);
    if (lane == 0) g_adjb[gw] = m;
}

// ---------------- W^T fp16 ----------------
__global__ void prep_w_kernel(const float* __restrict__ W) {
    int hd = blockIdx.x;
    int h = hd >> 6, d = hd & 63;
    for (int k = threadIdx.x; k < D_; k += 128) {
        float v = W[(size_t)h * D_ * DH_ + (size_t)k * DH_ + d];
        g_W16[(size_t)hd * D_ + k] = __half_as_ushort(__float2half_rn(v));
    }
}

// ---------------- GEMM1: fp16, k64 chunks, fused fs/fd + fused hT16 transpose ----
// stage (shorts): A0@0 (5120), A1@5120, B0@10240 (2560), B1@12800; 15360 sh = 30720 B
#define GM_DSM (2 * 30720)
__device__ __forceinline__ void g1_issue(unsigned sbase, int st, int c, int m0, int h, int t) {
    unsigned sb = sbase + (unsigned)st * 30720u;
    int k0 = c * 64;
#pragma unroll
    for (int i = t; i < 1536; i += 256) {
        const unsigned short* g;
        unsigned dst;
        if (i < 1024) {
            int tile = i >> 9;
            int idx = i & 511;
            int row = idx >> 2, seg = idx & 3;
            g = g_xn16 + (size_t)(m0 + row) * D_ + k0 + tile * 32 + seg * 8;
            dst = sb + tile * 10240u + row * 80u + seg * 16u;
        } else {
            int idx = i - 1024;
            int tile = idx >> 8;
            idx &= 255;
            int row = idx >> 2, seg = idx & 3;
            g = g_W16 + (size_t)(h * 64 + row) * D_ + k0 + tile * 32 + seg * 8;
            dst = sb + 20480u + tile * 5120u + row * 80u + seg * 16u;
        }
        cpa16(dst, g);
    }
}
__global__ __launch_bounds__(256, 3) void gemm1t_kernel(const float* __restrict__ a_src,
                                                        const float* __restrict__ a_dst) {
    extern __shared__ unsigned short dsm[];
    __shared__ float as_s[64], ad_s[64];
    unsigned sbase = smem_u32(dsm);
    int t = threadIdx.x, warp = t >> 5, lane = t & 31;
    int m0 = blockIdx.x * 128, h = blockIdx.y;
    int ibase = warp * 16;

    if (t < 64) as_s[t] = a_src[h * 64 + t];
    else if (t < 128) ad_s[t - 64] = a_dst[h * 64 + t - 64];

    float acc[8][4];
#pragma unroll
    for (int i = 0; i < 8; i++)
#pragma unroll
        for (int j = 0; j < 4; j++) acc[i][j] = 0.0f;

    g1_issue(sbase, 0, 0, m0, h, t); CP_COMMIT();

    for (int c = 0; c < 8; c++) {
        CP_WAIT0();
        __syncthreads();
        if (c + 1 < 8) { g1_issue(sbase, (c + 1) & 1, c + 1, m0, h, t); CP_COMMIT(); }
        unsigned short* stg = dsm + (c & 1) * 15360;
        mma_chunk_ss(acc, stg,        stg + 10240, ibase, lane);   // k 0..31
        mma_chunk_ss(acc, stg + 5120, stg + 12800, ibase, lane);   // k 32..63
    }

    int r = lane >> 2, q = lane & 3, c2 = q * 2;
    // fused fs/fd
    float fs1 = 0.f, fd1 = 0.f, fs2 = 0.f, fd2 = 0.f;
#pragma unroll
    for (int nt = 0; nt < 8; nt++) {
        float a0 = as_s[nt * 8 + c2], a1 = as_s[nt * 8 + c2 + 1];
        float d0 = ad_s[nt * 8 + c2], d1 = ad_s[nt * 8 + c2 + 1];
        fs1 = fmaf(acc[nt][0], a0, fmaf(acc[nt][1], a1, fs1));
        fd1 = fmaf(acc[nt][0], d0, fmaf(acc[nt][1], d1, fd1));
        fs2 = fmaf(acc[nt][2], a0, fmaf(acc[nt][3], a1, fs2));
        fd2 = fmaf(acc[nt][2], d0, fmaf(acc[nt][3], d1, fd2));
    }
#pragma unroll
    for (int o = 1; o <= 2; o <<= 1) {
        fs1 += __shfl_xor_sync(0xffffffffu, fs1, o);
        fd1 += __shfl_xor_sync(0xffffffffu, fd1, o);
        fs2 += __shfl_xor_sync(0xffffffffu, fs2, o);
        fd2 += __shfl_xor_sync(0xffffffffu, fd2, o);
    }
    if (q == 0) {
        int m1 = m0 + ibase + r, m2 = m1 + 8;
        int b1 = m1 >> 10, n1 = m1 & 1023;
        int b2 = m2 >> 10, n2 = m2 & 1023;
        g_fs[(b1 * H_ + h) * N_ + n1] = fs1 * L2E;
        g_fd[(b1 * H_ + h) * N_ + n1] = fd1 * L2E;
        g_fs[(b2 * H_ + h) * N_ + n2] = fs2 * L2E;
        g_fd[(b2 * H_ + h) * N_ + n2] = fd2 * L2E;
    }

    // fused hT16: transpose acc via smem (layout [d][row], row stride 136 shorts)
    __syncthreads();                  // everyone done reading mma stages
#pragma unroll
    for (int nt = 0; nt < 8; nt++) {
        int d0 = nt * 8 + c2;
        dsm[(d0    ) * 136 + ibase + r    ] = __half_as_ushort(__float2half_rn(acc[nt][0]));
        dsm[(d0 + 1) * 136 + ibase + r    ] = __half_as_ushort(__float2half_rn(acc[nt][1]));
        dsm[(d0    ) * 136 + ibase + r + 8] = __half_as_ushort(__float2half_rn(acc[nt][2]));
        dsm[(d0 + 1) * 136 + ibase + r + 8] = __half_as_ushort(__float2half_rn(acc[nt][3]));
    }
    __syncthreads();
    int b = m0 >> 10, n0 = m0 & 1023;
    size_t base = ((size_t)(b * H_ + h) * DH_) * N_ + n0;
#pragma unroll
    for (int k = 0; k < 4; k++) {
        int i = t + k * 256;          // 0..1023
        int d = i >> 4, seg = i & 15;
        *(uint4*)&g_hT16[base + (size_t)d * N_ + seg * 8] =
            *(const uint4*)&dsm[d * 136 + seg * 8];
    }
}

// ---------------- merged gmax + uv ----------------
__global__ void gmaxuv_kernel() {
    __shared__ float sm[8];
    __shared__ float gmv;
    int bh = blockIdx.x, t = threadIdx.x;
    float fdv[4];
    float m = -1e30f;
#pragma unroll
    for (int k = 0; k < 4; k++) {
        fdv[k] = g_fd[bh * N_ + t + k * 256];
        m = fmaxf(m, fdv[k]);
    }
#pragma unroll
    for (int o = 16; o; o >>= 1) m = fmaxf(m, __shfl_xor_sync(0xffffffffu, m, o));
    if ((t & 31) == 0) sm[t >> 5] = m;
    __syncthreads();
    if (t == 0) {
        float mm = sm[0];
#pragma unroll
        for (int i = 1; i < 8; i++) mm = fmaxf(mm, sm[i]);
        gmv = mm;
    }
    __syncthreads();
    float gm = gmv;
#pragma unroll
    for (int k = 0; k < 4; k++) {
        int idx = bh * N_ + t + k * 256;
        float fs = g_fs[idx];
        float bound = fs + gm;
        float mx = fmaxf(bound, 0.2f * bound);
        g_A[idx] = fexp2f(bound - mx);
        g_C[idx] = fexp2f(0.2f * bound - mx);
        g_T[idx] = fexp2f(-bound);
        g_u[idx] = fexp2f(fdv[k] - gm);
        g_v[idx] = fexp2f(0.2f * (fdv[k] - gm));
    }
}

// ---------------- attention: fp16, j-chunk 64 (2 subtiles), ONE sync per 64 j ----
// dsm (shorts): h stages 2*5120 (each: sub0 2560 | sub1 2560),
//               P stages @10240: 2*10240 (each: sub0 5120 | sub1 5120),
//               uv floats @30720 (4096 sh). Total 69632 B.
#define AT_DSM (30720 * 2 + 8192)
__device__ __forceinline__ void at_issue(unsigned sbase, int st, int c, int bh, int t) {
    unsigned sb = sbase + (unsigned)st * 10240u;
    int j0 = c * 64;
#pragma unroll
    for (int i = t; i < 512; i += 256) {
        int sub = i >> 8;
        int idx = i & 255;
        int row = idx >> 2, seg = idx & 3;
        const unsigned short* g = g_hT16 +
            (size_t)bh * DH_ * N_ + (size_t)row * N_ + j0 + sub * 32 + seg * 8;
        cpa16(sb + sub * 5120u + row * 80u + seg * 16u, g);
    }
}
__global__ __launch_bounds__(256, 3) void attn_kernel(const float* __restrict__ x) {
    extern __shared__ unsigned short dsm[];
    __shared__ float As_[128], Cs_[128], Ts_[128], dens[128];
    unsigned sbase = smem_u32(dsm);
    int t = threadIdx.x, warp = t >> 5, lane = t & 31;
    int b = blockIdx.z, h = blockIdx.y, i0 = blockIdx.x * 128;
    int bh = b * H_ + h;
    int ibase = warp * 16;
    int il = t >> 1, s = t & 1, jb = s * 16;

    const float* uvf = (const float*)(dsm + 30720);

    // uv preload (8KB), then h chunk 0 (64 j)
#pragma unroll
    for (int i = t; i < 512; i += 256) {
        const float* g = (i < 256) ? (g_u + bh * N_ + i * 4)
                                   : (g_v + bh * N_ + (i - 256) * 4);
        cpa16(sbase + 61440u + (unsigned)i * 16u, g);
    }
    CP_COMMIT();
    at_issue(sbase, 0, 0, bh, t); CP_COMMIT();

    if (t < 128) {
        int gi = bh * N_ + i0 + t;
        As_[t] = g_A[gi]; Cs_[t] = g_C[gi]; Ts_[t] = g_T[gi];
    }
    uint2 adjn = *(const uint2*)&g_adjb[(size_t)(b * N_ + i0 + il) * NW_ + 0];

    float acc[8][4];
#pragma unroll
    for (int i = 0; i < 8; i++)
#pragma unroll
        for (int j = 0; j < 4; j++) acc[i][j] = 0.0f;
    float den = 0.0f;

    CP_WAIT1();               // uv complete
    __syncthreads();          // uv + As/Cs/Ts visible
    float fA = As_[il], fC = Cs_[il], fT = Ts_[il];

    auto buildP = [&](int c, uint2 w2) {
        unsigned short* Pst = dsm + 10240 + (c & 1) * 10240;
#pragma unroll
        for (int sub = 0; sub < 2; sub++) {
            unsigned short* Ph = Pst + sub * 5120;
            unsigned w = sub ? w2.y : w2.x;
            const float* us = uvf + c * 64 + sub * 32 + jb;
            const float* vs = uvf + 1024 + c * 64 + sub * 32 + jb;
#pragma unroll
            for (int qq = 0; qq < 16; qq += 4) {
                float4 u4 = *(const float4*)(us + qq);
                float4 v4 = *(const float4*)(vs + qq);
                float uu[4] = {u4.x, u4.y, u4.z, u4.w};
                float vv[4] = {v4.x, v4.y, v4.z, v4.w};
                float pv[4];
#pragma unroll
                for (int e = 0; e < 4; e++) {
                    bool cs = uu[e] > fT;
                    float p = (cs ? fA : fC) * (cs ? uu[e] : vv[e]);
                    p = ((w >> (jb + qq + e)) & 1u) ? p : 0.0f;
                    den += p;
                    pv[e] = p;
                }
                __half2 h01 = __floats2half2_rn(pv[0], pv[1]);
                __half2 h23 = __floats2half2_rn(pv[2], pv[3]);
                *(uint2*)&Ph[il * 40 + jb + qq] =
                    make_uint2(*(unsigned*)&h01, *(unsigned*)&h23);
            }
        }
    };
    buildP(0, adjn);
    adjn = *(const uint2*)&g_adjb[(size_t)(b * N_ + i0 + il) * NW_ + 2];

    for (int c = 0; c < 16; c++) {
        CP_WAIT0();
        __syncthreads();                 // h(c) ready; P(c) built by all threads
        if (c + 1 < 16) { at_issue(sbase, (c + 1) & 1, c + 1, bh, t); CP_COMMIT(); }
        unsigned short* hs = dsm + (c & 1) * 5120;
        unsigned short* Ph = dsm + 10240 + (c & 1) * 10240;
        mma_chunk_ss(acc, Ph,        hs,        ibase, lane);
        mma_chunk_ss(acc, Ph + 5120, hs + 2560, ibase, lane);
        if (c + 1 < 16) {
            buildP(c + 1, adjn);         // other P buffer, no barrier needed
            if (c + 2 < 16)
                adjn = *(const uint2*)&g_adjb[(size_t)(b * N_ + i0 + il) * NW_ + (c + 2) * 2];
        }
    }

    den += __shfl_xor_sync(0xffffffffu, den, 1);
    dens[il] = den;
    __syncthreads();

    int r = lane >> 2, c2 = (lane & 3) * 2;
    float inv1 = 1.0f / dens[ibase + r];
    float inv2 = 1.0f / dens[ibase + r + 8];
#pragma unroll
    for (int nt = 0; nt < 8; nt++) {
        size_t i1 = (size_t)(b * N_ + i0 + ibase + r) * D_ + h * DH_ + nt * 8 + c2;
        size_t i2 = (size_t)(b * N_ + i0 + ibase + r + 8) * D_ + h * DH_ + nt * 8 + c2;
        float2 x1 = *(const float2*)(x + i1);
        float2 x2 = *(const float2*)(x + i2);
        float2 o1 = make_float2(x1.x + elu1(acc[nt][0] * inv1),
                                x1.y + elu1(acc[nt][1] * inv1));
        float2 o2 = make_float2(x2.x + elu1(acc[nt][2] * inv2),
                                x2.y + elu1(acc[nt][3] * inv2));
        *(float2*)&g_y[i1] = o1;
        *(float2*)&g_y[i2] = o2;
    }
}

// ---------------- launch ----------------
extern "C" void kernel_launch(void* const* d_in, const int* in_sizes, int n_in,
                              void* d_out, int out_size) {
    const float* x     = (const float*)d_in[0];
    const int*   adj   = (const int*)  d_in[2];
    const float* W     = (const float*)d_in[3];
    const float* a_src = (const float*)d_in[4];
    const float* a_dst = (const float*)d_in[5];
    const float* ln1g  = (const float*)d_in[6];
    const float* ln1b  = (const float*)d_in[7];
    const float* ln2g  = (const float*)d_in[8];
    const float* ln2b  = (const float*)d_in[9];
    float* out = (float*)d_out;

    cudaFuncSetAttribute(gemm1t_kernel, cudaFuncAttributeMaxDynamicSharedMemorySize, GM_DSM);
    cudaFuncSetAttribute(attn_kernel,   cudaFuncAttributeMaxDynamicSharedMemorySize, AT_DSM);

    ln1_kernel   <<<B_*N_, 128>>>(x, ln1g, ln1b);
    pack_adj_kernel<<<(B_*N_*N_) / 256, 256>>>(adj);
    prep_w_kernel<<<H_*DH_, 128>>>(W);
    gemm1t_kernel<<<dim3(B_*N_/128, H_), 256, GM_DSM>>>(a_src, a_dst);
    gmaxuv_kernel<<<B_*H_, 256>>>();
    attn_kernel  <<<dim3(N_/128, H_, B_), 256, AT_DSM>>>(x);
    ln2_kernel   <<<B_*N_, 128>>>(ln2g, ln2b, out);
}

// round 13
// speedup vs baseline: 5.4227x; 1.0185x over previous
#include <cuda_runtime.h>
#include <cuda_fp16.h>
#include <cstdint>

#define B_ 8
#define N_ 1024
#define D_ 512
#define H_ 8
#define DH_ 64
#define NW_ (N_/32)
#define L2E 1.4426950408889634f

// ---------------- scratch ----------------
__device__ unsigned short g_xn16[B_*N_*D_];     // LN1 out, fp16
__device__ unsigned short g_W16 [H_*DH_*D_];    // W^T [h][d][k], fp16
__device__ unsigned short g_hT16[B_*H_*DH_*N_]; // h^T [b][h][d][j], fp16
__device__ float    g_fs[B_*H_*N_];
__device__ float    g_fd[B_*H_*N_];
__device__ unsigned g_adjb[B_*N_*NW_];
__device__ float    g_y [B_*N_*D_];
__device__ float    g_A[B_*H_*N_];
__device__ float    g_C[B_*H_*N_];
__device__ float    g_T[B_*H_*N_];
__device__ float    g_u[B_*H_*N_];
__device__ float    g_v[B_*H_*N_];

// ---------------- helpers ----------------
__device__ __forceinline__ float fexp2f(float t) {
    t = fmaxf(t, -125.0f);
    float r = t + 12582912.0f;
    int   n = __float_as_int(r) - 0x4B400000;
    float f = t - (r - 12582912.0f);
    float p = 1.3333558146e-3f;
    p = fmaf(p, f, 9.6181291298e-3f);
    p = fmaf(p, f, 5.5504108664e-2f);
    p = fmaf(p, f, 2.4022650696e-1f);
    p = fmaf(p, f, 6.9314718056e-1f);
    p = fmaf(p, f, 1.0f);
    return __int_as_float(__float_as_int(p) + (n << 23));
}
__device__ __forceinline__ float elu1(float v) {
    return v > 0.0f ? v : (fexp2f(v * L2E) - 1.0f);
}
__device__ __forceinline__ unsigned smem_u32(const void* p) {
    unsigned a;
    asm("{ .reg .u64 t; cvta.to.shared.u64 t, %1; cvt.u32.u64 %0, t; }" : "=r"(a) : "l"(p));
    return a;
}
__device__ __forceinline__ void cpa16(unsigned s, const void* g) {
    asm volatile("cp.async.cg.shared.global [%0], [%1], 16;" :: "r"(s), "l"(g) : "memory");
}
#define CP_COMMIT() asm volatile("cp.async.commit_group;" ::: "memory")
#define CP_WAIT0()  asm volatile("cp.async.wait_group 0;" ::: "memory")
#define CP_WAIT1()  asm volatile("cp.async.wait_group 1;" ::: "memory")

__device__ __forceinline__ void mma16816h(float* c, unsigned a0, unsigned a1,
                                          unsigned a2, unsigned a3,
                                          unsigned b0, unsigned b1) {
    asm volatile(
        "mma.sync.aligned.m16n8k16.row.col.f32.f16.f16.f32 "
        "{%0,%1,%2,%3}, {%4,%5,%6,%7}, {%8,%9}, {%0,%1,%2,%3};\n"
        : "+f"(c[0]), "+f"(c[1]), "+f"(c[2]), "+f"(c[3])
        : "r"(a0), "r"(a1), "r"(a2), "r"(a3), "r"(b0), "r"(b1));
}
__device__ __forceinline__ void ldsm4(unsigned addr, unsigned &r0, unsigned &r1,
                                      unsigned &r2, unsigned &r3) {
    asm volatile("ldmatrix.sync.aligned.m8n8.x4.shared.b16 {%0,%1,%2,%3}, [%4];"
                 : "=r"(r0), "=r"(r1), "=r"(r2), "=r"(r3) : "r"(addr));
}

// ---- fp16 k32 step via ldmatrix: A[128][32] stride 40 sh, B[64][32] stride 40 sh ----
// A, B are u32 smem byte-addresses of the tile bases.
__device__ __forceinline__ void mma_chunk_ss(float acc[8][4], unsigned A, unsigned B,
                                             int ibase, int lane) {
    int mat  = lane >> 3;       // which 8x8 matrix this lane's address feeds
    int mrow = lane & 7;
#pragma unroll
    for (int kk = 0; kk < 2; kk++) {
        // A mats: (row-half = mat&1, k-half = mat>>1)
        unsigned a0, a1, a2, a3;
        unsigned aaddr = A + (unsigned)(((ibase + (mat & 1) * 8 + mrow) * 40
                                         + kk * 16 + (mat >> 1) * 8) * 2);
        ldsm4(aaddr, a0, a1, a2, a3);
#pragma unroll
        for (int g = 0; g < 4; g++) {          // pairs of n-tiles
            int ntp = g * 2;
            // B mats: (n-tile = ntp + (mat>>1), k-half = mat&1)
            unsigned b0, b1, b2, b3;
            unsigned baddr = B + (unsigned)((((ntp + (mat >> 1)) * 8 + mrow) * 40
                                             + kk * 16 + (mat & 1) * 8) * 2);
            ldsm4(baddr, b0, b1, b2, b3);
            mma16816h(acc[ntp],     a0, a1, a2, a3, b0, b1);
            mma16816h(acc[ntp + 1], a0, a1, a2, a3, b2, b3);
        }
    }
}

// ---------------- LN1 (fp16 out) ----------------
__global__ void ln1_kernel(const float* __restrict__ x, const float* __restrict__ gw,
                           const float* __restrict__ bw) {
    int row = blockIdx.x, t = threadIdx.x;
    const float4 v = ((const float4*)(x + (size_t)row * D_))[t];
    float s = v.x + v.y + v.z + v.w;
    float q = v.x*v.x + v.y*v.y + v.z*v.z + v.w*v.w;
#pragma unroll
    for (int o = 16; o; o >>= 1) {
        s += __shfl_xor_sync(0xffffffffu, s, o);
        q += __shfl_xor_sync(0xffffffffu, q, o);
    }
    __shared__ float ss[4], qs[4];
    if ((t & 31) == 0) { ss[t >> 5] = s; qs[t >> 5] = q; }
    __syncthreads();
    s = ss[0] + ss[1] + ss[2] + ss[3];
    q = qs[0] + qs[1] + qs[2] + qs[3];
    float mean = s * (1.0f / D_);
    float var  = fmaxf(q * (1.0f / D_) - mean * mean, 0.0f);
    float inv  = 1.0f / (sqrtf(var) + 1e-6f);
    const float4 g4 = ((const float4*)gw)[t];
    const float4 b4 = ((const float4*)bw)[t];
    float o0 = fmaf(g4.x * (v.x - mean), inv, b4.x);
    float o1 = fmaf(g4.y * (v.y - mean), inv, b4.y);
    float o2 = fmaf(g4.z * (v.z - mean), inv, b4.z);
    float o3 = fmaf(g4.w * (v.w - mean), inv, b4.w);
    __half2 h01 = __floats2half2_rn(o0, o1);
    __half2 h23 = __floats2half2_rn(o2, o3);
    *(uint2*)&g_xn16[(size_t)row * D_ + t * 4] =
        make_uint2(*(unsigned*)&h01, *(unsigned*)&h23);
}

// ---------------- LN2 ----------------
__global__ void ln2_kernel(const float* __restrict__ gw, const float* __restrict__ bw,
                           float* __restrict__ out) {
    int row = blockIdx.x, t = threadIdx.x;
    const float4 v = ((const float4*)(g_y + (size_t)row * D_))[t];
    float s = v.x + v.y + v.z + v.w;
    float q = v.x*v.x + v.y*v.y + v.z*v.z + v.w*v.w;
#pragma unroll
    for (int o = 16; o; o >>= 1) {
        s += __shfl_xor_sync(0xffffffffu, s, o);
        q += __shfl_xor_sync(0xffffffffu, q, o);
    }
    __shared__ float ss[4], qs[4];
    if ((t & 31) == 0) { ss[t >> 5] = s; qs[t >> 5] = q; }
    __syncthreads();
    s = ss[0] + ss[1] + ss[2] + ss[3];
    q = qs[0] + qs[1] + qs[2] + qs[3];
    float mean = s * (1.0f / D_);
    float var  = fmaxf(q * (1.0f / D_) - mean * mean, 0.0f);
    float inv  = 1.0f / (sqrtf(var) + 1e-6f);
    const float4 g4 = ((const float4*)gw)[t];
    const float4 b4 = ((const float4*)bw)[t];
    float4 o;
    o.x = fmaf(g4.x * (v.x - mean), inv, b4.x);
    o.y = fmaf(g4.y * (v.y - mean), inv, b4.y);
    o.z = fmaf(g4.z * (v.z - mean), inv, b4.z);
    o.w = fmaf(g4.w * (v.w - mean), inv, b4.w);
    ((float4*)(out + (size_t)row * D_))[t] = o;
}

// ---------------- pack adj ----------------
__global__ void pack_adj_kernel(const int* __restrict__ adj) {
    int gw   = (blockIdx.x * blockDim.x + threadIdx.x) >> 5;
    int lane = threadIdx.x & 31;
    int v = adj[(size_t)gw * 32 + lane];
    unsigned m = __ballot_sync(0xffffffffu, v > 0);
    if (lane == 0) g_adjb[gw] = m;
}

// ---------------- W^T fp16 ----------------
__global__ void prep_w_kernel(const float* __restrict__ W) {
    int hd = blockIdx.x;
    int h = hd >> 6, d = hd & 63;
    for (int k = threadIdx.x; k < D_; k += 128) {
        float v = W[(size_t)h * D_ * DH_ + (size_t)k * DH_ + d];
        g_W16[(size_t)hd * D_ + k] = __half_as_ushort(__float2half_rn(v));
    }
}

// ---------------- GEMM1: fp16, k64 chunks, fused fs/fd + fused hT16 transpose ----
// stage (shorts): A0@0 (5120), A1@5120, B0@10240 (2560), B1@12800; 15360 sh = 30720 B
#define GM_DSM (2 * 30720)
__device__ __forceinline__ void g1_issue(unsigned sbase, int st, int c, int m0, int h, int t) {
    unsigned sb = sbase + (unsigned)st * 30720u;
    int k0 = c * 64;
#pragma unroll
    for (int i = t; i < 1536; i += 256) {
        const unsigned short* g;
        unsigned dst;
        if (i < 1024) {
            int tile = i >> 9;
            int idx = i & 511;
            int row = idx >> 2, seg = idx & 3;
            g = g_xn16 + (size_t)(m0 + row) * D_ + k0 + tile * 32 + seg * 8;
            dst = sb + tile * 10240u + row * 80u + seg * 16u;
        } else {
            int idx = i - 1024;
            int tile = idx >> 8;
            idx &= 255;
            int row = idx >> 2, seg = idx & 3;
            g = g_W16 + (size_t)(h * 64 + row) * D_ + k0 + tile * 32 + seg * 8;
            dst = sb + 20480u + tile * 5120u + row * 80u + seg * 16u;
        }
        cpa16(dst, g);
    }
}
__global__ __launch_bounds__(256, 3) void gemm1t_kernel(const float* __restrict__ a_src,
                                                        const float* __restrict__ a_dst) {
    extern __shared__ unsigned short dsm[];
    __shared__ float as_s[64], ad_s[64];
    unsigned sbase = smem_u32(dsm);
    int t = threadIdx.x, warp = t >> 5, lane = t & 31;
    int m0 = blockIdx.x * 128, h = blockIdx.y;
    int ibase = warp * 16;

    if (t < 64) as_s[t] = a_src[h * 64 + t];
    else if (t < 128) ad_s[t - 64] = a_dst[h * 64 + t - 64];

    float acc[8][4];
#pragma unroll
    for (int i = 0; i < 8; i++)
#pragma unroll
        for (int j = 0; j < 4; j++) acc[i][j] = 0.0f;

    g1_issue(sbase, 0, 0, m0, h, t); CP_COMMIT();

    for (int c = 0; c < 8; c++) {
        CP_WAIT0();
        __syncthreads();
        if (c + 1 < 8) { g1_issue(sbase, (c + 1) & 1, c + 1, m0, h, t); CP_COMMIT(); }
        unsigned stb = sbase + (unsigned)(c & 1) * 30720u;
        mma_chunk_ss(acc, stb,          stb + 20480u, ibase, lane);   // k 0..31
        mma_chunk_ss(acc, stb + 10240u, stb + 25600u, ibase, lane);   // k 32..63
    }

    int r = lane >> 2, q = lane & 3, c2 = q * 2;
    // fused fs/fd
    float fs1 = 0.f, fd1 = 0.f, fs2 = 0.f, fd2 = 0.f;
#pragma unroll
    for (int nt = 0; nt < 8; nt++) {
        float a0 = as_s[nt * 8 + c2], a1 = as_s[nt * 8 + c2 + 1];
        float d0 = ad_s[nt * 8 + c2], d1 = ad_s[nt * 8 + c2 + 1];
        fs1 = fmaf(acc[nt][0], a0, fmaf(acc[nt][1], a1, fs1));
        fd1 = fmaf(acc[nt][0], d0, fmaf(acc[nt][1], d1, fd1));
        fs2 = fmaf(acc[nt][2], a0, fmaf(acc[nt][3], a1, fs2));
        fd2 = fmaf(acc[nt][2], d0, fmaf(acc[nt][3], d1, fd2));
    }
#pragma unroll
    for (int o = 1; o <= 2; o <<= 1) {
        fs1 += __shfl_xor_sync(0xffffffffu, fs1, o);
        fd1 += __shfl_xor_sync(0xffffffffu, fd1, o);
        fs2 += __shfl_xor_sync(0xffffffffu, fs2, o);
        fd2 += __shfl_xor_sync(0xffffffffu, fd2, o);
    }
    if (q == 0) {
        int m1 = m0 + ibase + r, m2 = m1 + 8;
        int b1 = m1 >> 10, n1 = m1 & 1023;
        int b2 = m2 >> 10, n2 = m2 & 1023;
        g_fs[(b1 * H_ + h) * N_ + n1] = fs1 * L2E;
        g_fd[(b1 * H_ + h) * N_ + n1] = fd1 * L2E;
        g_fs[(b2 * H_ + h) * N_ + n2] = fs2 * L2E;
        g_fd[(b2 * H_ + h) * N_ + n2] = fd2 * L2E;
    }

    // fused hT16: transpose acc via smem (layout [d][row], row stride 136 shorts)
    __syncthreads();                  // everyone done reading mma stages
#pragma unroll
    for (int nt = 0; nt < 8; nt++) {
        int d0 = nt * 8 + c2;
        dsm[(d0    ) * 136 + ibase + r    ] = __half_as_ushort(__float2half_rn(acc[nt][0]));
        dsm[(d0 + 1) * 136 + ibase + r    ] = __half_as_ushort(__float2half_rn(acc[nt][1]));
        dsm[(d0    ) * 136 + ibase + r + 8] = __half_as_ushort(__float2half_rn(acc[nt][2]));
        dsm[(d0 + 1) * 136 + ibase + r + 8] = __half_as_ushort(__float2half_rn(acc[nt][3]));
    }
    __syncthreads();
    int b = m0 >> 10, n0 = m0 & 1023;
    size_t base = ((size_t)(b * H_ + h) * DH_) * N_ + n0;
#pragma unroll
    for (int k = 0; k < 4; k++) {
        int i = t + k * 256;          // 0..1023
        int d = i >> 4, seg = i & 15;
        *(uint4*)&g_hT16[base + (size_t)d * N_ + seg * 8] =
            *(const uint4*)&dsm[d * 136 + seg * 8];
    }
}

// ---------------- merged gmax + uv ----------------
__global__ void gmaxuv_kernel() {
    __shared__ float sm[8];
    __shared__ float gmv;
    int bh = blockIdx.x, t = threadIdx.x;
    float fdv[4];
    float m = -1e30f;
#pragma unroll
    for (int k = 0; k < 4; k++) {
        fdv[k] = g_fd[bh * N_ + t + k * 256];
        m = fmaxf(m, fdv[k]);
    }
#pragma unroll
    for (int o = 16; o; o >>= 1) m = fmaxf(m, __shfl_xor_sync(0xffffffffu, m, o));
    if ((t & 31) == 0) sm[t >> 5] = m;
    __syncthreads();
    if (t == 0) {
        float mm = sm[0];
#pragma unroll
        for (int i = 1; i < 8; i++) mm = fmaxf(mm, sm[i]);
        gmv = mm;
    }
    __syncthreads();
    float gm = gmv;
#pragma unroll
    for (int k = 0; k < 4; k++) {
        int idx = bh * N_ + t + k * 256;
        float fs = g_fs[idx];
        float bound = fs + gm;
        float mx = fmaxf(bound, 0.2f * bound);
        g_A[idx] = fexp2f(bound - mx);
        g_C[idx] = fexp2f(0.2f * bound - mx);
        g_T[idx] = fexp2f(-bound);
        g_u[idx] = fexp2f(fdv[k] - gm);
        g_v[idx] = fexp2f(0.2f * (fdv[k] - gm));
    }
}

// ---------------- attention: fp16, j-chunk 64, ldmatrix frags ----
// dsm (shorts): h stages 2*5120 (each: sub0 2560 | sub1 2560),
//               P stages @10240: 2*10240 (each: sub0 5120 | sub1 5120),
//               uv floats @30720 (4096 sh). Total 69632 B.
#define AT_DSM (30720 * 2 + 8192)
__device__ __forceinline__ void at_issue(unsigned sbase, int st, int c, int bh, int t) {
    unsigned sb = sbase + (unsigned)st * 10240u;
    int j0 = c * 64;
#pragma unroll
    for (int i = t; i < 512; i += 256) {
        int sub = i >> 8;
        int idx = i & 255;
        int row = idx >> 2, seg = idx & 3;
        const unsigned short* g = g_hT16 +
            (size_t)bh * DH_ * N_ + (size_t)row * N_ + j0 + sub * 32 + seg * 8;
        cpa16(sb + sub * 5120u + row * 80u + seg * 16u, g);
    }
}
__global__ __launch_bounds__(256, 3) void attn_kernel(const float* __restrict__ x) {
    extern __shared__ unsigned short dsm[];
    __shared__ float As_[128], Cs_[128], Ts_[128], dens[128];
    unsigned sbase = smem_u32(dsm);
    int t = threadIdx.x, warp = t >> 5, lane = t & 31;
    int b = blockIdx.z, h = blockIdx.y, i0 = blockIdx.x * 128;
    int bh = b * H_ + h;
    int ibase = warp * 16;
    int il = t >> 1, s = t & 1, jb = s * 16;

    const float* uvf = (const float*)(dsm + 30720);

    // uv preload (8KB), then h chunk 0 (64 j)
#pragma unroll
    for (int i = t; i < 512; i += 256) {
        const float* g = (i < 256) ? (g_u + bh * N_ + i * 4)
                                   : (g_v + bh * N_ + (i - 256) * 4);
        cpa16(sbase + 61440u + (unsigned)i * 16u, g);
    }
    CP_COMMIT();
    at_issue(sbase, 0, 0, bh, t); CP_COMMIT();

    if (t < 128) {
        int gi = bh * N_ + i0 + t;
        As_[t] = g_A[gi]; Cs_[t] = g_C[gi]; Ts_[t] = g_T[gi];
    }
    uint2 adjn = *(const uint2*)&g_adjb[(size_t)(b * N_ + i0 + il) * NW_ + 0];

    float acc[8][4];
#pragma unroll
    for (int i = 0; i < 8; i++)
#pragma unroll
        for (int j = 0; j < 4; j++) acc[i][j] = 0.0f;
    float den = 0.0f;

    CP_WAIT1();               // uv complete
    __syncthreads();          // uv + As/Cs/Ts visible
    float fA = As_[il], fC = Cs_[il], fT = Ts_[il];

    auto buildP = [&](int c, uint2 w2) {
        unsigned short* Pst = dsm + 10240 + (c & 1) * 10240;
#pragma unroll
        for (int sub = 0; sub < 2; sub++) {
            unsigned short* Ph = Pst + sub * 5120;
            unsigned w = sub ? w2.y : w2.x;
            const float* us = uvf + c * 64 + sub * 32 + jb;
            const float* vs = uvf + 1024 + c * 64 + sub * 32 + jb;
#pragma unroll
            for (int qq = 0; qq < 16; qq += 4) {
                float4 u4 = *(const float4*)(us + qq);
                float4 v4 = *(const float4*)(vs + qq);
                float uu[4] = {u4.x, u4.y, u4.z, u4.w};
                float vv[4] = {v4.x, v4.y, v4.z, v4.w};
                float pv[4];
#pragma unroll
                for (int e = 0; e < 4; e++) {
                    bool cs = uu[e] > fT;
                    float p = (cs ? fA : fC) * (cs ? uu[e] : vv[e]);
                    p = ((w >> (jb + qq + e)) & 1u) ? p : 0.0f;
                    den += p;
                    pv[e] = p;
                }
                __half2 h01 = __floats2half2_rn(pv[0], pv[1]);
                __half2 h23 = __floats2half2_rn(pv[2], pv[3]);
                *(uint2*)&Ph[il * 40 + jb + qq] =
                    make_uint2(*(unsigned*)&h01, *(unsigned*)&h23);
            }
        }
    };
    buildP(0, adjn);
    adjn = *(const uint2*)&g_adjb[(size_t)(b * N_ + i0 + il) * NW_ + 2];

    for (int c = 0; c < 16; c++) {
        CP_WAIT0();
        __syncthreads();                 // h(c) ready; P(c) built by all threads
        if (c + 1 < 16) { at_issue(sbase, (c + 1) & 1, c + 1, bh, t); CP_COMMIT(); }
        unsigned hsb = sbase + (unsigned)(c & 1) * 10240u;
        unsigned pb  = sbase + 20480u + (unsigned)(c & 1) * 20480u;
        mma_chunk_ss(acc, pb,           hsb,          ibase, lane);
        mma_chunk_ss(acc, pb + 10240u,  hsb + 5120u,  ibase, lane);
        if (c + 1 < 16) {
            buildP(c + 1, adjn);         // other P buffer, no barrier needed
            if (c + 2 < 16)
                adjn = *(const uint2*)&g_adjb[(size_t)(b * N_ + i0 + il) * NW_ + (c + 2) * 2];
        }
    }

    den += __shfl_xor_sync(0xffffffffu, den, 1);
    dens[il] = den;
    __syncthreads();

    int r = lane >> 2, c2 = (lane & 3) * 2;
    float inv1 = 1.0f / dens[ibase + r];
    float inv2 = 1.0f / dens[ibase + r + 8];
#pragma unroll
    for (int nt = 0; nt < 8; nt++) {
        size_t i1 = (size_t)(b * N_ + i0 + ibase + r) * D_ + h * DH_ + nt * 8 + c2;
        size_t i2 = (size_t)(b * N_ + i0 + ibase + r + 8) * D_ + h * DH_ + nt * 8 + c2;
        float2 x1 = *(const float2*)(x + i1);
        float2 x2 = *(const float2*)(x + i2);
        float2 o1 = make_float2(x1.x + elu1(acc[nt][0] * inv1),
                                x1.y + elu1(acc[nt][1] * inv1));
        float2 o2 = make_float2(x2.x + elu1(acc[nt][2] * inv2),
                                x2.y + elu1(acc[nt][3] * inv2));
        *(float2*)&g_y[i1] = o1;
        *(float2*)&g_y[i2] = o2;
    }
}

// ---------------- launch ----------------
extern "C" void kernel_launch(void* const* d_in, const int* in_sizes, int n_in,
                              void* d_out, int out_size) {
    const float* x     = (const float*)d_in[0];
    const int*   adj   = (const int*)  d_in[2];
    const float* W     = (const float*)d_in[3];
    const float* a_src = (const float*)d_in[4];
    const float* a_dst = (const float*)d_in[5];
    const float* ln1g  = (const float*)d_in[6];
    const float* ln1b  = (const float*)d_in[7];
    const float* ln2g  = (const float*)d_in[8];
    const float* ln2b  = (const float*)d_in[9];
    float* out = (float*)d_out;

    cudaFuncSetAttribute(gemm1t_kernel, cudaFuncAttributeMaxDynamicSharedMemorySize, GM_DSM);
    cudaFuncSetAttribute(attn_kernel,   cudaFuncAttributeMaxDynamicSharedMemorySize, AT_DSM);

    ln1_kernel   <<<B_*N_, 128>>>(x, ln1g, ln1b);
    pack_adj_kernel<<<(B_*N_*N_) / 256, 256>>>(adj);
    prep_w_kernel<<<H_*DH_, 128>>>(W);
    gemm1t_kernel<<<dim3(B_*N_/128, H_), 256, GM_DSM>>>(a_src, a_dst);
    gmaxuv_kernel<<<B_*H_, 256>>>();
    attn_kernel  <<<dim3(N_/128, H_, B_), 256, AT_DSM>>>(x);
    ln2_kernel   <<<B_*N_, 128>>>(ln2g, ln2b, out);
}

// round 14
// speedup vs baseline: 5.8334x; 1.0757x over previous
#include <cuda_runtime.h>
#include <cuda_fp16.h>
#include <cstdint>

#define B_ 8
#define N_ 1024
#define D_ 512
#define H_ 8
#define DH_ 64
#define NW_ (N_/32)
#define L2E 1.4426950408889634f

// ---------------- scratch ----------------
__device__ unsigned short g_xn16[B_*N_*D_];     // LN1 out, fp16
__device__ unsigned short g_W16 [H_*DH_*D_];    // W^T [h][d][k], fp16
__device__ unsigned short g_hT16[B_*H_*DH_*N_]; // h^T [b][h][d][j], fp16
__device__ float    g_fs[B_*H_*N_];
__device__ float    g_fd[B_*H_*N_];
__device__ unsigned g_adjb[B_*N_*NW_];
__device__ float    g_y [B_*N_*D_];
__device__ float    g_A[B_*H_*N_];
__device__ float    g_C[B_*H_*N_];
__device__ float    g_T[B_*H_*N_];
__device__ float    g_u[B_*H_*N_];
__device__ float    g_v[B_*H_*N_];

// ---------------- helpers ----------------
__device__ __forceinline__ float fexp2f(float t) {
    t = fmaxf(t, -125.0f);
    float r = t + 12582912.0f;
    int   n = __float_as_int(r) - 0x4B400000;
    float f = t - (r - 12582912.0f);
    float p = 1.3333558146e-3f;
    p = fmaf(p, f, 9.6181291298e-3f);
    p = fmaf(p, f, 5.5504108664e-2f);
    p = fmaf(p, f, 2.4022650696e-1f);
    p = fmaf(p, f, 6.9314718056e-1f);
    p = fmaf(p, f, 1.0f);
    return __int_as_float(__float_as_int(p) + (n << 23));
}
__device__ __forceinline__ float elu1(float v) {
    return v > 0.0f ? v : (fexp2f(v * L2E) - 1.0f);
}
__device__ __forceinline__ unsigned smem_u32(const void* p) {
    unsigned a;
    asm("{ .reg .u64 t; cvta.to.shared.u64 t, %1; cvt.u32.u64 %0, t; }" : "=r"(a) : "l"(p));
    return a;
}
__device__ __forceinline__ void cpa16(unsigned s, const void* g) {
    asm volatile("cp.async.cg.shared.global [%0], [%1], 16;" :: "r"(s), "l"(g) : "memory");
}
#define CP_COMMIT() asm volatile("cp.async.commit_group;" ::: "memory")
#define CP_WAIT0()  asm volatile("cp.async.wait_group 0;" ::: "memory")
#define CP_WAIT1()  asm volatile("cp.async.wait_group 1;" ::: "memory")

__device__ __forceinline__ void mma16816h(float* c, unsigned a0, unsigned a1,
                                          unsigned a2, unsigned a3,
                                          unsigned b0, unsigned b1) {
    asm volatile(
        "mma.sync.aligned.m16n8k16.row.col.f32.f16.f16.f32 "
        "{%0,%1,%2,%3}, {%4,%5,%6,%7}, {%8,%9}, {%0,%1,%2,%3};\n"
        : "+f"(c[0]), "+f"(c[1]), "+f"(c[2]), "+f"(c[3])
        : "r"(a0), "r"(a1), "r"(a2), "r"(a3), "r"(b0), "r"(b1));
}
__device__ __forceinline__ void ldsm4(unsigned addr, unsigned &r0, unsigned &r1,
                                      unsigned &r2, unsigned &r3) {
    asm volatile("ldmatrix.sync.aligned.m8n8.x4.shared.b16 {%0,%1,%2,%3}, [%4];"
                 : "=r"(r0), "=r"(r1), "=r"(r2), "=r"(r3) : "r"(addr));
}

// ---- fp16 k32 step via ldmatrix (used by gemm1): A[128][32], B[64][32], stride 40 ----
__device__ __forceinline__ void mma_chunk_ss(float acc[8][4], unsigned A, unsigned B,
                                             int ibase, int lane) {
    int mat  = lane >> 3;
    int mrow = lane & 7;
#pragma unroll
    for (int kk = 0; kk < 2; kk++) {
        unsigned a0, a1, a2, a3;
        unsigned aaddr = A + (unsigned)(((ibase + (mat & 1) * 8 + mrow) * 40
                                         + kk * 16 + (mat >> 1) * 8) * 2);
        ldsm4(aaddr, a0, a1, a2, a3);
#pragma unroll
        for (int g = 0; g < 4; g++) {
            int ntp = g * 2;
            unsigned b0, b1, b2, b3;
            unsigned baddr = B + (unsigned)((((ntp + (mat >> 1)) * 8 + mrow) * 40
                                             + kk * 16 + (mat & 1) * 8) * 2);
            ldsm4(baddr, b0, b1, b2, b3);
            mma16816h(acc[ntp],     a0, a1, a2, a3, b0, b1);
            mma16816h(acc[ntp + 1], a0, a1, a2, a3, b2, b3);
        }
    }
}

// ---------------- LN1 (fp16 out) ----------------
__global__ void ln1_kernel(const float* __restrict__ x, const float* __restrict__ gw,
                           const float* __restrict__ bw) {
    int row = blockIdx.x, t = threadIdx.x;
    const float4 v = ((const float4*)(x + (size_t)row * D_))[t];
    float s = v.x + v.y + v.z + v.w;
    float q = v.x*v.x + v.y*v.y + v.z*v.z + v.w*v.w;
#pragma unroll
    for (int o = 16; o; o >>= 1) {
        s += __shfl_xor_sync(0xffffffffu, s, o);
        q += __shfl_xor_sync(0xffffffffu, q, o);
    }
    __shared__ float ss[4], qs[4];
    if ((t & 31) == 0) { ss[t >> 5] = s; qs[t >> 5] = q; }
    __syncthreads();
    s = ss[0] + ss[1] + ss[2] + ss[3];
    q = qs[0] + qs[1] + qs[2] + qs[3];
    float mean = s * (1.0f / D_);
    float var  = fmaxf(q * (1.0f / D_) - mean * mean, 0.0f);
    float inv  = 1.0f / (sqrtf(var) + 1e-6f);
    const float4 g4 = ((const float4*)gw)[t];
    const float4 b4 = ((const float4*)bw)[t];
    float o0 = fmaf(g4.x * (v.x - mean), inv, b4.x);
    float o1 = fmaf(g4.y * (v.y - mean), inv, b4.y);
    float o2 = fmaf(g4.z * (v.z - mean), inv, b4.z);
    float o3 = fmaf(g4.w * (v.w - mean), inv, b4.w);
    __half2 h01 = __floats2half2_rn(o0, o1);
    __half2 h23 = __floats2half2_rn(o2, o3);
    *(uint2*)&g_xn16[(size_t)row * D_ + t * 4] =
        make_uint2(*(unsigned*)&h01, *(unsigned*)&h23);
}

// ---------------- LN2 ----------------
__global__ void ln2_kernel(const float* __restrict__ gw, const float* __restrict__ bw,
                           float* __restrict__ out) {
    int row = blockIdx.x, t = threadIdx.x;
    const float4 v = ((const float4*)(g_y + (size_t)row * D_))[t];
    float s = v.x + v.y + v.z + v.w;
    float q = v.x*v.x + v.y*v.y + v.z*v.z + v.w*v.w;
#pragma unroll
    for (int o = 16; o; o >>= 1) {
        s += __shfl_xor_sync(0xffffffffu, s, o);
        q += __shfl_xor_sync(0xffffffffu, q, o);
    }
    __shared__ float ss[4], qs[4];
    if ((t & 31) == 0) { ss[t >> 5] = s; qs[t >> 5] = q; }
    __syncthreads();
    s = ss[0] + ss[1] + ss[2] + ss[3];
    q = qs[0] + qs[1] + qs[2] + qs[3];
    float mean = s * (1.0f / D_);
    float var  = fmaxf(q * (1.0f / D_) - mean * mean, 0.0f);
    float inv  = 1.0f / (sqrtf(var) + 1e-6f);
    const float4 g4 = ((const float4*)gw)[t];
    const float4 b4 = ((const float4*)bw)[t];
    float4 o;
    o.x = fmaf(g4.x * (v.x - mean), inv, b4.x);
    o.y = fmaf(g4.y * (v.y - mean), inv, b4.y);
    o.z = fmaf(g4.z * (v.z - mean), inv, b4.z);
    o.w = fmaf(g4.w * (v.w - mean), inv, b4.w);
    ((float4*)(out + (size_t)row * D_))[t] = o;
}

// ---------------- pack adj ----------------
__global__ void pack_adj_kernel(const int* __restrict__ adj) {
    int gw   = (blockIdx.x * blockDim.x + threadIdx.x) >> 5;
    int lane = threadIdx.x & 31;
    int v = adj[(size_t)gw * 32 + lane];
    unsigned m = __ballot_sync(0xffffffffu, v > 0);
    if (lane == 0) g_adjb[gw] = m;
}

// ---------------- W^T fp16 ----------------
__global__ void prep_w_kernel(const float* __restrict__ W) {
    int hd = blockIdx.x;
    int h = hd >> 6, d = hd & 63;
    for (int k = threadIdx.x; k < D_; k += 128) {
        float v = W[(size_t)h * D_ * DH_ + (size_t)k * DH_ + d];
        g_W16[(size_t)hd * D_ + k] = __half_as_ushort(__float2half_rn(v));
    }
}

// ---------------- GEMM1: fp16, k64 chunks, fused fs/fd + fused hT16 transpose ----
// stage (shorts): A0@0 (5120), A1@5120, B0@10240 (2560), B1@12800; 15360 sh = 30720 B
#define GM_DSM (2 * 30720)
__device__ __forceinline__ void g1_issue(unsigned sbase, int st, int c, int m0, int h, int t) {
    unsigned sb = sbase + (unsigned)st * 30720u;
    int k0 = c * 64;
#pragma unroll
    for (int i = t; i < 1536; i += 256) {
        const unsigned short* g;
        unsigned dst;
        if (i < 1024) {
            int tile = i >> 9;
            int idx = i & 511;
            int row = idx >> 2, seg = idx & 3;
            g = g_xn16 + (size_t)(m0 + row) * D_ + k0 + tile * 32 + seg * 8;
            dst = sb + tile * 10240u + row * 80u + seg * 16u;
        } else {
            int idx = i - 1024;
            int tile = idx >> 8;
            idx &= 255;
            int row = idx >> 2, seg = idx & 3;
            g = g_W16 + (size_t)(h * 64 + row) * D_ + k0 + tile * 32 + seg * 8;
            dst = sb + 20480u + tile * 5120u + row * 80u + seg * 16u;
        }
        cpa16(dst, g);
    }
}
__global__ __launch_bounds__(256, 3) void gemm1t_kernel(const float* __restrict__ a_src,
                                                        const float* __restrict__ a_dst) {
    extern __shared__ unsigned short dsm[];
    __shared__ float as_s[64], ad_s[64];
    unsigned sbase = smem_u32(dsm);
    int t = threadIdx.x, warp = t >> 5, lane = t & 31;
    int m0 = blockIdx.x * 128, h = blockIdx.y;
    int ibase = warp * 16;

    if (t < 64) as_s[t] = a_src[h * 64 + t];
    else if (t < 128) ad_s[t - 64] = a_dst[h * 64 + t - 64];

    float acc[8][4];
#pragma unroll
    for (int i = 0; i < 8; i++)
#pragma unroll
        for (int j = 0; j < 4; j++) acc[i][j] = 0.0f;

    g1_issue(sbase, 0, 0, m0, h, t); CP_COMMIT();

    for (int c = 0; c < 8; c++) {
        CP_WAIT0();
        __syncthreads();
        if (c + 1 < 8) { g1_issue(sbase, (c + 1) & 1, c + 1, m0, h, t); CP_COMMIT(); }
        unsigned stb = sbase + (unsigned)(c & 1) * 30720u;
        mma_chunk_ss(acc, stb,          stb + 20480u, ibase, lane);   // k 0..31
        mma_chunk_ss(acc, stb + 10240u, stb + 25600u, ibase, lane);   // k 32..63
    }

    int r = lane >> 2, q = lane & 3, c2 = q * 2;
    // fused fs/fd
    float fs1 = 0.f, fd1 = 0.f, fs2 = 0.f, fd2 = 0.f;
#pragma unroll
    for (int nt = 0; nt < 8; nt++) {
        float a0 = as_s[nt * 8 + c2], a1 = as_s[nt * 8 + c2 + 1];
        float d0 = ad_s[nt * 8 + c2], d1 = ad_s[nt * 8 + c2 + 1];
        fs1 = fmaf(acc[nt][0], a0, fmaf(acc[nt][1], a1, fs1));
        fd1 = fmaf(acc[nt][0], d0, fmaf(acc[nt][1], d1, fd1));
        fs2 = fmaf(acc[nt][2], a0, fmaf(acc[nt][3], a1, fs2));
        fd2 = fmaf(acc[nt][2], d0, fmaf(acc[nt][3], d1, fd2));
    }
#pragma unroll
    for (int o = 1; o <= 2; o <<= 1) {
        fs1 += __shfl_xor_sync(0xffffffffu, fs1, o);
        fd1 += __shfl_xor_sync(0xffffffffu, fd1, o);
        fs2 += __shfl_xor_sync(0xffffffffu, fs2, o);
        fd2 += __shfl_xor_sync(0xffffffffu, fd2, o);
    }
    if (q == 0) {
        int m1 = m0 + ibase + r, m2 = m1 + 8;
        int b1 = m1 >> 10, n1 = m1 & 1023;
        int b2 = m2 >> 10, n2 = m2 & 1023;
        g_fs[(b1 * H_ + h) * N_ + n1] = fs1 * L2E;
        g_fd[(b1 * H_ + h) * N_ + n1] = fd1 * L2E;
        g_fs[(b2 * H_ + h) * N_ + n2] = fs2 * L2E;
        g_fd[(b2 * H_ + h) * N_ + n2] = fd2 * L2E;
    }

    // fused hT16: transpose acc via smem (layout [d][row], row stride 136 shorts)
    __syncthreads();
#pragma unroll
    for (int nt = 0; nt < 8; nt++) {
        int d0 = nt * 8 + c2;
        dsm[(d0    ) * 136 + ibase + r    ] = __half_as_ushort(__float2half_rn(acc[nt][0]));
        dsm[(d0 + 1) * 136 + ibase + r    ] = __half_as_ushort(__float2half_rn(acc[nt][1]));
        dsm[(d0    ) * 136 + ibase + r + 8] = __half_as_ushort(__float2half_rn(acc[nt][2]));
        dsm[(d0 + 1) * 136 + ibase + r + 8] = __half_as_ushort(__float2half_rn(acc[nt][3]));
    }
    __syncthreads();
    int b = m0 >> 10, n0 = m0 & 1023;
    size_t base = ((size_t)(b * H_ + h) * DH_) * N_ + n0;
#pragma unroll
    for (int k = 0; k < 4; k++) {
        int i = t + k * 256;
        int d = i >> 4, seg = i & 15;
        *(uint4*)&g_hT16[base + (size_t)d * N_ + seg * 8] =
            *(const uint4*)&dsm[d * 136 + seg * 8];
    }
}

// ---------------- merged gmax + uv ----------------
__global__ void gmaxuv_kernel() {
    __shared__ float sm[8];
    __shared__ float gmv;
    int bh = blockIdx.x, t = threadIdx.x;
    float fdv[4];
    float m = -1e30f;
#pragma unroll
    for (int k = 0; k < 4; k++) {
        fdv[k] = g_fd[bh * N_ + t + k * 256];
        m = fmaxf(m, fdv[k]);
    }
#pragma unroll
    for (int o = 16; o; o >>= 1) m = fmaxf(m, __shfl_xor_sync(0xffffffffu, m, o));
    if ((t & 31) == 0) sm[t >> 5] = m;
    __syncthreads();
    if (t == 0) {
        float mm = sm[0];
#pragma unroll
        for (int i = 1; i < 8; i++) mm = fmaxf(mm, sm[i]);
        gmv = mm;
    }
    __syncthreads();
    float gm = gmv;
#pragma unroll
    for (int k = 0; k < 4; k++) {
        int idx = bh * N_ + t + k * 256;
        float fs = g_fs[idx];
        float bound = fs + gm;
        float mx = fmaxf(bound, 0.2f * bound);
        g_A[idx] = fexp2f(bound - mx);
        g_C[idx] = fexp2f(0.2f * bound - mx);
        g_T[idx] = fexp2f(-bound);
        g_u[idx] = fexp2f(fdv[k] - gm);
        g_v[idx] = fexp2f(0.2f * (fdv[k] - gm));
    }
}

// ---------------- attention: register-built P fragments, 3-stage h ring ----
// dsm: h stages 3*10240 B (each: sub0 5120 | sub1 5120); uv floats @30720 B (8192 B)
#define AT_DSM (30720 + 8192)
__device__ __forceinline__ void at_issue3(unsigned sbase, int st, int c, int bh, int t) {
    unsigned sb = sbase + (unsigned)st * 10240u;
    int j0 = c * 64;
#pragma unroll
    for (int i = t; i < 512; i += 256) {
        int sub = i >> 8;
        int idx = i & 255;
        int row = idx >> 2, seg = idx & 3;
        const unsigned short* g = g_hT16 +
            (size_t)bh * DH_ * N_ + (size_t)row * N_ + j0 + sub * 32 + seg * 8;
        cpa16(sb + sub * 5120u + row * 80u + seg * 16u, g);
    }
}
__global__ __launch_bounds__(256, 3) void attn_kernel(const float* __restrict__ x) {
    extern __shared__ unsigned short dsm[];
    unsigned sbase = smem_u32(dsm);
    int t = threadIdx.x, warp = t >> 5, lane = t & 31;
    int b = blockIdx.z, h = blockIdx.y, i0 = blockIdx.x * 128;
    int bh = b * H_ + h;
    int ibase = warp * 16;
    int r = lane >> 2, c2 = (lane & 3) * 2;
    int mat = lane >> 3, mrow = lane & 7;
    int row_lo = i0 + ibase + r, row_hi = row_lo + 8;

    const float* uvf = (const float*)(dsm + 15360);    // byte offset 30720

    // uv preload (8KB) = group 0
#pragma unroll
    for (int i = t; i < 512; i += 256) {
        const float* g = (i < 256) ? (g_u + bh * N_ + i * 4)
                                   : (g_v + bh * N_ + (i - 256) * 4);
        cpa16(sbase + 30720u + (unsigned)i * 16u, g);
    }
    CP_COMMIT();
    at_issue3(sbase, 0, 0, bh, t); CP_COMMIT();
    at_issue3(sbase, 1, 1, bh, t); CP_COMMIT();

    // row constants (quad-broadcast LDG)
    float fA_lo = g_A[bh * N_ + row_lo], fA_hi = g_A[bh * N_ + row_hi];
    float fC_lo = g_C[bh * N_ + row_lo], fC_hi = g_C[bh * N_ + row_hi];
    float fT_lo = g_T[bh * N_ + row_lo], fT_hi = g_T[bh * N_ + row_hi];

    const unsigned* adj_lo = &g_adjb[(size_t)(b * N_ + row_lo) * NW_];
    const unsigned* adj_hi = &g_adjb[(size_t)(b * N_ + row_hi) * NW_];
    unsigned wl0 = adj_lo[0], wl1 = adj_lo[1];
    unsigned wh0 = adj_hi[0], wh1 = adj_hi[1];

    float acc[8][4];
#pragma unroll
    for (int i = 0; i < 8; i++)
#pragma unroll
        for (int j = 0; j < 4; j++) acc[i][j] = 0.0f;
    float den_lo = 0.0f, den_hi = 0.0f;

    for (int c = 0; c < 16; c++) {
        CP_WAIT1();                 // h(c) + uv done; h(c+1) may be in flight
        __syncthreads();
        if (c + 2 < 16) { at_issue3(sbase, (c + 2) % 3, c + 2, bh, t); CP_COMMIT(); }
        unsigned hsb = sbase + (unsigned)(c % 3) * 10240u;
        unsigned wlc[2] = {wl0, wl1}, whc[2] = {wh0, wh1};
        if (c + 1 < 16) {
            wl0 = adj_lo[(c + 1) * 2]; wl1 = adj_lo[(c + 1) * 2 + 1];
            wh0 = adj_hi[(c + 1) * 2]; wh1 = adj_hi[(c + 1) * 2 + 1];
        }
#pragma unroll
        for (int sub = 0; sub < 2; sub++) {
            unsigned wl = wlc[sub], wh = whc[sub];
            const float* us = uvf + c * 64 + sub * 32;
            const float* vs = uvf + 1024 + c * 64 + sub * 32;
            unsigned Bs = hsb + sub * 5120u;
#pragma unroll
            for (int kk = 0; kk < 2; kk++) {
                int jb = kk * 16 + c2;
                float u0 = us[jb], u1 = us[jb + 1], u8 = us[jb + 8], u9 = us[jb + 9];
                float v0 = vs[jb], v1 = vs[jb + 1], v8 = vs[jb + 8], v9 = vs[jb + 9];
                float pl0 = ((wl >> (jb    )) & 1u) ? (u0 > fT_lo ? fA_lo * u0 : fC_lo * v0) : 0.f;
                float pl1 = ((wl >> (jb + 1)) & 1u) ? (u1 > fT_lo ? fA_lo * u1 : fC_lo * v1) : 0.f;
                float pl8 = ((wl >> (jb + 8)) & 1u) ? (u8 > fT_lo ? fA_lo * u8 : fC_lo * v8) : 0.f;
                float pl9 = ((wl >> (jb + 9)) & 1u) ? (u9 > fT_lo ? fA_lo * u9 : fC_lo * v9) : 0.f;
                float ph0 = ((wh >> (jb    )) & 1u) ? (u0 > fT_hi ? fA_hi * u0 : fC_hi * v0) : 0.f;
                float ph1 = ((wh >> (jb + 1)) & 1u) ? (u1 > fT_hi ? fA_hi * u1 : fC_hi * v1) : 0.f;
                float ph8 = ((wh >> (jb + 8)) & 1u) ? (u8 > fT_hi ? fA_hi * u8 : fC_hi * v8) : 0.f;
                float ph9 = ((wh >> (jb + 9)) & 1u) ? (u9 > fT_hi ? fA_hi * u9 : fC_hi * v9) : 0.f;
                den_lo += (pl0 + pl1) + (pl8 + pl9);
                den_hi += (ph0 + ph1) + (ph8 + ph9);
                __half2 A0 = __floats2half2_rn(pl0, pl1);
                __half2 A1 = __floats2half2_rn(ph0, ph1);
                __half2 A2 = __floats2half2_rn(pl8, pl9);
                __half2 A3 = __floats2half2_rn(ph8, ph9);
                unsigned a0 = *(unsigned*)&A0, a1 = *(unsigned*)&A1;
                unsigned a2 = *(unsigned*)&A2, a3 = *(unsigned*)&A3;
#pragma unroll
                for (int g = 0; g < 4; g++) {
                    int ntp = g * 2;
                    unsigned b0, b1, b2, b3;
                    unsigned baddr = Bs + (unsigned)((((ntp + (mat >> 1)) * 8 + mrow) * 40
                                                     + kk * 16 + (mat & 1) * 8) * 2);
                    ldsm4(baddr, b0, b1, b2, b3);
                    mma16816h(acc[ntp],     a0, a1, a2, a3, b0, b1);
                    mma16816h(acc[ntp + 1], a0, a1, a2, a3, b2, b3);
                }
            }
        }
    }

    // den: quad covers all j for each row
    den_lo += __shfl_xor_sync(0xffffffffu, den_lo, 1);
    den_lo += __shfl_xor_sync(0xffffffffu, den_lo, 2);
    den_hi += __shfl_xor_sync(0xffffffffu, den_hi, 1);
    den_hi += __shfl_xor_sync(0xffffffffu, den_hi, 2);
    float inv1 = 1.0f / den_lo;
    float inv2 = 1.0f / den_hi;

#pragma unroll
    for (int nt = 0; nt < 8; nt++) {
        size_t i1 = (size_t)(b * N_ + row_lo) * D_ + h * DH_ + nt * 8 + c2;
        size_t i2 = (size_t)(b * N_ + row_hi) * D_ + h * DH_ + nt * 8 + c2;
        float2 x1 = *(const float2*)(x + i1);
        float2 x2 = *(const float2*)(x + i2);
        float2 o1 = make_float2(x1.x + elu1(acc[nt][0] * inv1),
                                x1.y + elu1(acc[nt][1] * inv1));
        float2 o2 = make_float2(x2.x + elu1(acc[nt][2] * inv2),
                                x2.y + elu1(acc[nt][3] * inv2));
        *(float2*)&g_y[i1] = o1;
        *(float2*)&g_y[i2] = o2;
    }
}

// ---------------- launch ----------------
extern "C" void kernel_launch(void* const* d_in, const int* in_sizes, int n_in,
                              void* d_out, int out_size) {
    const float* x     = (const float*)d_in[0];
    const int*   adj   = (const int*)  d_in[2];
    const float* W     = (const float*)d_in[3];
    const float* a_src = (const float*)d_in[4];
    const float* a_dst = (const float*)d_in[5];
    const float* ln1g  = (const float*)d_in[6];
    const float* ln1b  = (const float*)d_in[7];
    const float* ln2g  = (const float*)d_in[8];
    const float* ln2b  = (const float*)d_in[9];
    float* out = (float*)d_out;

    cudaFuncSetAttribute(gemm1t_kernel, cudaFuncAttributeMaxDynamicSharedMemorySize, GM_DSM);
    cudaFuncSetAttribute(attn_kernel,   cudaFuncAttributeMaxDynamicSharedMemorySize, AT_DSM);

    ln1_kernel   <<<B_*N_, 128>>>(x, ln1g, ln1b);
    pack_adj_kernel<<<(B_*N_*N_) / 256, 256>>>(adj);
    prep_w_kernel<<<H_*DH_, 128>>>(W);
    gemm1t_kernel<<<dim3(B_*N_/128, H_), 256, GM_DSM>>>(a_src, a_dst);
    gmaxuv_kernel<<<B_*H_, 256>>>();
    attn_kernel  <<<dim3(N_/128, H_, B_), 256, AT_DSM>>>(x);
    ln2_kernel   <<<B_*N_, 128>>>(ln2g, ln2b, out);
}

// round 15
// speedup vs baseline: 6.1802x; 1.0595x over previous
#include <cuda_runtime.h>
#include <cuda_fp16.h>
#include <cstdint>

#define B_ 8
#define N_ 1024
#define D_ 512
#define H_ 8
#define DH_ 64
#define NW_ (N_/32)
#define L2E 1.4426950408889634f

// ---------------- scratch ----------------
__device__ unsigned short g_xn16[B_*N_*D_];     // LN1 out, fp16
__device__ unsigned short g_W16 [H_*DH_*D_];    // W^T [h][d][k], fp16
__device__ unsigned short g_hT16[B_*H_*DH_*N_]; // h^T [b][h][d][j], fp16
__device__ float    g_fs[B_*H_*N_];
__device__ float    g_fd[B_*H_*N_];
__device__ unsigned g_adjb[B_*N_*NW_];
__device__ float    g_y [B_*N_*D_];
__device__ float    g_A[B_*H_*N_];
__device__ float    g_C[B_*H_*N_];
__device__ float    g_u[B_*H_*N_];
__device__ float    g_v[B_*H_*N_];

// ---------------- helpers ----------------
__device__ __forceinline__ float fexp2f(float t) {
    t = fmaxf(t, -125.0f);
    float r = t + 12582912.0f;
    int   n = __float_as_int(r) - 0x4B400000;
    float f = t - (r - 12582912.0f);
    float p = 1.3333558146e-3f;
    p = fmaf(p, f, 9.6181291298e-3f);
    p = fmaf(p, f, 5.5504108664e-2f);
    p = fmaf(p, f, 2.4022650696e-1f);
    p = fmaf(p, f, 6.9314718056e-1f);
    p = fmaf(p, f, 1.0f);
    return __int_as_float(__float_as_int(p) + (n << 23));
}
__device__ __forceinline__ float elu1(float v) {
    return v > 0.0f ? v : (fexp2f(v * L2E) - 1.0f);
}
__device__ __forceinline__ unsigned smem_u32(const void* p) {
    unsigned a;
    asm("{ .reg .u64 t; cvta.to.shared.u64 t, %1; cvt.u32.u64 %0, t; }" : "=r"(a) : "l"(p));
    return a;
}
__device__ __forceinline__ void cpa16(unsigned s, const void* g) {
    asm volatile("cp.async.cg.shared.global [%0], [%1], 16;" :: "r"(s), "l"(g) : "memory");
}
#define CP_COMMIT() asm volatile("cp.async.commit_group;" ::: "memory")
#define CP_WAIT0()  asm volatile("cp.async.wait_group 0;" ::: "memory")
#define CP_WAIT1()  asm volatile("cp.async.wait_group 1;" ::: "memory")

__device__ __forceinline__ void mma16816h(float* c, unsigned a0, unsigned a1,
                                          unsigned a2, unsigned a3,
                                          unsigned b0, unsigned b1) {
    asm volatile(
        "mma.sync.aligned.m16n8k16.row.col.f32.f16.f16.f32 "
        "{%0,%1,%2,%3}, {%4,%5,%6,%7}, {%8,%9}, {%0,%1,%2,%3};\n"
        : "+f"(c[0]), "+f"(c[1]), "+f"(c[2]), "+f"(c[3])
        : "r"(a0), "r"(a1), "r"(a2), "r"(a3), "r"(b0), "r"(b1));
}
__device__ __forceinline__ void ldsm4(unsigned addr, unsigned &r0, unsigned &r1,
                                      unsigned &r2, unsigned &r3) {
    asm volatile("ldmatrix.sync.aligned.m8n8.x4.shared.b16 {%0,%1,%2,%3}, [%4];"
                 : "=r"(r0), "=r"(r1), "=r"(r2), "=r"(r3) : "r"(addr));
}

// ---- fp16 k32 step via ldmatrix (gemm1): A[128][32], B[64][32], stride 40 ----
__device__ __forceinline__ void mma_chunk_ss(float acc[8][4], unsigned A, unsigned B,
                                             int ibase, int lane) {
    int mat  = lane >> 3;
    int mrow = lane & 7;
#pragma unroll
    for (int kk = 0; kk < 2; kk++) {
        unsigned a0, a1, a2, a3;
        unsigned aaddr = A + (unsigned)(((ibase + (mat & 1) * 8 + mrow) * 40
                                         + kk * 16 + (mat >> 1) * 8) * 2);
        ldsm4(aaddr, a0, a1, a2, a3);
#pragma unroll
        for (int g = 0; g < 4; g++) {
            int ntp = g * 2;
            unsigned b0, b1, b2, b3;
            unsigned baddr = B + (unsigned)((((ntp + (mat >> 1)) * 8 + mrow) * 40
                                             + kk * 16 + (mat & 1) * 8) * 2);
            ldsm4(baddr, b0, b1, b2, b3);
            mma16816h(acc[ntp],     a0, a1, a2, a3, b0, b1);
            mma16816h(acc[ntp + 1], a0, a1, a2, a3, b2, b3);
        }
    }
}

// ---------------- LN1 (fp16 out) ----------------
__global__ void ln1_kernel(const float* __restrict__ x, const float* __restrict__ gw,
                           const float* __restrict__ bw) {
    int row = blockIdx.x, t = threadIdx.x;
    const float4 v = ((const float4*)(x + (size_t)row * D_))[t];
    float s = v.x + v.y + v.z + v.w;
    float q = v.x*v.x + v.y*v.y + v.z*v.z + v.w*v.w;
#pragma unroll
    for (int o = 16; o; o >>= 1) {
        s += __shfl_xor_sync(0xffffffffu, s, o);
        q += __shfl_xor_sync(0xffffffffu, q, o);
    }
    __shared__ float ss[4], qs[4];
    if ((t & 31) == 0) { ss[t >> 5] = s; qs[t >> 5] = q; }
    __syncthreads();
    s = ss[0] + ss[1] + ss[2] + ss[3];
    q = qs[0] + qs[1] + qs[2] + qs[3];
    float mean = s * (1.0f / D_);
    float var  = fmaxf(q * (1.0f / D_) - mean * mean, 0.0f);
    float inv  = 1.0f / (sqrtf(var) + 1e-6f);
    const float4 g4 = ((const float4*)gw)[t];
    const float4 b4 = ((const float4*)bw)[t];
    float o0 = fmaf(g4.x * (v.x - mean), inv, b4.x);
    float o1 = fmaf(g4.y * (v.y - mean), inv, b4.y);
    float o2 = fmaf(g4.z * (v.z - mean), inv, b4.z);
    float o3 = fmaf(g4.w * (v.w - mean), inv, b4.w);
    __half2 h01 = __floats2half2_rn(o0, o1);
    __half2 h23 = __floats2half2_rn(o2, o3);
    *(uint2*)&g_xn16[(size_t)row * D_ + t * 4] =
        make_uint2(*(unsigned*)&h01, *(unsigned*)&h23);
}

// ---------------- LN2 ----------------
__global__ void ln2_kernel(const float* __restrict__ gw, const float* __restrict__ bw,
                           float* __restrict__ out) {
    int row = blockIdx.x, t = threadIdx.x;
    const float4 v = ((const float4*)(g_y + (size_t)row * D_))[t];
    float s = v.x + v.y + v.z + v.w;
    float q = v.x*v.x + v.y*v.y + v.z*v.z + v.w*v.w;
#pragma unroll
    for (int o = 16; o; o >>= 1) {
        s += __shfl_xor_sync(0xffffffffu, s, o);
        q += __shfl_xor_sync(0xffffffffu, q, o);
    }
    __shared__ float ss[4], qs[4];
    if ((t & 31) == 0) { ss[t >> 5] = s; qs[t >> 5] = q; }
    __syncthreads();
    s = ss[0] + ss[1] + ss[2] + ss[3];
    q = qs[0] + qs[1] + qs[2] + qs[3];
    float mean = s * (1.0f / D_);
    float var  = fmaxf(q * (1.0f / D_) - mean * mean, 0.0f);
    float inv  = 1.0f / (sqrtf(var) + 1e-6f);
    const float4 g4 = ((const float4*)gw)[t];
    const float4 b4 = ((const float4*)bw)[t];
    float4 o;
    o.x = fmaf(g4.x * (v.x - mean), inv, b4.x);
    o.y = fmaf(g4.y * (v.y - mean), inv, b4.y);
    o.z = fmaf(g4.z * (v.z - mean), inv, b4.z);
    o.w = fmaf(g4.w * (v.w - mean), inv, b4.w);
    ((float4*)(out + (size_t)row * D_))[t] = o;
}

// ---------------- pack adj ----------------
__global__ void pack_adj_kernel(const int* __restrict__ adj) {
    int gw   = (blockIdx.x * blockDim.x + threadIdx.x) >> 5;
    int lane = threadIdx.x & 31;
    int v = adj[(size_t)gw * 32 + lane];
    unsigned m = __ballot_sync(0xffffffffu, v > 0);
    if (lane == 0) g_adjb[gw] = m;
}

// ---------------- W^T fp16 ----------------
__global__ void prep_w_kernel(const float* __restrict__ W) {
    int hd = blockIdx.x;
    int h = hd >> 6, d = hd & 63;
    for (int k = threadIdx.x; k < D_; k += 128) {
        float v = W[(size_t)h * D_ * DH_ + (size_t)k * DH_ + d];
        g_W16[(size_t)hd * D_ + k] = __half_as_ushort(__float2half_rn(v));
    }
}

// ---------------- GEMM1: fp16, k64 chunks, fused fs/fd + fused hT16 transpose ----
#define GM_DSM (2 * 30720)
__device__ __forceinline__ void g1_issue(unsigned sbase, int st, int c, int m0, int h, int t) {
    unsigned sb = sbase + (unsigned)st * 30720u;
    int k0 = c * 64;
#pragma unroll
    for (int i = t; i < 1536; i += 256) {
        const unsigned short* g;
        unsigned dst;
        if (i < 1024) {
            int tile = i >> 9;
            int idx = i & 511;
            int row = idx >> 2, seg = idx & 3;
            g = g_xn16 + (size_t)(m0 + row) * D_ + k0 + tile * 32 + seg * 8;
            dst = sb + tile * 10240u + row * 80u + seg * 16u;
        } else {
            int idx = i - 1024;
            int tile = idx >> 8;
            idx &= 255;
            int row = idx >> 2, seg = idx & 3;
            g = g_W16 + (size_t)(h * 64 + row) * D_ + k0 + tile * 32 + seg * 8;
            dst = sb + 20480u + tile * 5120u + row * 80u + seg * 16u;
        }
        cpa16(dst, g);
    }
}
__global__ __launch_bounds__(256, 3) void gemm1t_kernel(const float* __restrict__ a_src,
                                                        const float* __restrict__ a_dst) {
    extern __shared__ unsigned short dsm[];
    __shared__ float as_s[64], ad_s[64];
    unsigned sbase = smem_u32(dsm);
    int t = threadIdx.x, warp = t >> 5, lane = t & 31;
    int m0 = blockIdx.x * 128, h = blockIdx.y;
    int ibase = warp * 16;

    if (t < 64) as_s[t] = a_src[h * 64 + t];
    else if (t < 128) ad_s[t - 64] = a_dst[h * 64 + t - 64];

    float acc[8][4];
#pragma unroll
    for (int i = 0; i < 8; i++)
#pragma unroll
        for (int j = 0; j < 4; j++) acc[i][j] = 0.0f;

    g1_issue(sbase, 0, 0, m0, h, t); CP_COMMIT();

    for (int c = 0; c < 8; c++) {
        CP_WAIT0();
        __syncthreads();
        if (c + 1 < 8) { g1_issue(sbase, (c + 1) & 1, c + 1, m0, h, t); CP_COMMIT(); }
        unsigned stb = sbase + (unsigned)(c & 1) * 30720u;
        mma_chunk_ss(acc, stb,          stb + 20480u, ibase, lane);
        mma_chunk_ss(acc, stb + 10240u, stb + 25600u, ibase, lane);
    }

    int r = lane >> 2, q = lane & 3, c2 = q * 2;
    float fs1 = 0.f, fd1 = 0.f, fs2 = 0.f, fd2 = 0.f;
#pragma unroll
    for (int nt = 0; nt < 8; nt++) {
        float a0 = as_s[nt * 8 + c2], a1 = as_s[nt * 8 + c2 + 1];
        float d0 = ad_s[nt * 8 + c2], d1 = ad_s[nt * 8 + c2 + 1];
        fs1 = fmaf(acc[nt][0], a0, fmaf(acc[nt][1], a1, fs1));
        fd1 = fmaf(acc[nt][0], d0, fmaf(acc[nt][1], d1, fd1));
        fs2 = fmaf(acc[nt][2], a0, fmaf(acc[nt][3], a1, fs2));
        fd2 = fmaf(acc[nt][2], d0, fmaf(acc[nt][3], d1, fd2));
    }
#pragma unroll
    for (int o = 1; o <= 2; o <<= 1) {
        fs1 += __shfl_xor_sync(0xffffffffu, fs1, o);
        fd1 += __shfl_xor_sync(0xffffffffu, fd1, o);
        fs2 += __shfl_xor_sync(0xffffffffu, fs2, o);
        fd2 += __shfl_xor_sync(0xffffffffu, fd2, o);
    }
    if (q == 0) {
        int m1 = m0 + ibase + r, m2 = m1 + 8;
        int b1 = m1 >> 10, n1 = m1 & 1023;
        int b2 = m2 >> 10, n2 = m2 & 1023;
        g_fs[(b1 * H_ + h) * N_ + n1] = fs1 * L2E;
        g_fd[(b1 * H_ + h) * N_ + n1] = fd1 * L2E;
        g_fs[(b2 * H_ + h) * N_ + n2] = fs2 * L2E;
        g_fd[(b2 * H_ + h) * N_ + n2] = fd2 * L2E;
    }

    __syncthreads();
#pragma unroll
    for (int nt = 0; nt < 8; nt++) {
        int d0 = nt * 8 + c2;
        dsm[(d0    ) * 136 + ibase + r    ] = __half_as_ushort(__float2half_rn(acc[nt][0]));
        dsm[(d0 + 1) * 136 + ibase + r    ] = __half_as_ushort(__float2half_rn(acc[nt][1]));
        dsm[(d0    ) * 136 + ibase + r + 8] = __half_as_ushort(__float2half_rn(acc[nt][2]));
        dsm[(d0 + 1) * 136 + ibase + r + 8] = __half_as_ushort(__float2half_rn(acc[nt][3]));
    }
    __syncthreads();
    int b = m0 >> 10, n0 = m0 & 1023;
    size_t base = ((size_t)(b * H_ + h) * DH_) * N_ + n0;
#pragma unroll
    for (int k = 0; k < 4; k++) {
        int i = t + k * 256;
        int d = i >> 4, seg = i & 15;
        *(uint4*)&g_hT16[base + (size_t)d * N_ + seg * 8] =
            *(const uint4*)&dsm[d * 136 + seg * 8];
    }
}

// ---------------- merged gmax + uv (no T needed anymore) ----------------
__global__ void gmaxuv_kernel() {
    __shared__ float sm[8];
    __shared__ float gmv;
    int bh = blockIdx.x, t = threadIdx.x;
    float fdv[4];
    float m = -1e30f;
#pragma unroll
    for (int k = 0; k < 4; k++) {
        fdv[k] = g_fd[bh * N_ + t + k * 256];
        m = fmaxf(m, fdv[k]);
    }
#pragma unroll
    for (int o = 16; o; o >>= 1) m = fmaxf(m, __shfl_xor_sync(0xffffffffu, m, o));
    if ((t & 31) == 0) sm[t >> 5] = m;
    __syncthreads();
    if (t == 0) {
        float mm = sm[0];
#pragma unroll
        for (int i = 1; i < 8; i++) mm = fmaxf(mm, sm[i]);
        gmv = mm;
    }
    __syncthreads();
    float gm = gmv;
#pragma unroll
    for (int k = 0; k < 4; k++) {
        int idx = bh * N_ + t + k * 256;
        float fs = g_fs[idx];
        float bound = fs + gm;
        float mx = fmaxf(bound, 0.2f * bound);
        g_A[idx] = fexp2f(bound - mx);
        g_C[idx] = fexp2f(0.2f * bound - mx);
        g_u[idx] = fexp2f(fdv[k] - gm);
        g_v[idx] = fexp2f(0.2f * (fdv[k] - gm));
    }
}

// ---------------- attention: i-tile 256, warp-tile 32x64, register P, max-form ----
// dsm: h stages 3*10240 B; uv floats @30720 B (8192 B). Total 38912 B. 2 CTAs/SM.
#define AT_DSM (30720 + 8192)
__device__ __forceinline__ void at_issue3(unsigned sbase, int st, int c, int bh, int t) {
    unsigned sb = sbase + (unsigned)st * 10240u;
    int j0 = c * 64;
#pragma unroll
    for (int i = t; i < 512; i += 256) {
        int sub = i >> 8;
        int idx = i & 255;
        int row = idx >> 2, seg = idx & 3;
        const unsigned short* g = g_hT16 +
            (size_t)bh * DH_ * N_ + (size_t)row * N_ + j0 + sub * 32 + seg * 8;
        cpa16(sb + sub * 5120u + row * 80u + seg * 16u, g);
    }
}
__global__ __launch_bounds__(256, 2) void attn_kernel(const float* __restrict__ x) {
    extern __shared__ unsigned short dsm[];
    unsigned sbase = smem_u32(dsm);
    int t = threadIdx.x, warp = t >> 5, lane = t & 31;
    int b = blockIdx.z, h = blockIdx.y, i0 = blockIdx.x * 256;
    int bh = b * H_ + h;
    int ibase = warp * 32;
    int r = lane >> 2, c2 = (lane & 3) * 2;
    int mat = lane >> 3, mrow = lane & 7;
    int row0 = i0 + ibase + r;            // rows row0 + {0,8,16,24}

    const float* uvf = (const float*)(dsm + 15360);    // byte offset 30720

#pragma unroll
    for (int i = t; i < 512; i += 256) {
        const float* g = (i < 256) ? (g_u + bh * N_ + i * 4)
                                   : (g_v + bh * N_ + (i - 256) * 4);
        cpa16(sbase + 30720u + (unsigned)i * 16u, g);
    }
    CP_COMMIT();
    at_issue3(sbase, 0, 0, bh, t); CP_COMMIT();
    at_issue3(sbase, 1, 1, bh, t); CP_COMMIT();

    float fA[4], fC[4];
    const unsigned* adjp[4];
#pragma unroll
    for (int q = 0; q < 4; q++) {
        int rq = row0 + q * 8;
        fA[q] = g_A[bh * N_ + rq];
        fC[q] = g_C[bh * N_ + rq];
        adjp[q] = &g_adjb[(size_t)(b * N_ + rq) * NW_];
    }
    unsigned wcur[4][2];
#pragma unroll
    for (int q = 0; q < 4; q++) { wcur[q][0] = adjp[q][0]; wcur[q][1] = adjp[q][1]; }

    float acc[16][4];
#pragma unroll
    for (int i = 0; i < 16; i++)
#pragma unroll
        for (int j = 0; j < 4; j++) acc[i][j] = 0.0f;
    float den[4] = {0.f, 0.f, 0.f, 0.f};

    for (int c = 0; c < 16; c++) {
        CP_WAIT1();
        __syncthreads();
        if (c + 2 < 16) { at_issue3(sbase, (c + 2) % 3, c + 2, bh, t); CP_COMMIT(); }
        unsigned hsb = sbase + (unsigned)(c % 3) * 10240u;
        unsigned w[4][2];
#pragma unroll
        for (int q = 0; q < 4; q++) { w[q][0] = wcur[q][0]; w[q][1] = wcur[q][1]; }
        if (c + 1 < 16) {
#pragma unroll
            for (int q = 0; q < 4; q++) {
                wcur[q][0] = adjp[q][(c + 1) * 2];
                wcur[q][1] = adjp[q][(c + 1) * 2 + 1];
            }
        }
#pragma unroll
        for (int sub = 0; sub < 2; sub++) {
            const float* us = uvf + c * 64 + sub * 32;
            const float* vs = uvf + 1024 + c * 64 + sub * 32;
            unsigned Bs = hsb + sub * 5120u;
#pragma unroll
            for (int kk = 0; kk < 2; kk++) {
                int jb = kk * 16 + c2;
                float2 u01 = *(const float2*)(us + jb);
                float2 u89 = *(const float2*)(us + jb + 8);
                float2 v01 = *(const float2*)(vs + jb);
                float2 v89 = *(const float2*)(vs + jb + 8);
                unsigned afr[2][4];
#pragma unroll
                for (int tile = 0; tile < 2; tile++) {
#pragma unroll
                    for (int rr = 0; rr < 2; rr++) {
                        int q = tile * 2 + rr;
                        unsigned wq = w[q][sub];
                        float p0 = ((wq >> (jb    )) & 1u) ? fmaxf(fA[q]*u01.x, fC[q]*v01.x) : 0.f;
                        float p1 = ((wq >> (jb + 1)) & 1u) ? fmaxf(fA[q]*u01.y, fC[q]*v01.y) : 0.f;
                        float p8 = ((wq >> (jb + 8)) & 1u) ? fmaxf(fA[q]*u89.x, fC[q]*v89.x) : 0.f;
                        float p9 = ((wq >> (jb + 9)) & 1u) ? fmaxf(fA[q]*u89.y, fC[q]*v89.y) : 0.f;
                        den[q] += (p0 + p1) + (p8 + p9);
                        __half2 lo = __floats2half2_rn(p0, p1);
                        __half2 hi = __floats2half2_rn(p8, p9);
                        afr[tile][rr]     = *(unsigned*)&lo;
                        afr[tile][2 + rr] = *(unsigned*)&hi;
                    }
                }
#pragma unroll
                for (int g = 0; g < 4; g++) {
                    int ntp = g * 2;
                    unsigned b0, b1, b2, b3;
                    unsigned baddr = Bs + (unsigned)((((ntp + (mat >> 1)) * 8 + mrow) * 40
                                                     + kk * 16 + (mat & 1) * 8) * 2);
                    ldsm4(baddr, b0, b1, b2, b3);
                    mma16816h(acc[ntp],         afr[0][0], afr[0][1], afr[0][2], afr[0][3], b0, b1);
                    mma16816h(acc[ntp + 1],     afr[0][0], afr[0][1], afr[0][2], afr[0][3], b2, b3);
                    mma16816h(acc[8 + ntp],     afr[1][0], afr[1][1], afr[1][2], afr[1][3], b0, b1);
                    mma16816h(acc[8 + ntp + 1], afr[1][0], afr[1][1], afr[1][2], afr[1][3], b2, b3);
                }
            }
        }
    }

#pragma unroll
    for (int q = 0; q < 4; q++) {
        den[q] += __shfl_xor_sync(0xffffffffu, den[q], 1);
        den[q] += __shfl_xor_sync(0xffffffffu, den[q], 2);
    }
    float inv0 = 1.0f / den[0], inv1 = 1.0f / den[1];
    float inv2 = 1.0f / den[2], inv3 = 1.0f / den[3];

#pragma unroll
    for (int nt = 0; nt < 8; nt++) {
        size_t i1 = (size_t)(b * N_ + row0     ) * D_ + h * DH_ + nt * 8 + c2;
        size_t i2 = (size_t)(b * N_ + row0 +  8) * D_ + h * DH_ + nt * 8 + c2;
        size_t i3 = (size_t)(b * N_ + row0 + 16) * D_ + h * DH_ + nt * 8 + c2;
        size_t i4 = (size_t)(b * N_ + row0 + 24) * D_ + h * DH_ + nt * 8 + c2;
        float2 x1 = *(const float2*)(x + i1);
        float2 x2 = *(const float2*)(x + i2);
        float2 x3 = *(const float2*)(x + i3);
        float2 x4 = *(const float2*)(x + i4);
        *(float2*)&g_y[i1] = make_float2(x1.x + elu1(acc[nt][0] * inv0),
                                         x1.y + elu1(acc[nt][1] * inv0));
        *(float2*)&g_y[i2] = make_float2(x2.x + elu1(acc[nt][2] * inv1),
                                         x2.y + elu1(acc[nt][3] * inv1));
        *(float2*)&g_y[i3] = make_float2(x3.x + elu1(acc[8 + nt][0] * inv2),
                                         x3.y + elu1(acc[8 + nt][1] * inv2));
        *(float2*)&g_y[i4] = make_float2(x4.x + elu1(acc[8 + nt][2] * inv3),
                                         x4.y + elu1(acc[8 + nt][3] * inv3));
    }
}

// ---------------- launch ----------------
extern "C" void kernel_launch(void* const* d_in, const int* in_sizes, int n_in,
                              void* d_out, int out_size) {
    const float* x     = (const float*)d_in[0];
    const int*   adj   = (const int*)  d_in[2];
    const float* W     = (const float*)d_in[3];
    const float* a_src = (const float*)d_in[4];
    const float* a_dst = (const float*)d_in[5];
    const float* ln1g  = (const float*)d_in[6];
    const float* ln1b  = (const float*)d_in[7];
    const float* ln2g  = (const float*)d_in[8];
    const float* ln2b  = (const float*)d_in[9];
    float* out = (float*)d_out;

    cudaFuncSetAttribute(gemm1t_kernel, cudaFuncAttributeMaxDynamicSharedMemorySize, GM_DSM);
    cudaFuncSetAttribute(attn_kernel,   cudaFuncAttributeMaxDynamicSharedMemorySize, AT_DSM);

    ln1_kernel   <<<B_*N_, 128>>>(x, ln1g, ln1b);
    pack_adj_kernel<<<(B_*N_*N_) / 256, 256>>>(adj);
    prep_w_kernel<<<H_*DH_, 128>>>(W);
    gemm1t_kernel<<<dim3(B_*N_/128, H_), 256, GM_DSM>>>(a_src, a_dst);
    gmaxuv_kernel<<<B_*H_, 256>>>();
    attn_kernel  <<<dim3(N_/256, H_, B_), 256, AT_DSM>>>(x);
    ln2_kernel   <<<B_*N_, 128>>>(ln2g, ln2b, out);
}